// round 9
// baseline (speedup 1.0000x reference)
#include <cuda_runtime.h>
#include <cuda_fp16.h>
#include <math.h>
#include <stdint.h>

#define HIDK 1024
#define MTOK 4096
#define LSEQ 2048
#define NHEAD 16
#define HDIM 64
#define CT 64
#define NCH (LSEQ / CT)
#define PD 68
#define PDH 72

// ---------------- scratch (device globals; no allocations) ----------------
__device__ float g_xg[MTOK * HIDK];
__device__ float g_att[MTOK * HIDK];                      // final o (inter writes)
__device__ __align__(16) __half g_qh16[MTOK * HIDK];
__device__ __align__(16) __half g_kh16[MTOK * HIDK];
__device__ __align__(16) __half g_vh16[MTOK * HIDK];
__device__ __align__(16) __half g_gkh[MTOK * HIDK];
__device__ __align__(16) __half g_expDh[MTOK * HIDK];
__device__ __align__(16) __half g_atth[MTOK * HIDK];      // intra-chunk o
__device__ __align__(16) __half g_Ph[32 * NCH * HDIM * HDIM];
__device__ __align__(16) __half g_Sh[32 * NCH * HDIM * HDIM];
// fp16 GEMM operands: activations single + 2^-10-scaled copy; weights exact pair
__device__ __align__(16) __half g_xh[MTOK * HIDK];
__device__ __align__(16) __half g_xs[MTOK * HIDK];
__device__ __align__(16) __half g_yh[MTOK * HIDK];
__device__ __align__(16) __half g_ys[MTOK * HIDK];
__device__ __align__(16) __half g_wh[5 * HIDK * HIDK];
__device__ __align__(16) __half g_wl[5 * HIDK * HIDK];

// ======================= helpers =======================
__device__ __forceinline__ uint32_t smem_u32(const void* p) {
    uint32_t a;
    asm("{ .reg .u64 t; cvta.to.shared.u64 t, %1; cvt.u32.u64 %0, t; }" : "=r"(a) : "l"(p));
    return a;
}
__device__ __forceinline__ void cpasync16(uint32_t s, const void* g) {
    asm volatile("cp.async.cg.shared.global [%0], [%1], 16;" ::"r"(s), "l"(g));
}
__device__ __forceinline__ void cpcommit() { asm volatile("cp.async.commit_group;"); }

__device__ __forceinline__ void ldmx4(uint32_t& r0, uint32_t& r1, uint32_t& r2,
                                      uint32_t& r3, uint32_t addr) {
    asm volatile("ldmatrix.sync.aligned.m8n8.x4.shared.b16 {%0,%1,%2,%3}, [%4];"
                 : "=r"(r0), "=r"(r1), "=r"(r2), "=r"(r3)
                 : "r"(addr));
}
__device__ __forceinline__ void ldmx4t(uint32_t& r0, uint32_t& r1, uint32_t& r2,
                                       uint32_t& r3, uint32_t addr) {
    asm volatile("ldmatrix.sync.aligned.m8n8.x4.trans.shared.b16 {%0,%1,%2,%3}, [%4];"
                 : "=r"(r0), "=r"(r1), "=r"(r2), "=r"(r3)
                 : "r"(addr));
}
__device__ __forceinline__ void mma16816(float* c, const uint32_t* a, const uint32_t* b) {
    asm volatile(
        "mma.sync.aligned.m16n8k16.row.col.f32.f16.f16.f32 "
        "{%0,%1,%2,%3}, {%4,%5,%6,%7}, {%8,%9}, {%0,%1,%2,%3};"
        : "+f"(c[0]), "+f"(c[1]), "+f"(c[2]), "+f"(c[3])
        : "r"(a[0]), "r"(a[1]), "r"(a[2]), "r"(a[3]), "r"(b[0]), "r"(b[1]));
}

// ======================= fp16 mma.sync big GEMM ==============
#define ROWB 80
#define STG_A (128 * ROWB)
#define STG (2 * STG_A)
#define NSTG 4
#define SMEM_MM (NSTG * STG)
#define NSTAGES 64

__device__ __forceinline__ void mm_issue(int s, uint32_t sb, int tid, int brow, int bcol,
                                         const __half* Ah, const __half* As,
                                         const __half* Bh, const __half* Bl) {
    if (s < NSTAGES) {
        int p = s >> 5;
        int kk = (s & 31) << 5;
        const __half* Ab = p ? As : Ah;
        const __half* Bb = p ? Bl : Bh;
        uint32_t st = sb + (uint32_t)(s & 3) * STG;
        int row = tid >> 2, cw = tid & 3;
        const char* ga = (const char*)(Ab + (size_t)(brow + row) * HIDK + kk + cw * 8);
        cpasync16(st + row * ROWB + cw * 16, ga);
        cpasync16(st + (row + 64) * ROWB + cw * 16, ga + (size_t)64 * HIDK * 2);
        const char* gb = (const char*)(Bb + (size_t)(bcol + row) * HIDK + kk + cw * 8);
        cpasync16(st + STG_A + row * ROWB + cw * 16, gb);
        cpasync16(st + STG_A + (row + 64) * ROWB + cw * 16, gb + (size_t)64 * HIDK * 2);
    }
    cpcommit();
}

__device__ __forceinline__ void mma_gemm_body(const __half* __restrict__ Ah,
                                              const __half* __restrict__ As,
                                              const __half* __restrict__ Bh,
                                              const __half* __restrict__ Bl,
                                              void* __restrict__ Cv, bool half_out) {
    extern __shared__ char sm_raw[];
    uint32_t sb = smem_u32(sm_raw);
    int tid = threadIdx.x, lane = tid & 31, wid = tid >> 5;
    int wm = wid & 3, wn = wid >> 2;
    int brow = blockIdx.y * 128, bcol = blockIdx.x * 128;

    float c[2][8][4];
#pragma unroll
    for (int i = 0; i < 2; i++)
#pragma unroll
        for (int j = 0; j < 8; j++)
#pragma unroll
            for (int l = 0; l < 4; l++) c[i][j][l] = 0.f;

    mm_issue(0, sb, tid, brow, bcol, Ah, As, Bh, Bl);
    mm_issue(1, sb, tid, brow, bcol, Ah, As, Bh, Bl);
    mm_issue(2, sb, tid, brow, bcol, Ah, As, Bh, Bl);

    int q = lane >> 3, r = lane & 7;

    for (int s = 0; s < NSTAGES; s++) {
        asm volatile("cp.async.wait_group 2;" ::: "memory");
        __syncthreads();
        // refill slot (s+3)&3 — fully consumed at iteration s-1, safe after this sync
        mm_issue(s + 3, sb, tid, brow, bcol, Ah, As, Bh, Bl);
        uint32_t st = sb + (uint32_t)(s & 3) * STG;
        uint32_t sA = st, sB = st + STG_A;
#pragma unroll
        for (int k0 = 0; k0 < 32; k0 += 16) {
            uint32_t a[2][4], b[8][2];
#pragma unroll
            for (int mf = 0; mf < 2; mf++) {
                int rrow = wm * 32 + mf * 16 + (q & 1) * 8 + r;
                int kc = k0 + (q >> 1) * 8;
                ldmx4(a[mf][0], a[mf][1], a[mf][2], a[mf][3], sA + rrow * ROWB + kc * 2);
            }
#pragma unroll
            for (int pb = 0; pb < 4; pb++) {
                int nrow = wn * 64 + pb * 16 + (q >> 1) * 8 + r;
                int kc = k0 + (q & 1) * 8;
                uint32_t r0, r1, r2, r3;
                ldmx4(r0, r1, r2, r3, sB + nrow * ROWB + kc * 2);
                b[pb * 2][0] = r0;
                b[pb * 2][1] = r1;
                b[pb * 2 + 1][0] = r2;
                b[pb * 2 + 1][1] = r3;
            }
#pragma unroll
            for (int mf = 0; mf < 2; mf++)
#pragma unroll
                for (int nf = 0; nf < 8; nf++) mma16816(c[mf][nf], a[mf], b[nf]);
        }
    }

    int qr = lane >> 2, qc = lane & 3;
    if (half_out) {
        __half* Ch = (__half*)Cv;
#pragma unroll
        for (int mf = 0; mf < 2; mf++)
#pragma unroll
            for (int nf = 0; nf < 8; nf++) {
                int row0 = brow + wm * 32 + mf * 16 + qr;
                int col = bcol + wn * 64 + nf * 8 + qc * 2;
                *(__half2*)&Ch[(size_t)row0 * HIDK + col] =
                    __floats2half2_rn(c[mf][nf][0], c[mf][nf][1]);
                *(__half2*)&Ch[(size_t)(row0 + 8) * HIDK + col] =
                    __floats2half2_rn(c[mf][nf][2], c[mf][nf][3]);
            }
    } else {
        float* Cf = (float*)Cv;
#pragma unroll
        for (int mf = 0; mf < 2; mf++)
#pragma unroll
            for (int nf = 0; nf < 8; nf++) {
                int row0 = brow + wm * 32 + mf * 16 + qr;
                int col = bcol + wn * 64 + nf * 8 + qc * 2;
                *(float2*)&Cf[(size_t)row0 * HIDK + col] =
                    make_float2(c[mf][nf][0], c[mf][nf][1]);
                *(float2*)&Cf[(size_t)(row0 + 8) * HIDK + col] =
                    make_float2(c[mf][nf][2], c[mf][nf][3]);
            }
    }
}

__global__ void __launch_bounds__(256, 2) mmproj_kernel() {
    int z = blockIdx.z;
    const __half* Bh = g_wh + (size_t)z * HIDK * HIDK;
    const __half* Bl = g_wl + (size_t)z * HIDK * HIDK;
    void* C;
    bool ho = true;
    switch (z) {
        case 0: C = g_qh16; break;
        case 1: C = g_kh16; break;
        case 2: C = g_vh16; break;
        default: C = g_xg; ho = false; break;
    }
    mma_gemm_body(g_xh, g_xs, Bh, Bl, C, ho);
}
__global__ void __launch_bounds__(256, 2) mmout_kernel(float* __restrict__ out) {
    mma_gemm_body(g_yh, g_ys, g_wh + (size_t)4 * HIDK * HIDK,
                  g_wl + (size_t)4 * HIDK * HIDK, out, false);
}

// ======================= conversion kernels =====================
#define SC_DN (1.f / 1024.f)
__global__ void __launch_bounds__(256) xconv_kernel(const float* __restrict__ x) {
    size_t i = (size_t)blockIdx.x * 256 + threadIdx.x;
    float4 v = ((const float4*)x)[i];
    __half2* ph = (__half2*)g_xh;
    __half2* ps = (__half2*)g_xs;
    ph[2 * i] = __halves2half2(__float2half(v.x), __float2half(v.y));
    ph[2 * i + 1] = __halves2half2(__float2half(v.z), __float2half(v.w));
    ps[2 * i] = __halves2half2(__float2half(v.x * SC_DN), __float2half(v.y * SC_DN));
    ps[2 * i + 1] = __halves2half2(__float2half(v.z * SC_DN), __float2half(v.w * SC_DN));
}

__global__ void __launch_bounds__(256) wconv_kernel(const float* __restrict__ W0,
                                                    const float* __restrict__ W1,
                                                    const float* __restrict__ W2,
                                                    const float* __restrict__ W3,
                                                    const float* __restrict__ W4) {
    int z = blockIdx.z;
    const float* W = (z == 0) ? W0 : (z == 1) ? W1 : (z == 2) ? W2 : (z == 3) ? W3 : W4;
    __half* Th = g_wh + (size_t)z * HIDK * HIDK;
    __half* Tl = g_wl + (size_t)z * HIDK * HIDK;
    __shared__ float t[32][33];
    int n0 = blockIdx.x * 32, k0 = blockIdx.y * 32;
    int lx = threadIdx.x & 31, ly = threadIdx.x >> 5;
#pragma unroll
    for (int i = 0; i < 4; i++) {
        int r = ly + i * 8;
        t[r][lx] = W[(size_t)(k0 + r) * HIDK + n0 + lx];
    }
    __syncthreads();
#pragma unroll
    for (int i = 0; i < 4; i++) {
        int r = ly + i * 8;
        float v = t[lx][r];
        __half h = __float2half(v);
        size_t o = (size_t)(n0 + r) * HIDK + k0 + lx;
        Th[o] = h;
        Tl[o] = __float2half((v - __half2float(h)) * 1024.f);
    }
}

// ---------------- fused low-rank gate path ---------------------
#define SMEM_LR (32 * 1024 * sizeof(float))
__global__ void __launch_bounds__(256) lr_fused_kernel(const float* __restrict__ x,
                                                       const float* __restrict__ W1,
                                                       const float* __restrict__ W2,
                                                       const float* __restrict__ bias) {
    extern __shared__ float s[];
    float* w1s = s;
    float* w2s = s + 16384;
    __shared__ float ts[16][17];
    int tid = threadIdx.x;
#pragma unroll
    for (int i = 0; i < 16; i++) {
        int idx = tid + i * 256;
        ((float4*)w1s)[idx] = ((const float4*)W1)[idx];
        ((float4*)w2s)[idx] = ((const float4*)W2)[idx];
    }
    __syncthreads();

    int m0 = blockIdx.x * 16;
    {
        int mt = tid >> 4, r = tid & 15;
        const float* xr = x + (size_t)(m0 + mt) * HIDK;
        float acc = 0.f;
#pragma unroll 8
        for (int kk = 0; kk < HIDK; kk++) acc = fmaf(xr[kk], w1s[kk * 16 + r], acc);
        ts[mt][r] = acc;
    }
    __syncthreads();

    int n = tid * 4;
    float4 b4 = *(const float4*)(bias + n);
#pragma unroll 1
    for (int mi = 0; mi < 16; mi++) {
        float4 a = b4;
#pragma unroll
        for (int rr = 0; rr < 16; rr++) {
            float tv = ts[mi][rr];
            float4 w = *(float4*)&w2s[rr * 1024 + n];
            a.x = fmaf(tv, w.x, a.x);
            a.y = fmaf(tv, w.y, a.y);
            a.z = fmaf(tv, w.z, a.z);
            a.w = fmaf(tv, w.w, a.w);
        }
        float ox = (fminf(a.x, 0.f) - __logf(1.f + __expf(-fabsf(a.x)))) * 0.0625f;
        float oy = (fminf(a.y, 0.f) - __logf(1.f + __expf(-fabsf(a.y)))) * 0.0625f;
        float oz = (fminf(a.z, 0.f) - __logf(1.f + __expf(-fabsf(a.z)))) * 0.0625f;
        float ow = (fminf(a.w, 0.f) - __logf(1.f + __expf(-fabsf(a.w)))) * 0.0625f;
        size_t go = (size_t)(m0 + mi) * HIDK + n;
        *(__half2*)&g_gkh[go] = __floats2half2_rn(ox, oy);
        *(__half2*)&g_gkh[go + 2] = __floats2half2_rn(oz, ow);
    }
}

// ---------------- chunked GLA: kernel A — fp16 tensor cores -----------------
// smem: sGf fp32 [64][68]; Vh/Qh/Kh/Uh/Ah fp16 [64][72]
#define OFF_V 17408
#define OFF_Q 26624
#define OFF_K 35840
#define OFF_U 45056
#define OFF_A 54272
#define SMEM_CH 63488

__global__ void __launch_bounds__(256) chunk_kernel() {
    extern __shared__ char smc[];
    float* sGf = (float*)smc;
    uint32_t sb = smem_u32(smc);
    uint32_t Qb = sb + OFF_Q, Kb = sb + OFF_K, Ub = sb + OFF_U, Ab = sb + OFF_A;
    __half* VhP = (__half*)(smc + OFF_V);
    __half* QhP = (__half*)(smc + OFF_Q);
    __half* KhP = (__half*)(smc + OFF_K);
    __half* UhP = (__half*)(smc + OFF_U);
    __half* AhP = (__half*)(smc + OFF_A);
    __shared__ float sTot[4][64];

    int c = blockIdx.x, bh = blockIdx.y;
    int b = bh >> 4, h = bh & 15;
    int tid = threadIdx.x;
    size_t rowbase = (size_t)(b * LSEQ + c * CT) * HIDK + h * HDIM;

    // stage fp16 q,k,v + gk(fp16)->fp32
#pragma unroll
    for (int i = 0; i < 2; i++) {
        int idx = tid + i * 256;              // 0..511
        int t = idx >> 3, c8 = (idx & 7) << 3;
        size_t gi = rowbase + (size_t)t * HIDK + c8;
        *(uint4*)&QhP[t * PDH + c8] = *(const uint4*)(g_qh16 + gi);
        *(uint4*)&KhP[t * PDH + c8] = *(const uint4*)(g_kh16 + gi);
        *(uint4*)&VhP[t * PDH + c8] = *(const uint4*)(g_vh16 + gi);
        uint4 gg4 = *(const uint4*)(g_gkh + gi);
        const __half2* gh = (const __half2*)&gg4;
        float* dst = &sGf[t * PD + c8];
        float2 a0 = __half22float2(gh[0]);
        float2 a1 = __half22float2(gh[1]);
        float2 a2 = __half22float2(gh[2]);
        float2 a3 = __half22float2(gh[3]);
        dst[0] = a0.x; dst[1] = a0.y; dst[2] = a1.x; dst[3] = a1.y;
        dst[4] = a2.x; dst[5] = a2.y; dst[6] = a3.x; dst[7] = a3.y;
    }
    __syncthreads();

    // segment-parallel cumsum -> sGf = exp(D), Uh = fp16(exp(-D)*v)
    {
        int ch = tid & 63, seg = tid >> 6;
        int t0s = seg * 16;
        float run = 0.f;
#pragma unroll
        for (int t = t0s; t < t0s + 16; t++) {
            run += sGf[t * PD + ch];
            sGf[t * PD + ch] = run;
        }
        sTot[seg][ch] = run;
    }
    __syncthreads();
    {
        int ch = tid & 63, seg = tid >> 6;
        float off = 0.f;
        if (seg > 0) off += sTot[0][ch];
        if (seg > 1) off += sTot[1][ch];
        if (seg > 2) off += sTot[2][ch];
        int t0s = seg * 16;
#pragma unroll
        for (int t = t0s; t < t0s + 16; t++) {
            float D = sGf[t * PD + ch] + off;
            sGf[t * PD + ch] = __expf(D);
            UhP[t * PDH + ch] = __float2half(__expf(-D) * __half2float(VhP[t * PDH + ch]));
        }
    }
    __syncthreads();

    // write exp(D) fp16 to global
#pragma unroll
    for (int i = 0; i < 2; i++) {
        int idx = tid + i * 256;
        int t = idx >> 3, c8 = (idx & 7) << 3;
        __half h8[8];
#pragma unroll
        for (int j = 0; j < 8; j++) h8[j] = __float2half(sGf[t * PD + c8 + j]);
        *(uint4*)(g_expDh + rowbase + (size_t)t * HIDK + c8) = *(uint4*)h8;
    }

    int w = tid >> 5, l = tid & 31;
    int m0 = (w & 3) << 4, n0h = (w >> 2) << 5;
    int lr2 = l >> 2, lc2 = (l & 3) << 1;

    // ---- GEMM1: A[t,s] = Q.K^T, masked -> Ah fp16 ----
    {
        float cc[4][4];
#pragma unroll
        for (int i = 0; i < 4; i++)
#pragma unroll
            for (int j = 0; j < 4; j++) cc[i][j] = 0.f;
#pragma unroll
        for (int k0 = 0; k0 < 64; k0 += 16) {
            uint32_t a[4], b0[4], b1[4];
            ldmx4(a[0], a[1], a[2], a[3],
                  Qb + ((m0 + (l & 15)) * PDH + k0 + ((l & 16) ? 8 : 0)) * 2);
            ldmx4(b0[0], b0[1], b0[2], b0[3],
                  Kb + ((n0h + (l & 7) + ((l & 16) ? 8 : 0)) * PDH + k0 + ((l & 8) ? 8 : 0)) * 2);
            ldmx4(b1[0], b1[1], b1[2], b1[3],
                  Kb + ((n0h + 16 + (l & 7) + ((l & 16) ? 8 : 0)) * PDH + k0 + ((l & 8) ? 8 : 0)) * 2);
            mma16816(cc[0], a, &b0[0]);
            mma16816(cc[1], a, &b0[2]);
            mma16816(cc[2], a, &b1[0]);
            mma16816(cc[3], a, &b1[2]);
        }
        int tr = m0 + lr2;
#pragma unroll
        for (int nf = 0; nf < 4; nf++) {
            int sc = n0h + nf * 8 + lc2;
            *(__half2*)&AhP[tr * PDH + sc] = __halves2half2(
                __float2half(sc <= tr ? cc[nf][0] : 0.f),
                __float2half(sc + 1 <= tr ? cc[nf][1] : 0.f));
            int tr2 = tr + 8;
            *(__half2*)&AhP[tr2 * PDH + sc] = __halves2half2(
                __float2half(sc <= tr2 ? cc[nf][2] : 0.f),
                __float2half(sc + 1 <= tr2 ? cc[nf][3] : 0.f));
        }
    }
    __syncthreads();

    // ---- GEMM2: o_intra[t,v] = A'.U; scale expD; store fp16 ----
    {
        float cc[4][4];
#pragma unroll
        for (int i = 0; i < 4; i++)
#pragma unroll
            for (int j = 0; j < 4; j++) cc[i][j] = 0.f;
#pragma unroll
        for (int s0 = 0; s0 < 64; s0 += 16) {
            uint32_t a[4], b0[4], b1[4];
            ldmx4(a[0], a[1], a[2], a[3],
                  Ab + ((m0 + (l & 15)) * PDH + s0 + ((l & 16) ? 8 : 0)) * 2);
            ldmx4t(b0[0], b0[1], b0[2], b0[3],
                   Ub + ((s0 + (l & 15)) * PDH + n0h + ((l & 16) ? 8 : 0)) * 2);
            ldmx4t(b1[0], b1[1], b1[2], b1[3],
                   Ub + ((s0 + (l & 15)) * PDH + n0h + 16 + ((l & 16) ? 8 : 0)) * 2);
            mma16816(cc[0], a, &b0[0]);
            mma16816(cc[1], a, &b0[2]);
            mma16816(cc[2], a, &b1[0]);
            mma16816(cc[3], a, &b1[2]);
        }
        int tr = m0 + lr2;
#pragma unroll
        for (int nf = 0; nf < 4; nf++) {
            int v = n0h + nf * 8 + lc2;
            float2 e0 = *(float2*)&sGf[tr * PD + v];
            *(__half2*)&g_atth[rowbase + (size_t)tr * HIDK + v] =
                __floats2half2_rn(cc[nf][0] * e0.x, cc[nf][1] * e0.y);
            float2 e1 = *(float2*)&sGf[(tr + 8) * PD + v];
            *(__half2*)&g_atth[rowbase + (size_t)(tr + 8) * HIDK + v] =
                __floats2half2_rn(cc[nf][2] * e1.x, cc[nf][3] * e1.y);
        }
    }

    // ---- GEMM3: P[v,kd] = U^T.K; scale expD_end; store fp16 ----
    {
        float cc[4][4];
#pragma unroll
        for (int i = 0; i < 4; i++)
#pragma unroll
            for (int j = 0; j < 4; j++) cc[i][j] = 0.f;
#pragma unroll
        for (int s0 = 0; s0 < 64; s0 += 16) {
            uint32_t a[4], b0[4], b1[4];
            ldmx4t(a[0], a[1], a[2], a[3],
                   Ub + ((s0 + (l & 7) + ((l & 16) ? 8 : 0)) * PDH + m0 + ((l & 8) ? 8 : 0)) * 2);
            ldmx4t(b0[0], b0[1], b0[2], b0[3],
                   Kb + ((s0 + (l & 15)) * PDH + n0h + ((l & 16) ? 8 : 0)) * 2);
            ldmx4t(b1[0], b1[1], b1[2], b1[3],
                   Kb + ((s0 + (l & 15)) * PDH + n0h + 16 + ((l & 16) ? 8 : 0)) * 2);
            mma16816(cc[0], a, &b0[0]);
            mma16816(cc[1], a, &b0[2]);
            mma16816(cc[2], a, &b1[0]);
            mma16816(cc[3], a, &b1[2]);
        }
        size_t pbase = ((size_t)(bh * NCH + c)) << 12;
        int vr = m0 + lr2;
        float ev0 = sGf[63 * PD + vr];
        float ev1 = sGf[63 * PD + vr + 8];
#pragma unroll
        for (int nf = 0; nf < 4; nf++) {
            int kd = n0h + nf * 8 + lc2;
            *(__half2*)&g_Ph[pbase + ((size_t)vr << 6) + kd] =
                __floats2half2_rn(cc[nf][0] * ev0, cc[nf][1] * ev0);
            *(__half2*)&g_Ph[pbase + ((size_t)(vr + 8) << 6) + kd] =
                __floats2half2_rn(cc[nf][2] * ev1, cc[nf][3] * ev1);
        }
    }
}

// ---------------- kernel B: scan over chunk states (k-split, fp16 I/O) -----
__global__ void __launch_bounds__(512) chunkscan_kernel() {
    int ks = blockIdx.x;
    int bh = blockIdx.y;
    int b = bh >> 4, h = bh & 15;
    int tid = threadIdx.x;
    int v = tid >> 3;
    int k = ks * 16 + (tid & 7) * 2;
    float2 S = make_float2(0.f, 0.f);

    for (int c = 0; c < NCH; c++) {
        size_t base = (((size_t)(bh * NCH + c)) << 12) + ((size_t)v << 6) + k;
        *(__half2*)(g_Sh + base) = __floats2half2_rn(S.x, S.y);
        float E = __half2float(g_expDh[((size_t)(b * LSEQ + c * CT + 63)) * HIDK + h * HDIM + v]);
        float2 p = __half22float2(*(__half2*)(g_Ph + base));
        S.x = fmaf(S.x, E, p.x);
        S.y = fmaf(S.y, E, p.y);
    }
}

// ---------------- kernel C: inter-chunk output — fp16 tensor cores ---------
__global__ void __launch_bounds__(256) inter_kernel() {
    __shared__ __align__(16) __half sQ[64 * PDH];
    __shared__ __align__(16) __half sS[64 * PDH];
    int c = blockIdx.x, bh = blockIdx.y;
    int b = bh >> 4, h = bh & 15;
    int tid = threadIdx.x;
    size_t rowbase = (size_t)(b * LSEQ + c * CT) * HIDK + h * HDIM;
    size_t sbase = ((size_t)(bh * NCH + c)) << 12;
    uint32_t Qb = smem_u32(sQ), Sb = smem_u32(sS);

#pragma unroll
    for (int i = 0; i < 2; i++) {
        int idx = tid + i * 256;
        int t = idx >> 3, c8 = (idx & 7) << 3;
        *(uint4*)&sQ[t * PDH + c8] = *(const uint4*)(g_qh16 + rowbase + (size_t)t * HIDK + c8);
        *(uint4*)&sS[t * PDH + c8] = *(const uint4*)(g_Sh + sbase + ((size_t)t << 6) + c8);
    }
    __syncthreads();

    int w = tid >> 5, l = tid & 31;
    int m0 = (w & 3) << 4, n0h = (w >> 2) << 5;
    int lr2 = l >> 2, lc2 = (l & 3) << 1;

    float cc[4][4];
#pragma unroll
    for (int i = 0; i < 4; i++)
#pragma unroll
        for (int j = 0; j < 4; j++) cc[i][j] = 0.f;
#pragma unroll
    for (int k0 = 0; k0 < 64; k0 += 16) {
        uint32_t a[4], b0[4], b1[4];
        ldmx4(a[0], a[1], a[2], a[3],
              Qb + ((m0 + (l & 15)) * PDH + k0 + ((l & 16) ? 8 : 0)) * 2);
        ldmx4(b0[0], b0[1], b0[2], b0[3],
              Sb + ((n0h + (l & 7) + ((l & 16) ? 8 : 0)) * PDH + k0 + ((l & 8) ? 8 : 0)) * 2);
        ldmx4(b1[0], b1[1], b1[2], b1[3],
              Sb + ((n0h + 16 + (l & 7) + ((l & 16) ? 8 : 0)) * PDH + k0 + ((l & 8) ? 8 : 0)) * 2);
        mma16816(cc[0], a, &b0[0]);
        mma16816(cc[1], a, &b0[2]);
        mma16816(cc[2], a, &b1[0]);
        mma16816(cc[3], a, &b1[2]);
    }
    int tr = m0 + lr2;
#pragma unroll
    for (int nf = 0; nf < 4; nf++) {
        int v = n0h + nf * 8 + lc2;
        size_t gi0 = rowbase + (size_t)tr * HIDK + v;
        float2 e0 = __half22float2(*(__half2*)(g_expDh + gi0));
        float2 i0 = __half22float2(*(__half2*)(g_atth + gi0));
        *(float2*)(g_att + gi0) =
            make_float2(fmaf(cc[nf][0], e0.x, i0.x), fmaf(cc[nf][1], e0.y, i0.y));
        size_t gi1 = rowbase + (size_t)(tr + 8) * HIDK + v;
        float2 e1 = __half22float2(*(__half2*)(g_expDh + gi1));
        float2 i1 = __half22float2(*(__half2*)(g_atth + gi1));
        *(float2*)(g_att + gi1) =
            make_float2(fmaf(cc[nf][2], e1.x, i1.x), fmaf(cc[nf][3], e1.y, i1.y));
    }
}

// ---------------- LayerNorm + SiLU gate -> fp16 y (+ scaled copy) ----------
__global__ void __launch_bounds__(256) ln_gate_kernel(const float* __restrict__ gamma,
                                                      const float* __restrict__ beta) {
    int row = blockIdx.x;
    int tid = threadIdx.x;
    const float* a = g_att + (size_t)row * HIDK;
    float vals[4];
    float s = 0.f, s2 = 0.f;
#pragma unroll
    for (int i = 0; i < 4; i++) {
        vals[i] = a[i * 256 + tid];
        s += vals[i];
        s2 = fmaf(vals[i], vals[i], s2);
    }
#pragma unroll
    for (int o = 16; o; o >>= 1) {
        s += __shfl_xor_sync(0xffffffffu, s, o);
        s2 += __shfl_xor_sync(0xffffffffu, s2, o);
    }
    __shared__ float rs[8], rs2[8];
    int warp = tid >> 5;
    if ((tid & 31) == 0) { rs[warp] = s; rs2[warp] = s2; }
    __syncthreads();
    s = 0.f;
    s2 = 0.f;
#pragma unroll
    for (int w = 0; w < 8; w++) { s += rs[w]; s2 += rs2[w]; }
    float mean = s * (1.f / HIDK);
    float var = s2 * (1.f / HIDK) - mean * mean;
    float rstd = rsqrtf(var + 1e-5f);
#pragma unroll
    for (int i = 0; i < 4; i++) {
        int col = i * 256 + tid;
        float gv = g_xg[(size_t)row * HIDK + col];
        float sil = gv / (1.f + __expf(-gv));
        float yv = ((vals[i] - mean) * rstd * gamma[col] + beta[col]) * sil;
        g_yh[(size_t)row * HIDK + col] = __float2half(yv);
        g_ys[(size_t)row * HIDK + col] = __float2half(yv * SC_DN);
    }
}

// ---------------- launch --------------------------------------------------
extern "C" void kernel_launch(void* const* d_in, const int* in_sizes, int n_in,
                              void* d_out, int out_size) {
    const float* x = (const float*)d_in[0];
    const float* Wq = (const float*)d_in[1];
    const float* Wk = (const float*)d_in[2];
    const float* Wv = (const float*)d_in[3];
    const float* Wg = (const float*)d_in[4];
    const float* Wgk1 = (const float*)d_in[5];
    const float* Wgk2 = (const float*)d_in[6];
    const float* bgk2 = (const float*)d_in[7];
    const float* gamma = (const float*)d_in[8];
    const float* beta = (const float*)d_in[9];
    const float* Wout = (const float*)d_in[10];
    float* out = (float*)d_out;

    cudaFuncSetAttribute(chunk_kernel, cudaFuncAttributeMaxDynamicSharedMemorySize, SMEM_CH);
    cudaFuncSetAttribute(mmproj_kernel, cudaFuncAttributeMaxDynamicSharedMemorySize, SMEM_MM);
    cudaFuncSetAttribute(mmout_kernel, cudaFuncAttributeMaxDynamicSharedMemorySize, SMEM_MM);
    cudaFuncSetAttribute(lr_fused_kernel, cudaFuncAttributeMaxDynamicSharedMemorySize, SMEM_LR);

    xconv_kernel<<<MTOK * HIDK / 1024, 256>>>(x);
    wconv_kernel<<<dim3(32, 32, 5), 256>>>(Wq, Wk, Wv, Wg, Wout);
    lr_fused_kernel<<<MTOK / 16, 256, SMEM_LR>>>(x, Wgk1, Wgk2, bgk2);

    mmproj_kernel<<<dim3(8, 32, 4), 256, SMEM_MM>>>();

    chunk_kernel<<<dim3(NCH, 32), 256, SMEM_CH>>>();
    chunkscan_kernel<<<dim3(4, 32), 512>>>();
    inter_kernel<<<dim3(NCH, 32), 256>>>();
    ln_gate_kernel<<<MTOK, 256>>>(gamma, beta);

    mmout_kernel<<<dim3(8, 32, 1), 256, SMEM_MM>>>(out);
}

// round 10
// speedup vs baseline: 1.0673x; 1.0673x over previous
#include <cuda_runtime.h>
#include <cuda_fp16.h>
#include <math.h>
#include <stdint.h>

#define HIDK 1024
#define MTOK 4096
#define LSEQ 2048
#define NHEAD 16
#define HDIM 64
#define CT 64
#define NCH (LSEQ / CT)
#define PD 68
#define PDH 72

// ---------------- scratch (device globals; no allocations) ----------------
__device__ float g_xg[MTOK * HIDK];
__device__ float g_att[MTOK * HIDK];                      // final o (inter writes)
__device__ __align__(16) __half g_qh16[MTOK * HIDK];
__device__ __align__(16) __half g_kh16[MTOK * HIDK];
__device__ __align__(16) __half g_vh16[MTOK * HIDK];
__device__ __align__(16) __half g_gkh[MTOK * HIDK];
__device__ __align__(16) __half g_expDh[MTOK * HIDK];
__device__ __align__(16) __half g_atth[MTOK * HIDK];      // intra-chunk o
__device__ __align__(16) __half g_Ph[32 * NCH * HDIM * HDIM];
__device__ __align__(16) __half g_Sh[32 * NCH * HDIM * HDIM];
// fp16 GEMM operands: activations single + 2^-10-scaled copy; weights exact pair
__device__ __align__(16) __half g_xh[MTOK * HIDK];
__device__ __align__(16) __half g_xs[MTOK * HIDK];
__device__ __align__(16) __half g_yh[MTOK * HIDK];
__device__ __align__(16) __half g_ys[MTOK * HIDK];
__device__ __align__(16) __half g_wh[5 * HIDK * HIDK];
__device__ __align__(16) __half g_wl[5 * HIDK * HIDK];

// ======================= helpers =======================
__device__ __forceinline__ uint32_t smem_u32(const void* p) {
    uint32_t a;
    asm("{ .reg .u64 t; cvta.to.shared.u64 t, %1; cvt.u32.u64 %0, t; }" : "=r"(a) : "l"(p));
    return a;
}
__device__ __forceinline__ void cpasync16(uint32_t s, const void* g) {
    asm volatile("cp.async.cg.shared.global [%0], [%1], 16;" ::"r"(s), "l"(g));
}
__device__ __forceinline__ void cpcommit() { asm volatile("cp.async.commit_group;"); }

__device__ __forceinline__ void ldmx4(uint32_t& r0, uint32_t& r1, uint32_t& r2,
                                      uint32_t& r3, uint32_t addr) {
    asm volatile("ldmatrix.sync.aligned.m8n8.x4.shared.b16 {%0,%1,%2,%3}, [%4];"
                 : "=r"(r0), "=r"(r1), "=r"(r2), "=r"(r3)
                 : "r"(addr));
}
__device__ __forceinline__ void ldmx4t(uint32_t& r0, uint32_t& r1, uint32_t& r2,
                                       uint32_t& r3, uint32_t addr) {
    asm volatile("ldmatrix.sync.aligned.m8n8.x4.trans.shared.b16 {%0,%1,%2,%3}, [%4];"
                 : "=r"(r0), "=r"(r1), "=r"(r2), "=r"(r3)
                 : "r"(addr));
}
__device__ __forceinline__ void mma16816(float* c, const uint32_t* a, const uint32_t* b) {
    asm volatile(
        "mma.sync.aligned.m16n8k16.row.col.f32.f16.f16.f32 "
        "{%0,%1,%2,%3}, {%4,%5,%6,%7}, {%8,%9}, {%0,%1,%2,%3};"
        : "+f"(c[0]), "+f"(c[1]), "+f"(c[2]), "+f"(c[3])
        : "r"(a[0]), "r"(a[1]), "r"(a[2]), "r"(a[3]), "r"(b[0]), "r"(b[1]));
}

// ======================= fp16 mma.sync big GEMM (R8 ordering) ==============
#define ROWB 80
#define STG_A (128 * ROWB)
#define STG (2 * STG_A)
#define NSTG 4
#define SMEM_MM (NSTG * STG)
#define NSTAGES 64

__device__ __forceinline__ void mm_issue(int s, uint32_t sb, int tid, int brow, int bcol,
                                         const __half* Ah, const __half* As,
                                         const __half* Bh, const __half* Bl) {
    if (s < NSTAGES) {
        int p = s >> 5;
        int kk = (s & 31) << 5;
        const __half* Ab = p ? As : Ah;
        const __half* Bb = p ? Bl : Bh;
        uint32_t st = sb + (uint32_t)(s & 3) * STG;
        int row = tid >> 2, cw = tid & 3;
        const char* ga = (const char*)(Ab + (size_t)(brow + row) * HIDK + kk + cw * 8);
        cpasync16(st + row * ROWB + cw * 16, ga);
        cpasync16(st + (row + 64) * ROWB + cw * 16, ga + (size_t)64 * HIDK * 2);
        const char* gb = (const char*)(Bb + (size_t)(bcol + row) * HIDK + kk + cw * 8);
        cpasync16(st + STG_A + row * ROWB + cw * 16, gb);
        cpasync16(st + STG_A + (row + 64) * ROWB + cw * 16, gb + (size_t)64 * HIDK * 2);
    }
    cpcommit();
}

__device__ __forceinline__ void mma_gemm_body(const __half* __restrict__ Ah,
                                              const __half* __restrict__ As,
                                              const __half* __restrict__ Bh,
                                              const __half* __restrict__ Bl,
                                              void* __restrict__ Cv, bool half_out) {
    extern __shared__ char sm_raw[];
    uint32_t sb = smem_u32(sm_raw);
    int tid = threadIdx.x, lane = tid & 31, wid = tid >> 5;
    int wm = wid & 3, wn = wid >> 2;
    int brow = blockIdx.y * 128, bcol = blockIdx.x * 128;

    float c[2][8][4];
#pragma unroll
    for (int i = 0; i < 2; i++)
#pragma unroll
        for (int j = 0; j < 8; j++)
#pragma unroll
            for (int l = 0; l < 4; l++) c[i][j][l] = 0.f;

    mm_issue(0, sb, tid, brow, bcol, Ah, As, Bh, Bl);
    mm_issue(1, sb, tid, brow, bcol, Ah, As, Bh, Bl);
    mm_issue(2, sb, tid, brow, bcol, Ah, As, Bh, Bl);

    int q = lane >> 3, r = lane & 7;

    for (int s = 0; s < NSTAGES; s++) {
        asm volatile("cp.async.wait_group 2;" ::: "memory");
        __syncthreads();
        uint32_t st = sb + (uint32_t)(s & 3) * STG;
        uint32_t sA = st, sB = st + STG_A;
#pragma unroll
        for (int k0 = 0; k0 < 32; k0 += 16) {
            uint32_t a[2][4], b[8][2];
#pragma unroll
            for (int mf = 0; mf < 2; mf++) {
                int rrow = wm * 32 + mf * 16 + (q & 1) * 8 + r;
                int kc = k0 + (q >> 1) * 8;
                ldmx4(a[mf][0], a[mf][1], a[mf][2], a[mf][3], sA + rrow * ROWB + kc * 2);
            }
#pragma unroll
            for (int pb = 0; pb < 4; pb++) {
                int nrow = wn * 64 + pb * 16 + (q >> 1) * 8 + r;
                int kc = k0 + (q & 1) * 8;
                uint32_t r0, r1, r2, r3;
                ldmx4(r0, r1, r2, r3, sB + nrow * ROWB + kc * 2);
                b[pb * 2][0] = r0;
                b[pb * 2][1] = r1;
                b[pb * 2 + 1][0] = r2;
                b[pb * 2 + 1][1] = r3;
            }
#pragma unroll
            for (int mf = 0; mf < 2; mf++)
#pragma unroll
                for (int nf = 0; nf < 8; nf++) mma16816(c[mf][nf], a[mf], b[nf]);
        }
        mm_issue(s + 3, sb, tid, brow, bcol, Ah, As, Bh, Bl);
    }

    int qr = lane >> 2, qc = lane & 3;
    if (half_out) {
        __half* Ch = (__half*)Cv;
#pragma unroll
        for (int mf = 0; mf < 2; mf++)
#pragma unroll
            for (int nf = 0; nf < 8; nf++) {
                int row0 = brow + wm * 32 + mf * 16 + qr;
                int col = bcol + wn * 64 + nf * 8 + qc * 2;
                *(__half2*)&Ch[(size_t)row0 * HIDK + col] =
                    __floats2half2_rn(c[mf][nf][0], c[mf][nf][1]);
                *(__half2*)&Ch[(size_t)(row0 + 8) * HIDK + col] =
                    __floats2half2_rn(c[mf][nf][2], c[mf][nf][3]);
            }
    } else {
        float* Cf = (float*)Cv;
#pragma unroll
        for (int mf = 0; mf < 2; mf++)
#pragma unroll
            for (int nf = 0; nf < 8; nf++) {
                int row0 = brow + wm * 32 + mf * 16 + qr;
                int col = bcol + wn * 64 + nf * 8 + qc * 2;
                *(float2*)&Cf[(size_t)row0 * HIDK + col] =
                    make_float2(c[mf][nf][0], c[mf][nf][1]);
                *(float2*)&Cf[(size_t)(row0 + 8) * HIDK + col] =
                    make_float2(c[mf][nf][2], c[mf][nf][3]);
            }
    }
}

__global__ void __launch_bounds__(256, 2) mmproj_kernel() {
    int z = blockIdx.z;
    const __half* Bh = g_wh + (size_t)z * HIDK * HIDK;
    const __half* Bl = g_wl + (size_t)z * HIDK * HIDK;
    void* C;
    bool ho = true;
    switch (z) {
        case 0: C = g_qh16; break;
        case 1: C = g_kh16; break;
        case 2: C = g_vh16; break;
        default: C = g_xg; ho = false; break;
    }
    mma_gemm_body(g_xh, g_xs, Bh, Bl, C, ho);
}
__global__ void __launch_bounds__(256, 2) mmout_kernel(float* __restrict__ out) {
    mma_gemm_body(g_yh, g_ys, g_wh + (size_t)4 * HIDK * HIDK,
                  g_wl + (size_t)4 * HIDK * HIDK, out, false);
}

// ======================= conversion kernels =====================
#define SC_DN (1.f / 1024.f)
__global__ void __launch_bounds__(256) xconv_kernel(const float* __restrict__ x) {
    size_t i = (size_t)blockIdx.x * 256 + threadIdx.x;
    float4 v = ((const float4*)x)[i];
    __half2* ph = (__half2*)g_xh;
    __half2* ps = (__half2*)g_xs;
    ph[2 * i] = __halves2half2(__float2half(v.x), __float2half(v.y));
    ph[2 * i + 1] = __halves2half2(__float2half(v.z), __float2half(v.w));
    ps[2 * i] = __halves2half2(__float2half(v.x * SC_DN), __float2half(v.y * SC_DN));
    ps[2 * i + 1] = __halves2half2(__float2half(v.z * SC_DN), __float2half(v.w * SC_DN));
}

__global__ void __launch_bounds__(256) wconv_kernel(const float* __restrict__ W0,
                                                    const float* __restrict__ W1,
                                                    const float* __restrict__ W2,
                                                    const float* __restrict__ W3,
                                                    const float* __restrict__ W4) {
    int z = blockIdx.z;
    const float* W = (z == 0) ? W0 : (z == 1) ? W1 : (z == 2) ? W2 : (z == 3) ? W3 : W4;
    __half* Th = g_wh + (size_t)z * HIDK * HIDK;
    __half* Tl = g_wl + (size_t)z * HIDK * HIDK;
    __shared__ float t[32][33];
    int n0 = blockIdx.x * 32, k0 = blockIdx.y * 32;
    int lx = threadIdx.x & 31, ly = threadIdx.x >> 5;
#pragma unroll
    for (int i = 0; i < 4; i++) {
        int r = ly + i * 8;
        t[r][lx] = W[(size_t)(k0 + r) * HIDK + n0 + lx];
    }
    __syncthreads();
#pragma unroll
    for (int i = 0; i < 4; i++) {
        int r = ly + i * 8;
        float v = t[lx][r];
        __half h = __float2half(v);
        size_t o = (size_t)(n0 + r) * HIDK + k0 + lx;
        Th[o] = h;
        Tl[o] = __float2half((v - __half2float(h)) * 1024.f);
    }
}

// ---------------- fused low-rank gate path ---------------------
#define SMEM_LR (32 * 1024 * sizeof(float))
__global__ void __launch_bounds__(256) lr_fused_kernel(const float* __restrict__ x,
                                                       const float* __restrict__ W1,
                                                       const float* __restrict__ W2,
                                                       const float* __restrict__ bias) {
    extern __shared__ float s[];
    float* w1s = s;
    float* w2s = s + 16384;
    __shared__ float ts[16][17];
    int tid = threadIdx.x;
#pragma unroll
    for (int i = 0; i < 16; i++) {
        int idx = tid + i * 256;
        ((float4*)w1s)[idx] = ((const float4*)W1)[idx];
        ((float4*)w2s)[idx] = ((const float4*)W2)[idx];
    }
    __syncthreads();

    int m0 = blockIdx.x * 16;
    {
        int mt = tid >> 4, r = tid & 15;
        const float* xr = x + (size_t)(m0 + mt) * HIDK;
        float acc = 0.f;
#pragma unroll 8
        for (int kk = 0; kk < HIDK; kk++) acc = fmaf(xr[kk], w1s[kk * 16 + r], acc);
        ts[mt][r] = acc;
    }
    __syncthreads();

    int n = tid * 4;
    float4 b4 = *(const float4*)(bias + n);
#pragma unroll 1
    for (int mi = 0; mi < 16; mi++) {
        float4 a = b4;
#pragma unroll
        for (int rr = 0; rr < 16; rr++) {
            float tv = ts[mi][rr];
            float4 w = *(float4*)&w2s[rr * 1024 + n];
            a.x = fmaf(tv, w.x, a.x);
            a.y = fmaf(tv, w.y, a.y);
            a.z = fmaf(tv, w.z, a.z);
            a.w = fmaf(tv, w.w, a.w);
        }
        float ox = (fminf(a.x, 0.f) - __logf(1.f + __expf(-fabsf(a.x)))) * 0.0625f;
        float oy = (fminf(a.y, 0.f) - __logf(1.f + __expf(-fabsf(a.y)))) * 0.0625f;
        float oz = (fminf(a.z, 0.f) - __logf(1.f + __expf(-fabsf(a.z)))) * 0.0625f;
        float ow = (fminf(a.w, 0.f) - __logf(1.f + __expf(-fabsf(a.w)))) * 0.0625f;
        size_t go = (size_t)(m0 + mi) * HIDK + n;
        *(__half2*)&g_gkh[go] = __floats2half2_rn(ox, oy);
        *(__half2*)&g_gkh[go + 2] = __floats2half2_rn(oz, ow);
    }
}

// ---------------- chunked GLA: kernel A — fp16 tensor cores -----------------
// smem: sGf fp32 [64][68]; Vh/Qh/Kh/Uh/Ah fp16 [64][72]
#define OFF_V 17408
#define OFF_Q 26624
#define OFF_K 35840
#define OFF_U 45056
#define OFF_A 54272
#define SMEM_CH 63488

__global__ void __launch_bounds__(256) chunk_kernel() {
    extern __shared__ char smc[];
    float* sGf = (float*)smc;
    uint32_t sb = smem_u32(smc);
    uint32_t Qb = sb + OFF_Q, Kb = sb + OFF_K, Ub = sb + OFF_U, Ab = sb + OFF_A;
    __half* VhP = (__half*)(smc + OFF_V);
    __half* QhP = (__half*)(smc + OFF_Q);
    __half* KhP = (__half*)(smc + OFF_K);
    __half* UhP = (__half*)(smc + OFF_U);
    __half* AhP = (__half*)(smc + OFF_A);
    __shared__ float sTot[4][64];

    int c = blockIdx.x, bh = blockIdx.y;
    int b = bh >> 4, h = bh & 15;
    int tid = threadIdx.x;
    size_t rowbase = (size_t)(b * LSEQ + c * CT) * HIDK + h * HDIM;

    // stage fp16 q,k,v + gk(fp16)->fp32
#pragma unroll
    for (int i = 0; i < 2; i++) {
        int idx = tid + i * 256;              // 0..511
        int t = idx >> 3, c8 = (idx & 7) << 3;
        size_t gi = rowbase + (size_t)t * HIDK + c8;
        *(uint4*)&QhP[t * PDH + c8] = *(const uint4*)(g_qh16 + gi);
        *(uint4*)&KhP[t * PDH + c8] = *(const uint4*)(g_kh16 + gi);
        *(uint4*)&VhP[t * PDH + c8] = *(const uint4*)(g_vh16 + gi);
        uint4 gg4 = *(const uint4*)(g_gkh + gi);
        const __half2* gh = (const __half2*)&gg4;
        float* dst = &sGf[t * PD + c8];
        float2 a0 = __half22float2(gh[0]);
        float2 a1 = __half22float2(gh[1]);
        float2 a2 = __half22float2(gh[2]);
        float2 a3 = __half22float2(gh[3]);
        dst[0] = a0.x; dst[1] = a0.y; dst[2] = a1.x; dst[3] = a1.y;
        dst[4] = a2.x; dst[5] = a2.y; dst[6] = a3.x; dst[7] = a3.y;
    }
    __syncthreads();

    // segment-parallel cumsum -> sGf = exp(D), Uh = fp16(exp(-D)*v)
    {
        int ch = tid & 63, seg = tid >> 6;
        int t0s = seg * 16;
        float run = 0.f;
#pragma unroll
        for (int t = t0s; t < t0s + 16; t++) {
            run += sGf[t * PD + ch];
            sGf[t * PD + ch] = run;
        }
        sTot[seg][ch] = run;
    }
    __syncthreads();
    {
        int ch = tid & 63, seg = tid >> 6;
        float off = 0.f;
        if (seg > 0) off += sTot[0][ch];
        if (seg > 1) off += sTot[1][ch];
        if (seg > 2) off += sTot[2][ch];
        int t0s = seg * 16;
#pragma unroll
        for (int t = t0s; t < t0s + 16; t++) {
            float D = sGf[t * PD + ch] + off;
            sGf[t * PD + ch] = __expf(D);
            UhP[t * PDH + ch] = __float2half(__expf(-D) * __half2float(VhP[t * PDH + ch]));
        }
    }
    __syncthreads();

    // write exp(D) fp16 to global
#pragma unroll
    for (int i = 0; i < 2; i++) {
        int idx = tid + i * 256;
        int t = idx >> 3, c8 = (idx & 7) << 3;
        __half h8[8];
#pragma unroll
        for (int j = 0; j < 8; j++) h8[j] = __float2half(sGf[t * PD + c8 + j]);
        *(uint4*)(g_expDh + rowbase + (size_t)t * HIDK + c8) = *(uint4*)h8;
    }

    int w = tid >> 5, l = tid & 31;
    int m0 = (w & 3) << 4, n0h = (w >> 2) << 5;
    int lr2 = l >> 2, lc2 = (l & 3) << 1;

    // ---- GEMM1: A[t,s] = Q.K^T, masked -> Ah fp16 ----
    {
        float cc[4][4];
#pragma unroll
        for (int i = 0; i < 4; i++)
#pragma unroll
            for (int j = 0; j < 4; j++) cc[i][j] = 0.f;
#pragma unroll
        for (int k0 = 0; k0 < 64; k0 += 16) {
            uint32_t a[4], b0[4], b1[4];
            ldmx4(a[0], a[1], a[2], a[3],
                  Qb + ((m0 + (l & 15)) * PDH + k0 + ((l & 16) ? 8 : 0)) * 2);
            ldmx4(b0[0], b0[1], b0[2], b0[3],
                  Kb + ((n0h + (l & 7) + ((l & 16) ? 8 : 0)) * PDH + k0 + ((l & 8) ? 8 : 0)) * 2);
            ldmx4(b1[0], b1[1], b1[2], b1[3],
                  Kb + ((n0h + 16 + (l & 7) + ((l & 16) ? 8 : 0)) * PDH + k0 + ((l & 8) ? 8 : 0)) * 2);
            mma16816(cc[0], a, &b0[0]);
            mma16816(cc[1], a, &b0[2]);
            mma16816(cc[2], a, &b1[0]);
            mma16816(cc[3], a, &b1[2]);
        }
        int tr = m0 + lr2;
#pragma unroll
        for (int nf = 0; nf < 4; nf++) {
            int sc = n0h + nf * 8 + lc2;
            *(__half2*)&AhP[tr * PDH + sc] = __halves2half2(
                __float2half(sc <= tr ? cc[nf][0] : 0.f),
                __float2half(sc + 1 <= tr ? cc[nf][1] : 0.f));
            int tr2 = tr + 8;
            *(__half2*)&AhP[tr2 * PDH + sc] = __halves2half2(
                __float2half(sc <= tr2 ? cc[nf][2] : 0.f),
                __float2half(sc + 1 <= tr2 ? cc[nf][3] : 0.f));
        }
    }
    __syncthreads();

    // ---- GEMM2: o_intra[t,v] = A'.U; scale expD; store fp16 ----
    {
        float cc[4][4];
#pragma unroll
        for (int i = 0; i < 4; i++)
#pragma unroll
            for (int j = 0; j < 4; j++) cc[i][j] = 0.f;
#pragma unroll
        for (int s0 = 0; s0 < 64; s0 += 16) {
            uint32_t a[4], b0[4], b1[4];
            ldmx4(a[0], a[1], a[2], a[3],
                  Ab + ((m0 + (l & 15)) * PDH + s0 + ((l & 16) ? 8 : 0)) * 2);
            ldmx4t(b0[0], b0[1], b0[2], b0[3],
                   Ub + ((s0 + (l & 15)) * PDH + n0h + ((l & 16) ? 8 : 0)) * 2);
            ldmx4t(b1[0], b1[1], b1[2], b1[3],
                   Ub + ((s0 + (l & 15)) * PDH + n0h + 16 + ((l & 16) ? 8 : 0)) * 2);
            mma16816(cc[0], a, &b0[0]);
            mma16816(cc[1], a, &b0[2]);
            mma16816(cc[2], a, &b1[0]);
            mma16816(cc[3], a, &b1[2]);
        }
        int tr = m0 + lr2;
#pragma unroll
        for (int nf = 0; nf < 4; nf++) {
            int v = n0h + nf * 8 + lc2;
            float2 e0 = *(float2*)&sGf[tr * PD + v];
            *(__half2*)&g_atth[rowbase + (size_t)tr * HIDK + v] =
                __floats2half2_rn(cc[nf][0] * e0.x, cc[nf][1] * e0.y);
            float2 e1 = *(float2*)&sGf[(tr + 8) * PD + v];
            *(__half2*)&g_atth[rowbase + (size_t)(tr + 8) * HIDK + v] =
                __floats2half2_rn(cc[nf][2] * e1.x, cc[nf][3] * e1.y);
        }
    }

    // ---- GEMM3: P[v,kd] = U^T.K; scale expD_end; store fp16 ----
    {
        float cc[4][4];
#pragma unroll
        for (int i = 0; i < 4; i++)
#pragma unroll
            for (int j = 0; j < 4; j++) cc[i][j] = 0.f;
#pragma unroll
        for (int s0 = 0; s0 < 64; s0 += 16) {
            uint32_t a[4], b0[4], b1[4];
            ldmx4t(a[0], a[1], a[2], a[3],
                   Ub + ((s0 + (l & 7) + ((l & 16) ? 8 : 0)) * PDH + m0 + ((l & 8) ? 8 : 0)) * 2);
            ldmx4t(b0[0], b0[1], b0[2], b0[3],
                   Kb + ((s0 + (l & 15)) * PDH + n0h + ((l & 16) ? 8 : 0)) * 2);
            ldmx4t(b1[0], b1[1], b1[2], b1[3],
                   Kb + ((s0 + (l & 15)) * PDH + n0h + 16 + ((l & 16) ? 8 : 0)) * 2);
            mma16816(cc[0], a, &b0[0]);
            mma16816(cc[1], a, &b0[2]);
            mma16816(cc[2], a, &b1[0]);
            mma16816(cc[3], a, &b1[2]);
        }
        size_t pbase = ((size_t)(bh * NCH + c)) << 12;
        int vr = m0 + lr2;
        float ev0 = sGf[63 * PD + vr];
        float ev1 = sGf[63 * PD + vr + 8];
#pragma unroll
        for (int nf = 0; nf < 4; nf++) {
            int kd = n0h + nf * 8 + lc2;
            *(__half2*)&g_Ph[pbase + ((size_t)vr << 6) + kd] =
                __floats2half2_rn(cc[nf][0] * ev0, cc[nf][1] * ev0);
            *(__half2*)&g_Ph[pbase + ((size_t)(vr + 8) << 6) + kd] =
                __floats2half2_rn(cc[nf][2] * ev1, cc[nf][3] * ev1);
        }
    }
}

// ---------------- kernel B: scan over chunk states (k-split, fp16 I/O) -----
__global__ void __launch_bounds__(512) chunkscan_kernel() {
    int ks = blockIdx.x;
    int bh = blockIdx.y;
    int b = bh >> 4, h = bh & 15;
    int tid = threadIdx.x;
    int v = tid >> 3;
    int k = ks * 16 + (tid & 7) * 2;
    float2 S = make_float2(0.f, 0.f);

    for (int c = 0; c < NCH; c++) {
        size_t base = (((size_t)(bh * NCH + c)) << 12) + ((size_t)v << 6) + k;
        *(__half2*)(g_Sh + base) = __floats2half2_rn(S.x, S.y);
        float E = __half2float(g_expDh[((size_t)(b * LSEQ + c * CT + 63)) * HIDK + h * HDIM + v]);
        float2 p = __half22float2(*(__half2*)(g_Ph + base));
        S.x = fmaf(S.x, E, p.x);
        S.y = fmaf(S.y, E, p.y);
    }
}

// ---------------- kernel C: inter-chunk output — fp16 tensor cores ---------
__global__ void __launch_bounds__(256) inter_kernel() {
    __shared__ __align__(16) __half sQ[64 * PDH];
    __shared__ __align__(16) __half sS[64 * PDH];
    int c = blockIdx.x, bh = blockIdx.y;
    int b = bh >> 4, h = bh & 15;
    int tid = threadIdx.x;
    size_t rowbase = (size_t)(b * LSEQ + c * CT) * HIDK + h * HDIM;
    size_t sbase = ((size_t)(bh * NCH + c)) << 12;
    uint32_t Qb = smem_u32(sQ), Sb = smem_u32(sS);

#pragma unroll
    for (int i = 0; i < 2; i++) {
        int idx = tid + i * 256;
        int t = idx >> 3, c8 = (idx & 7) << 3;
        *(uint4*)&sQ[t * PDH + c8] = *(const uint4*)(g_qh16 + rowbase + (size_t)t * HIDK + c8);
        *(uint4*)&sS[t * PDH + c8] = *(const uint4*)(g_Sh + sbase + ((size_t)t << 6) + c8);
    }
    __syncthreads();

    int w = tid >> 5, l = tid & 31;
    int m0 = (w & 3) << 4, n0h = (w >> 2) << 5;
    int lr2 = l >> 2, lc2 = (l & 3) << 1;

    float cc[4][4];
#pragma unroll
    for (int i = 0; i < 4; i++)
#pragma unroll
        for (int j = 0; j < 4; j++) cc[i][j] = 0.f;
#pragma unroll
    for (int k0 = 0; k0 < 64; k0 += 16) {
        uint32_t a[4], b0[4], b1[4];
        ldmx4(a[0], a[1], a[2], a[3],
              Qb + ((m0 + (l & 15)) * PDH + k0 + ((l & 16) ? 8 : 0)) * 2);
        ldmx4(b0[0], b0[1], b0[2], b0[3],
              Sb + ((n0h + (l & 7) + ((l & 16) ? 8 : 0)) * PDH + k0 + ((l & 8) ? 8 : 0)) * 2);
        ldmx4(b1[0], b1[1], b1[2], b1[3],
              Sb + ((n0h + 16 + (l & 7) + ((l & 16) ? 8 : 0)) * PDH + k0 + ((l & 8) ? 8 : 0)) * 2);
        mma16816(cc[0], a, &b0[0]);
        mma16816(cc[1], a, &b0[2]);
        mma16816(cc[2], a, &b1[0]);
        mma16816(cc[3], a, &b1[2]);
    }
    int tr = m0 + lr2;
#pragma unroll
    for (int nf = 0; nf < 4; nf++) {
        int v = n0h + nf * 8 + lc2;
        size_t gi0 = rowbase + (size_t)tr * HIDK + v;
        float2 e0 = __half22float2(*(__half2*)(g_expDh + gi0));
        float2 i0 = __half22float2(*(__half2*)(g_atth + gi0));
        *(float2*)(g_att + gi0) =
            make_float2(fmaf(cc[nf][0], e0.x, i0.x), fmaf(cc[nf][1], e0.y, i0.y));
        size_t gi1 = rowbase + (size_t)(tr + 8) * HIDK + v;
        float2 e1 = __half22float2(*(__half2*)(g_expDh + gi1));
        float2 i1 = __half22float2(*(__half2*)(g_atth + gi1));
        *(float2*)(g_att + gi1) =
            make_float2(fmaf(cc[nf][2], e1.x, i1.x), fmaf(cc[nf][3], e1.y, i1.y));
    }
}

// ---------------- LayerNorm + SiLU gate -> fp16 y (+ scaled copy) ----------
__global__ void __launch_bounds__(256) ln_gate_kernel(const float* __restrict__ gamma,
                                                      const float* __restrict__ beta) {
    int row = blockIdx.x;
    int tid = threadIdx.x;
    const float* a = g_att + (size_t)row * HIDK;
    float vals[4];
    float s = 0.f, s2 = 0.f;
#pragma unroll
    for (int i = 0; i < 4; i++) {
        vals[i] = a[i * 256 + tid];
        s += vals[i];
        s2 = fmaf(vals[i], vals[i], s2);
    }
#pragma unroll
    for (int o = 16; o; o >>= 1) {
        s += __shfl_xor_sync(0xffffffffu, s, o);
        s2 += __shfl_xor_sync(0xffffffffu, s2, o);
    }
    __shared__ float rs[8], rs2[8];
    int warp = tid >> 5;
    if ((tid & 31) == 0) { rs[warp] = s; rs2[warp] = s2; }
    __syncthreads();
    s = 0.f;
    s2 = 0.f;
#pragma unroll
    for (int w = 0; w < 8; w++) { s += rs[w]; s2 += rs2[w]; }
    float mean = s * (1.f / HIDK);
    float var = s2 * (1.f / HIDK) - mean * mean;
    float rstd = rsqrtf(var + 1e-5f);
#pragma unroll
    for (int i = 0; i < 4; i++) {
        int col = i * 256 + tid;
        float gv = g_xg[(size_t)row * HIDK + col];
        float sil = gv / (1.f + __expf(-gv));
        float yv = ((vals[i] - mean) * rstd * gamma[col] + beta[col]) * sil;
        g_yh[(size_t)row * HIDK + col] = __float2half(yv);
        g_ys[(size_t)row * HIDK + col] = __float2half(yv * SC_DN);
    }
}

// ---------------- launch --------------------------------------------------
extern "C" void kernel_launch(void* const* d_in, const int* in_sizes, int n_in,
                              void* d_out, int out_size) {
    const float* x = (const float*)d_in[0];
    const float* Wq = (const float*)d_in[1];
    const float* Wk = (const float*)d_in[2];
    const float* Wv = (const float*)d_in[3];
    const float* Wg = (const float*)d_in[4];
    const float* Wgk1 = (const float*)d_in[5];
    const float* Wgk2 = (const float*)d_in[6];
    const float* bgk2 = (const float*)d_in[7];
    const float* gamma = (const float*)d_in[8];
    const float* beta = (const float*)d_in[9];
    const float* Wout = (const float*)d_in[10];
    float* out = (float*)d_out;

    cudaFuncSetAttribute(chunk_kernel, cudaFuncAttributeMaxDynamicSharedMemorySize, SMEM_CH);
    cudaFuncSetAttribute(mmproj_kernel, cudaFuncAttributeMaxDynamicSharedMemorySize, SMEM_MM);
    cudaFuncSetAttribute(mmout_kernel, cudaFuncAttributeMaxDynamicSharedMemorySize, SMEM_MM);
    cudaFuncSetAttribute(lr_fused_kernel, cudaFuncAttributeMaxDynamicSharedMemorySize, SMEM_LR);

    xconv_kernel<<<MTOK * HIDK / 1024, 256>>>(x);
    wconv_kernel<<<dim3(32, 32, 5), 256>>>(Wq, Wk, Wv, Wg, Wout);
    lr_fused_kernel<<<MTOK / 16, 256, SMEM_LR>>>(x, Wgk1, Wgk2, bgk2);

    mmproj_kernel<<<dim3(8, 32, 4), 256, SMEM_MM>>>();

    chunk_kernel<<<dim3(NCH, 32), 256, SMEM_CH>>>();
    chunkscan_kernel<<<dim3(4, 32), 512>>>();
    inter_kernel<<<dim3(NCH, 32), 256>>>();
    ln_gate_kernel<<<MTOK, 256>>>(gamma, beta);

    mmout_kernel<<<dim3(8, 32, 1), 256, SMEM_MM>>>(out);
}

// round 11
// speedup vs baseline: 1.3492x; 1.2642x over previous
#include <cuda_runtime.h>
#include <cuda_fp16.h>
#include <math.h>
#include <stdint.h>

#define HIDK 1024
#define MTOK 4096
#define LSEQ 2048
#define NHEAD 16
#define HDIM 64
#define CT 64
#define NCH (LSEQ / CT)
#define PD 68
#define PDH 72

// ---------------- scratch (device globals; no allocations) ----------------
__device__ float g_xg[MTOK * HIDK];
__device__ float g_att[MTOK * HIDK];                      // final o (inter writes)
__device__ __align__(16) __half g_qh16[MTOK * HIDK];
__device__ __align__(16) __half g_kh16[MTOK * HIDK];
__device__ __align__(16) __half g_vh16[MTOK * HIDK];
__device__ __align__(16) __half g_gkh[MTOK * HIDK];
__device__ __align__(16) __half g_expDh[MTOK * HIDK];
__device__ __align__(16) __half g_atth[MTOK * HIDK];      // intra-chunk o
__device__ __align__(16) __half g_Ph[32 * NCH * HDIM * HDIM];
__device__ __align__(16) __half g_Sh[32 * NCH * HDIM * HDIM];
// fp16 GEMM operands: activations single + 2^-10-scaled copy; weights exact pair
__device__ __align__(16) __half g_xh[MTOK * HIDK];
__device__ __align__(16) __half g_xs[MTOK * HIDK];
__device__ __align__(16) __half g_yh[MTOK * HIDK];
__device__ __align__(16) __half g_ys[MTOK * HIDK];
__device__ __align__(16) __half g_wh[5 * HIDK * HIDK];
__device__ __align__(16) __half g_wl[5 * HIDK * HIDK];

// ======================= helpers =======================
__device__ __forceinline__ uint32_t smem_u32(const void* p) {
    uint32_t a;
    asm("{ .reg .u64 t; cvta.to.shared.u64 t, %1; cvt.u32.u64 %0, t; }" : "=r"(a) : "l"(p));
    return a;
}
__device__ __forceinline__ void cpasync16(uint32_t s, const void* g) {
    asm volatile("cp.async.cg.shared.global [%0], [%1], 16;" ::"r"(s), "l"(g));
}
__device__ __forceinline__ void cpcommit() { asm volatile("cp.async.commit_group;"); }

__device__ __forceinline__ void ldmx4(uint32_t& r0, uint32_t& r1, uint32_t& r2,
                                      uint32_t& r3, uint32_t addr) {
    asm volatile("ldmatrix.sync.aligned.m8n8.x4.shared.b16 {%0,%1,%2,%3}, [%4];"
                 : "=r"(r0), "=r"(r1), "=r"(r2), "=r"(r3)
                 : "r"(addr));
}
__device__ __forceinline__ void ldmx4t(uint32_t& r0, uint32_t& r1, uint32_t& r2,
                                       uint32_t& r3, uint32_t addr) {
    asm volatile("ldmatrix.sync.aligned.m8n8.x4.trans.shared.b16 {%0,%1,%2,%3}, [%4];"
                 : "=r"(r0), "=r"(r1), "=r"(r2), "=r"(r3)
                 : "r"(addr));
}
__device__ __forceinline__ void mma16816(float* c, const uint32_t* a, const uint32_t* b) {
    asm volatile(
        "mma.sync.aligned.m16n8k16.row.col.f32.f16.f16.f32 "
        "{%0,%1,%2,%3}, {%4,%5,%6,%7}, {%8,%9}, {%0,%1,%2,%3};"
        : "+f"(c[0]), "+f"(c[1]), "+f"(c[2]), "+f"(c[3])
        : "r"(a[0]), "r"(a[1]), "r"(a[2]), "r"(a[3]), "r"(b[0]), "r"(b[1]));
}

// ======================= fp16 mma.sync big GEMM (R8 ordering) ==============
// nstages = 32 -> hi product only; nstages = 64 -> hi + lo correction.
#define ROWB 80
#define STG_A (128 * ROWB)
#define STG (2 * STG_A)
#define NSTG 4
#define SMEM_MM (NSTG * STG)

__device__ __forceinline__ void mm_issue(int s, int nstages, uint32_t sb, int tid,
                                         int brow, int bcol,
                                         const __half* Ah, const __half* As,
                                         const __half* Bh, const __half* Bl) {
    if (s < nstages) {
        int p = s >> 5;
        int kk = (s & 31) << 5;
        const __half* Ab = p ? As : Ah;
        const __half* Bb = p ? Bl : Bh;
        uint32_t st = sb + (uint32_t)(s & 3) * STG;
        int row = tid >> 2, cw = tid & 3;
        const char* ga = (const char*)(Ab + (size_t)(brow + row) * HIDK + kk + cw * 8);
        cpasync16(st + row * ROWB + cw * 16, ga);
        cpasync16(st + (row + 64) * ROWB + cw * 16, ga + (size_t)64 * HIDK * 2);
        const char* gb = (const char*)(Bb + (size_t)(bcol + row) * HIDK + kk + cw * 8);
        cpasync16(st + STG_A + row * ROWB + cw * 16, gb);
        cpasync16(st + STG_A + (row + 64) * ROWB + cw * 16, gb + (size_t)64 * HIDK * 2);
    }
    cpcommit();
}

__device__ __forceinline__ void mma_gemm_body(const __half* __restrict__ Ah,
                                              const __half* __restrict__ As,
                                              const __half* __restrict__ Bh,
                                              const __half* __restrict__ Bl,
                                              void* __restrict__ Cv, bool half_out,
                                              int nstages) {
    extern __shared__ char sm_raw[];
    uint32_t sb = smem_u32(sm_raw);
    int tid = threadIdx.x, lane = tid & 31, wid = tid >> 5;
    int wm = wid & 3, wn = wid >> 2;
    int brow = blockIdx.y * 128, bcol = blockIdx.x * 128;

    float c[2][8][4];
#pragma unroll
    for (int i = 0; i < 2; i++)
#pragma unroll
        for (int j = 0; j < 8; j++)
#pragma unroll
            for (int l = 0; l < 4; l++) c[i][j][l] = 0.f;

    mm_issue(0, nstages, sb, tid, brow, bcol, Ah, As, Bh, Bl);
    mm_issue(1, nstages, sb, tid, brow, bcol, Ah, As, Bh, Bl);
    mm_issue(2, nstages, sb, tid, brow, bcol, Ah, As, Bh, Bl);

    int q = lane >> 3, r = lane & 7;

    for (int s = 0; s < nstages; s++) {
        asm volatile("cp.async.wait_group 2;" ::: "memory");
        __syncthreads();
        uint32_t st = sb + (uint32_t)(s & 3) * STG;
        uint32_t sA = st, sB = st + STG_A;
#pragma unroll
        for (int k0 = 0; k0 < 32; k0 += 16) {
            uint32_t a[2][4], b[8][2];
#pragma unroll
            for (int mf = 0; mf < 2; mf++) {
                int rrow = wm * 32 + mf * 16 + (q & 1) * 8 + r;
                int kc = k0 + (q >> 1) * 8;
                ldmx4(a[mf][0], a[mf][1], a[mf][2], a[mf][3], sA + rrow * ROWB + kc * 2);
            }
#pragma unroll
            for (int pb = 0; pb < 4; pb++) {
                int nrow = wn * 64 + pb * 16 + (q >> 1) * 8 + r;
                int kc = k0 + (q & 1) * 8;
                uint32_t r0, r1, r2, r3;
                ldmx4(r0, r1, r2, r3, sB + nrow * ROWB + kc * 2);
                b[pb * 2][0] = r0;
                b[pb * 2][1] = r1;
                b[pb * 2 + 1][0] = r2;
                b[pb * 2 + 1][1] = r3;
            }
#pragma unroll
            for (int mf = 0; mf < 2; mf++)
#pragma unroll
                for (int nf = 0; nf < 8; nf++) mma16816(c[mf][nf], a[mf], b[nf]);
        }
        mm_issue(s + 3, nstages, sb, tid, brow, bcol, Ah, As, Bh, Bl);
    }

    int qr = lane >> 2, qc = lane & 3;
    if (half_out) {
        __half* Ch = (__half*)Cv;
#pragma unroll
        for (int mf = 0; mf < 2; mf++)
#pragma unroll
            for (int nf = 0; nf < 8; nf++) {
                int row0 = brow + wm * 32 + mf * 16 + qr;
                int col = bcol + wn * 64 + nf * 8 + qc * 2;
                *(__half2*)&Ch[(size_t)row0 * HIDK + col] =
                    __floats2half2_rn(c[mf][nf][0], c[mf][nf][1]);
                *(__half2*)&Ch[(size_t)(row0 + 8) * HIDK + col] =
                    __floats2half2_rn(c[mf][nf][2], c[mf][nf][3]);
            }
    } else {
        float* Cf = (float*)Cv;
#pragma unroll
        for (int mf = 0; mf < 2; mf++)
#pragma unroll
            for (int nf = 0; nf < 8; nf++) {
                int row0 = brow + wm * 32 + mf * 16 + qr;
                int col = bcol + wn * 64 + nf * 8 + qc * 2;
                *(float2*)&Cf[(size_t)row0 * HIDK + col] =
                    make_float2(c[mf][nf][0], c[mf][nf][1]);
                *(float2*)&Cf[(size_t)(row0 + 8) * HIDK + col] =
                    make_float2(c[mf][nf][2], c[mf][nf][3]);
            }
    }
}

__global__ void __launch_bounds__(256, 2) mmproj_kernel() {
    int z = blockIdx.z;
    const __half* Bh = g_wh + (size_t)z * HIDK * HIDK;
    const __half* Bl = g_wl + (size_t)z * HIDK * HIDK;
    void* C;
    bool ho = true;
    int ns = 32;  // q,k,v: single hi product (their outputs are fp16-rounded anyway)
    switch (z) {
        case 0: C = g_qh16; break;
        case 1: C = g_kh16; break;
        case 2: C = g_vh16; break;
        default: C = g_xg; ho = false; ns = 64; break;  // gate path keeps correction
    }
    mma_gemm_body(g_xh, g_xs, Bh, Bl, C, ho, ns);
}
__global__ void __launch_bounds__(256, 2) mmout_kernel(float* __restrict__ out) {
    mma_gemm_body(g_yh, g_ys, g_wh + (size_t)4 * HIDK * HIDK,
                  g_wl + (size_t)4 * HIDK * HIDK, out, false, 64);
}

// ======================= weight conversion =====================
#define SC_DN (1.f / 1024.f)
__global__ void __launch_bounds__(256) wconv_kernel(const float* __restrict__ W0,
                                                    const float* __restrict__ W1,
                                                    const float* __restrict__ W2,
                                                    const float* __restrict__ W3,
                                                    const float* __restrict__ W4) {
    int z = blockIdx.z;
    const float* W = (z == 0) ? W0 : (z == 1) ? W1 : (z == 2) ? W2 : (z == 3) ? W3 : W4;
    __half* Th = g_wh + (size_t)z * HIDK * HIDK;
    __half* Tl = g_wl + (size_t)z * HIDK * HIDK;
    __shared__ float t[32][33];
    int n0 = blockIdx.x * 32, k0 = blockIdx.y * 32;
    int lx = threadIdx.x & 31, ly = threadIdx.x >> 5;
#pragma unroll
    for (int i = 0; i < 4; i++) {
        int r = ly + i * 8;
        t[r][lx] = W[(size_t)(k0 + r) * HIDK + n0 + lx];
    }
    __syncthreads();
#pragma unroll
    for (int i = 0; i < 4; i++) {
        int r = ly + i * 8;
        float v = t[lx][r];
        __half h = __float2half(v);
        size_t o = (size_t)(n0 + r) * HIDK + k0 + lx;
        Th[o] = h;
        Tl[o] = __float2half((v - __half2float(h)) * 1024.f);
    }
}

// ---------------- fused x-convert + low-rank gate path ----------------------
#define SMEM_LR (32 * 1024 * sizeof(float))
__global__ void __launch_bounds__(256) lr_fused_kernel(const float* __restrict__ x,
                                                       const float* __restrict__ W1,
                                                       const float* __restrict__ W2,
                                                       const float* __restrict__ bias) {
    extern __shared__ float s[];
    float* w1s = s;
    float* w2s = s + 16384;
    __shared__ float ts[16][17];
    int tid = threadIdx.x;
    int m0 = blockIdx.x * 16;

    // phase 0: x -> fp16 (hi + 2^-10 scaled) for this block's 16 rows + stage W1/W2
#pragma unroll
    for (int i = 0; i < 16; i++) {
        int idx = tid + i * 256;   // 4096 float4 = 16 rows x 1024
        ((float4*)w1s)[idx] = ((const float4*)W1)[idx];
        ((float4*)w2s)[idx] = ((const float4*)W2)[idx];
        float4 v = ((const float4*)x)[(size_t)m0 * (HIDK / 4) + idx];
        size_t eo = (size_t)m0 * HIDK + (size_t)idx * 4;
        *(__half2*)&g_xh[eo] = __floats2half2_rn(v.x, v.y);
        *(__half2*)&g_xh[eo + 2] = __floats2half2_rn(v.z, v.w);
        *(__half2*)&g_xs[eo] = __floats2half2_rn(v.x * SC_DN, v.y * SC_DN);
        *(__half2*)&g_xs[eo + 2] = __floats2half2_rn(v.z * SC_DN, v.w * SC_DN);
    }
    __syncthreads();

    {
        int mt = tid >> 4, r = tid & 15;
        const float* xr = x + (size_t)(m0 + mt) * HIDK;
        float acc = 0.f;
#pragma unroll 8
        for (int kk = 0; kk < HIDK; kk++) acc = fmaf(xr[kk], w1s[kk * 16 + r], acc);
        ts[mt][r] = acc;
    }
    __syncthreads();

    int n = tid * 4;
    float4 b4 = *(const float4*)(bias + n);
#pragma unroll 1
    for (int mi = 0; mi < 16; mi++) {
        float4 a = b4;
#pragma unroll
        for (int rr = 0; rr < 16; rr++) {
            float tv = ts[mi][rr];
            float4 w = *(float4*)&w2s[rr * 1024 + n];
            a.x = fmaf(tv, w.x, a.x);
            a.y = fmaf(tv, w.y, a.y);
            a.z = fmaf(tv, w.z, a.z);
            a.w = fmaf(tv, w.w, a.w);
        }
        float ox = (fminf(a.x, 0.f) - __logf(1.f + __expf(-fabsf(a.x)))) * 0.0625f;
        float oy = (fminf(a.y, 0.f) - __logf(1.f + __expf(-fabsf(a.y)))) * 0.0625f;
        float oz = (fminf(a.z, 0.f) - __logf(1.f + __expf(-fabsf(a.z)))) * 0.0625f;
        float ow = (fminf(a.w, 0.f) - __logf(1.f + __expf(-fabsf(a.w)))) * 0.0625f;
        size_t go = (size_t)(m0 + mi) * HIDK + n;
        *(__half2*)&g_gkh[go] = __floats2half2_rn(ox, oy);
        *(__half2*)&g_gkh[go + 2] = __floats2half2_rn(oz, ow);
    }
}

// ---------------- chunked GLA: kernel A — fp16 tensor cores -----------------
#define OFF_V 17408
#define OFF_Q 26624
#define OFF_K 35840
#define OFF_U 45056
#define OFF_A 54272
#define SMEM_CH 63488

__global__ void __launch_bounds__(256) chunk_kernel() {
    extern __shared__ char smc[];
    float* sGf = (float*)smc;
    uint32_t sb = smem_u32(smc);
    uint32_t Qb = sb + OFF_Q, Kb = sb + OFF_K, Ub = sb + OFF_U, Ab = sb + OFF_A;
    __half* VhP = (__half*)(smc + OFF_V);
    __half* QhP = (__half*)(smc + OFF_Q);
    __half* KhP = (__half*)(smc + OFF_K);
    __half* UhP = (__half*)(smc + OFF_U);
    __half* AhP = (__half*)(smc + OFF_A);
    __shared__ float sTot[4][64];

    int c = blockIdx.x, bh = blockIdx.y;
    int b = bh >> 4, h = bh & 15;
    int tid = threadIdx.x;
    size_t rowbase = (size_t)(b * LSEQ + c * CT) * HIDK + h * HDIM;

#pragma unroll
    for (int i = 0; i < 2; i++) {
        int idx = tid + i * 256;
        int t = idx >> 3, c8 = (idx & 7) << 3;
        size_t gi = rowbase + (size_t)t * HIDK + c8;
        *(uint4*)&QhP[t * PDH + c8] = *(const uint4*)(g_qh16 + gi);
        *(uint4*)&KhP[t * PDH + c8] = *(const uint4*)(g_kh16 + gi);
        *(uint4*)&VhP[t * PDH + c8] = *(const uint4*)(g_vh16 + gi);
        uint4 gg4 = *(const uint4*)(g_gkh + gi);
        const __half2* gh = (const __half2*)&gg4;
        float* dst = &sGf[t * PD + c8];
        float2 a0 = __half22float2(gh[0]);
        float2 a1 = __half22float2(gh[1]);
        float2 a2 = __half22float2(gh[2]);
        float2 a3 = __half22float2(gh[3]);
        dst[0] = a0.x; dst[1] = a0.y; dst[2] = a1.x; dst[3] = a1.y;
        dst[4] = a2.x; dst[5] = a2.y; dst[6] = a3.x; dst[7] = a3.y;
    }
    __syncthreads();

    {
        int ch = tid & 63, seg = tid >> 6;
        int t0s = seg * 16;
        float run = 0.f;
#pragma unroll
        for (int t = t0s; t < t0s + 16; t++) {
            run += sGf[t * PD + ch];
            sGf[t * PD + ch] = run;
        }
        sTot[seg][ch] = run;
    }
    __syncthreads();
    {
        int ch = tid & 63, seg = tid >> 6;
        float off = 0.f;
        if (seg > 0) off += sTot[0][ch];
        if (seg > 1) off += sTot[1][ch];
        if (seg > 2) off += sTot[2][ch];
        int t0s = seg * 16;
#pragma unroll
        for (int t = t0s; t < t0s + 16; t++) {
            float D = sGf[t * PD + ch] + off;
            sGf[t * PD + ch] = __expf(D);
            UhP[t * PDH + ch] = __float2half(__expf(-D) * __half2float(VhP[t * PDH + ch]));
        }
    }
    __syncthreads();

#pragma unroll
    for (int i = 0; i < 2; i++) {
        int idx = tid + i * 256;
        int t = idx >> 3, c8 = (idx & 7) << 3;
        __half h8[8];
#pragma unroll
        for (int j = 0; j < 8; j++) h8[j] = __float2half(sGf[t * PD + c8 + j]);
        *(uint4*)(g_expDh + rowbase + (size_t)t * HIDK + c8) = *(uint4*)h8;
    }

    int w = tid >> 5, l = tid & 31;
    int m0 = (w & 3) << 4, n0h = (w >> 2) << 5;
    int lr2 = l >> 2, lc2 = (l & 3) << 1;

    // GEMM1: A = Q.K^T masked -> fp16
    {
        float cc[4][4];
#pragma unroll
        for (int i = 0; i < 4; i++)
#pragma unroll
            for (int j = 0; j < 4; j++) cc[i][j] = 0.f;
#pragma unroll
        for (int k0 = 0; k0 < 64; k0 += 16) {
            uint32_t a[4], b0[4], b1[4];
            ldmx4(a[0], a[1], a[2], a[3],
                  Qb + ((m0 + (l & 15)) * PDH + k0 + ((l & 16) ? 8 : 0)) * 2);
            ldmx4(b0[0], b0[1], b0[2], b0[3],
                  Kb + ((n0h + (l & 7) + ((l & 16) ? 8 : 0)) * PDH + k0 + ((l & 8) ? 8 : 0)) * 2);
            ldmx4(b1[0], b1[1], b1[2], b1[3],
                  Kb + ((n0h + 16 + (l & 7) + ((l & 16) ? 8 : 0)) * PDH + k0 + ((l & 8) ? 8 : 0)) * 2);
            mma16816(cc[0], a, &b0[0]);
            mma16816(cc[1], a, &b0[2]);
            mma16816(cc[2], a, &b1[0]);
            mma16816(cc[3], a, &b1[2]);
        }
        int tr = m0 + lr2;
#pragma unroll
        for (int nf = 0; nf < 4; nf++) {
            int sc = n0h + nf * 8 + lc2;
            *(__half2*)&AhP[tr * PDH + sc] = __halves2half2(
                __float2half(sc <= tr ? cc[nf][0] : 0.f),
                __float2half(sc + 1 <= tr ? cc[nf][1] : 0.f));
            int tr2 = tr + 8;
            *(__half2*)&AhP[tr2 * PDH + sc] = __halves2half2(
                __float2half(sc <= tr2 ? cc[nf][2] : 0.f),
                __float2half(sc + 1 <= tr2 ? cc[nf][3] : 0.f));
        }
    }
    __syncthreads();

    // GEMM2: o_intra = A'.U; scale expD; store fp16
    {
        float cc[4][4];
#pragma unroll
        for (int i = 0; i < 4; i++)
#pragma unroll
            for (int j = 0; j < 4; j++) cc[i][j] = 0.f;
#pragma unroll
        for (int s0 = 0; s0 < 64; s0 += 16) {
            uint32_t a[4], b0[4], b1[4];
            ldmx4(a[0], a[1], a[2], a[3],
                  Ab + ((m0 + (l & 15)) * PDH + s0 + ((l & 16) ? 8 : 0)) * 2);
            ldmx4t(b0[0], b0[1], b0[2], b0[3],
                   Ub + ((s0 + (l & 15)) * PDH + n0h + ((l & 16) ? 8 : 0)) * 2);
            ldmx4t(b1[0], b1[1], b1[2], b1[3],
                   Ub + ((s0 + (l & 15)) * PDH + n0h + 16 + ((l & 16) ? 8 : 0)) * 2);
            mma16816(cc[0], a, &b0[0]);
            mma16816(cc[1], a, &b0[2]);
            mma16816(cc[2], a, &b1[0]);
            mma16816(cc[3], a, &b1[2]);
        }
        int tr = m0 + lr2;
#pragma unroll
        for (int nf = 0; nf < 4; nf++) {
            int v = n0h + nf * 8 + lc2;
            float2 e0 = *(float2*)&sGf[tr * PD + v];
            *(__half2*)&g_atth[rowbase + (size_t)tr * HIDK + v] =
                __floats2half2_rn(cc[nf][0] * e0.x, cc[nf][1] * e0.y);
            float2 e1 = *(float2*)&sGf[(tr + 8) * PD + v];
            *(__half2*)&g_atth[rowbase + (size_t)(tr + 8) * HIDK + v] =
                __floats2half2_rn(cc[nf][2] * e1.x, cc[nf][3] * e1.y);
        }
    }

    // GEMM3: P = U^T.K; scale expD_end; store fp16
    {
        float cc[4][4];
#pragma unroll
        for (int i = 0; i < 4; i++)
#pragma unroll
            for (int j = 0; j < 4; j++) cc[i][j] = 0.f;
#pragma unroll
        for (int s0 = 0; s0 < 64; s0 += 16) {
            uint32_t a[4], b0[4], b1[4];
            ldmx4t(a[0], a[1], a[2], a[3],
                   Ub + ((s0 + (l & 7) + ((l & 16) ? 8 : 0)) * PDH + m0 + ((l & 8) ? 8 : 0)) * 2);
            ldmx4t(b0[0], b0[1], b0[2], b0[3],
                   Kb + ((s0 + (l & 15)) * PDH + n0h + ((l & 16) ? 8 : 0)) * 2);
            ldmx4t(b1[0], b1[1], b1[2], b1[3],
                   Kb + ((s0 + (l & 15)) * PDH + n0h + 16 + ((l & 16) ? 8 : 0)) * 2);
            mma16816(cc[0], a, &b0[0]);
            mma16816(cc[1], a, &b0[2]);
            mma16816(cc[2], a, &b1[0]);
            mma16816(cc[3], a, &b1[2]);
        }
        size_t pbase = ((size_t)(bh * NCH + c)) << 12;
        int vr = m0 + lr2;
        float ev0 = sGf[63 * PD + vr];
        float ev1 = sGf[63 * PD + vr + 8];
#pragma unroll
        for (int nf = 0; nf < 4; nf++) {
            int kd = n0h + nf * 8 + lc2;
            *(__half2*)&g_Ph[pbase + ((size_t)vr << 6) + kd] =
                __floats2half2_rn(cc[nf][0] * ev0, cc[nf][1] * ev0);
            *(__half2*)&g_Ph[pbase + ((size_t)(vr + 8) << 6) + kd] =
                __floats2half2_rn(cc[nf][2] * ev1, cc[nf][3] * ev1);
        }
    }
}

// ---------------- kernel B: scan over chunk states (k-split, fp16 I/O) -----
__global__ void __launch_bounds__(512) chunkscan_kernel() {
    int ks = blockIdx.x;
    int bh = blockIdx.y;
    int b = bh >> 4, h = bh & 15;
    int tid = threadIdx.x;
    int v = tid >> 3;
    int k = ks * 16 + (tid & 7) * 2;
    float2 S = make_float2(0.f, 0.f);

    for (int c = 0; c < NCH; c++) {
        size_t base = (((size_t)(bh * NCH + c)) << 12) + ((size_t)v << 6) + k;
        *(__half2*)(g_Sh + base) = __floats2half2_rn(S.x, S.y);
        float E = __half2float(g_expDh[((size_t)(b * LSEQ + c * CT + 63)) * HIDK + h * HDIM + v]);
        float2 p = __half22float2(*(__half2*)(g_Ph + base));
        S.x = fmaf(S.x, E, p.x);
        S.y = fmaf(S.y, E, p.y);
    }
}

// ---------------- kernel C: inter-chunk output — fp16 tensor cores ---------
__global__ void __launch_bounds__(256) inter_kernel() {
    __shared__ __align__(16) __half sQ[64 * PDH];
    __shared__ __align__(16) __half sS[64 * PDH];
    int c = blockIdx.x, bh = blockIdx.y;
    int b = bh >> 4, h = bh & 15;
    int tid = threadIdx.x;
    size_t rowbase = (size_t)(b * LSEQ + c * CT) * HIDK + h * HDIM;
    size_t sbase = ((size_t)(bh * NCH + c)) << 12;
    uint32_t Qb = smem_u32(sQ), Sb = smem_u32(sS);

#pragma unroll
    for (int i = 0; i < 2; i++) {
        int idx = tid + i * 256;
        int t = idx >> 3, c8 = (idx & 7) << 3;
        *(uint4*)&sQ[t * PDH + c8] = *(const uint4*)(g_qh16 + rowbase + (size_t)t * HIDK + c8);
        *(uint4*)&sS[t * PDH + c8] = *(const uint4*)(g_Sh + sbase + ((size_t)t << 6) + c8);
    }
    __syncthreads();

    int w = tid >> 5, l = tid & 31;
    int m0 = (w & 3) << 4, n0h = (w >> 2) << 5;
    int lr2 = l >> 2, lc2 = (l & 3) << 1;

    float cc[4][4];
#pragma unroll
    for (int i = 0; i < 4; i++)
#pragma unroll
        for (int j = 0; j < 4; j++) cc[i][j] = 0.f;
#pragma unroll
    for (int k0 = 0; k0 < 64; k0 += 16) {
        uint32_t a[4], b0[4], b1[4];
        ldmx4(a[0], a[1], a[2], a[3],
              Qb + ((m0 + (l & 15)) * PDH + k0 + ((l & 16) ? 8 : 0)) * 2);
        ldmx4(b0[0], b0[1], b0[2], b0[3],
              Sb + ((n0h + (l & 7) + ((l & 16) ? 8 : 0)) * PDH + k0 + ((l & 8) ? 8 : 0)) * 2);
        ldmx4(b1[0], b1[1], b1[2], b1[3],
              Sb + ((n0h + 16 + (l & 7) + ((l & 16) ? 8 : 0)) * PDH + k0 + ((l & 8) ? 8 : 0)) * 2);
        mma16816(cc[0], a, &b0[0]);
        mma16816(cc[1], a, &b0[2]);
        mma16816(cc[2], a, &b1[0]);
        mma16816(cc[3], a, &b1[2]);
    }
    int tr = m0 + lr2;
#pragma unroll
    for (int nf = 0; nf < 4; nf++) {
        int v = n0h + nf * 8 + lc2;
        size_t gi0 = rowbase + (size_t)tr * HIDK + v;
        float2 e0 = __half22float2(*(__half2*)(g_expDh + gi0));
        float2 i0 = __half22float2(*(__half2*)(g_atth + gi0));
        *(float2*)(g_att + gi0) =
            make_float2(fmaf(cc[nf][0], e0.x, i0.x), fmaf(cc[nf][1], e0.y, i0.y));
        size_t gi1 = rowbase + (size_t)(tr + 8) * HIDK + v;
        float2 e1 = __half22float2(*(__half2*)(g_expDh + gi1));
        float2 i1 = __half22float2(*(__half2*)(g_atth + gi1));
        *(float2*)(g_att + gi1) =
            make_float2(fmaf(cc[nf][2], e1.x, i1.x), fmaf(cc[nf][3], e1.y, i1.y));
    }
}

// ---------------- LayerNorm + SiLU gate -> fp16 y (+ scaled copy) ----------
__global__ void __launch_bounds__(256) ln_gate_kernel(const float* __restrict__ gamma,
                                                      const float* __restrict__ beta) {
    int row = blockIdx.x;
    int tid = threadIdx.x;
    const float* a = g_att + (size_t)row * HIDK;
    float vals[4];
    float s = 0.f, s2 = 0.f;
#pragma unroll
    for (int i = 0; i < 4; i++) {
        vals[i] = a[i * 256 + tid];
        s += vals[i];
        s2 = fmaf(vals[i], vals[i], s2);
    }
#pragma unroll
    for (int o = 16; o; o >>= 1) {
        s += __shfl_xor_sync(0xffffffffu, s, o);
        s2 += __shfl_xor_sync(0xffffffffu, s2, o);
    }
    __shared__ float rs[8], rs2[8];
    int warp = tid >> 5;
    if ((tid & 31) == 0) { rs[warp] = s; rs2[warp] = s2; }
    __syncthreads();
    s = 0.f;
    s2 = 0.f;
#pragma unroll
    for (int w = 0; w < 8; w++) { s += rs[w]; s2 += rs2[w]; }
    float mean = s * (1.f / HIDK);
    float var = s2 * (1.f / HIDK) - mean * mean;
    float rstd = rsqrtf(var + 1e-5f);
#pragma unroll
    for (int i = 0; i < 4; i++) {
        int col = i * 256 + tid;
        float gv = g_xg[(size_t)row * HIDK + col];
        float sil = gv / (1.f + __expf(-gv));
        float yv = ((vals[i] - mean) * rstd * gamma[col] + beta[col]) * sil;
        g_yh[(size_t)row * HIDK + col] = __float2half(yv);
        g_ys[(size_t)row * HIDK + col] = __float2half(yv * SC_DN);
    }
}

// ---------------- launch --------------------------------------------------
extern "C" void kernel_launch(void* const* d_in, const int* in_sizes, int n_in,
                              void* d_out, int out_size) {
    const float* x = (const float*)d_in[0];
    const float* Wq = (const float*)d_in[1];
    const float* Wk = (const float*)d_in[2];
    const float* Wv = (const float*)d_in[3];
    const float* Wg = (const float*)d_in[4];
    const float* Wgk1 = (const float*)d_in[5];
    const float* Wgk2 = (const float*)d_in[6];
    const float* bgk2 = (const float*)d_in[7];
    const float* gamma = (const float*)d_in[8];
    const float* beta = (const float*)d_in[9];
    const float* Wout = (const float*)d_in[10];
    float* out = (float*)d_out;

    cudaFuncSetAttribute(chunk_kernel, cudaFuncAttributeMaxDynamicSharedMemorySize, SMEM_CH);
    cudaFuncSetAttribute(mmproj_kernel, cudaFuncAttributeMaxDynamicSharedMemorySize, SMEM_MM);
    cudaFuncSetAttribute(mmout_kernel, cudaFuncAttributeMaxDynamicSharedMemorySize, SMEM_MM);
    cudaFuncSetAttribute(lr_fused_kernel, cudaFuncAttributeMaxDynamicSharedMemorySize, SMEM_LR);

    wconv_kernel<<<dim3(32, 32, 5), 256>>>(Wq, Wk, Wv, Wg, Wout);
    lr_fused_kernel<<<MTOK / 16, 256, SMEM_LR>>>(x, Wgk1, Wgk2, bgk2);

    mmproj_kernel<<<dim3(8, 32, 4), 256, SMEM_MM>>>();

    chunk_kernel<<<dim3(NCH, 32), 256, SMEM_CH>>>();
    chunkscan_kernel<<<dim3(4, 32), 512>>>();
    inter_kernel<<<dim3(NCH, 32), 256>>>();
    ln_gate_kernel<<<MTOK, 256>>>(gamma, beta);

    mmout_kernel<<<dim3(8, 32, 1), 256, SMEM_MM>>>(out);
}

// round 12
// speedup vs baseline: 1.4800x; 1.0969x over previous
#include <cuda_runtime.h>
#include <cuda_fp16.h>
#include <math.h>
#include <stdint.h>

#define HIDK 1024
#define MTOK 4096
#define LSEQ 2048
#define NHEAD 16
#define HDIM 64
#define CT 64
#define NCH (LSEQ / CT)
#define PD 68
#define PDH 72

// ---------------- scratch (device globals; no allocations) ----------------
__device__ float g_xg[MTOK * HIDK];
__device__ float g_att[MTOK * HIDK];                      // final o (inter writes)
__device__ __align__(16) __half g_qh16[MTOK * HIDK];
__device__ __align__(16) __half g_kh16[MTOK * HIDK];
__device__ __align__(16) __half g_vh16[MTOK * HIDK];
__device__ __align__(16) __half g_gkh[MTOK * HIDK];
__device__ __align__(16) __half g_expDh[MTOK * HIDK];
__device__ __align__(16) __half g_atth[MTOK * HIDK];      // intra-chunk o
__device__ __align__(16) __half g_Ph[32 * NCH * HDIM * HDIM];
__device__ __align__(16) __half g_Sh[32 * NCH * HDIM * HDIM];
// fp16 GEMM operands
__device__ __align__(16) __half g_xh[MTOK * HIDK];
__device__ __align__(16) __half g_xs[MTOK * HIDK];   // x * 2^-10
__device__ __align__(16) __half g_yh[MTOK * HIDK];
__device__ __align__(16) __half g_wh[5 * HIDK * HIDK];
__device__ __align__(16) __half g_wl[5 * HIDK * HIDK];

// ======================= helpers =======================
__device__ __forceinline__ uint32_t smem_u32(const void* p) {
    uint32_t a;
    asm("{ .reg .u64 t; cvta.to.shared.u64 t, %1; cvt.u32.u64 %0, t; }" : "=r"(a) : "l"(p));
    return a;
}
__device__ __forceinline__ void cpasync16(uint32_t s, const void* g) {
    asm volatile("cp.async.cg.shared.global [%0], [%1], 16;" ::"r"(s), "l"(g));
}
__device__ __forceinline__ void cpcommit() { asm volatile("cp.async.commit_group;"); }

__device__ __forceinline__ void ldmx4(uint32_t& r0, uint32_t& r1, uint32_t& r2,
                                      uint32_t& r3, uint32_t addr) {
    asm volatile("ldmatrix.sync.aligned.m8n8.x4.shared.b16 {%0,%1,%2,%3}, [%4];"
                 : "=r"(r0), "=r"(r1), "=r"(r2), "=r"(r3)
                 : "r"(addr));
}
__device__ __forceinline__ void ldmx4t(uint32_t& r0, uint32_t& r1, uint32_t& r2,
                                       uint32_t& r3, uint32_t addr) {
    asm volatile("ldmatrix.sync.aligned.m8n8.x4.trans.shared.b16 {%0,%1,%2,%3}, [%4];"
                 : "=r"(r0), "=r"(r1), "=r"(r2), "=r"(r3)
                 : "r"(addr));
}
__device__ __forceinline__ void mma16816(float* c, const uint32_t* a, const uint32_t* b) {
    asm volatile(
        "mma.sync.aligned.m16n8k16.row.col.f32.f16.f16.f32 "
        "{%0,%1,%2,%3}, {%4,%5,%6,%7}, {%8,%9}, {%0,%1,%2,%3};"
        : "+f"(c[0]), "+f"(c[1]), "+f"(c[2]), "+f"(c[3])
        : "r"(a[0]), "r"(a[1]), "r"(a[2]), "r"(a[3]), "r"(b[0]), "r"(b[1]));
}

// ======================= fp16 mma.sync big GEMM (R8 ordering) ==============
#define ROWB 80
#define STG_A (128 * ROWB)
#define STG (2 * STG_A)
#define NSTG 4
#define SMEM_MM (NSTG * STG)

__device__ __forceinline__ void mm_issue(int s, int nstages, uint32_t sb, int tid,
                                         int brow, int bcol,
                                         const __half* Ah, const __half* As,
                                         const __half* Bh, const __half* Bl) {
    if (s < nstages) {
        int p = s >> 5;
        int kk = (s & 31) << 5;
        const __half* Ab = p ? As : Ah;
        const __half* Bb = p ? Bl : Bh;
        uint32_t st = sb + (uint32_t)(s & 3) * STG;
        int row = tid >> 2, cw = tid & 3;
        const char* ga = (const char*)(Ab + (size_t)(brow + row) * HIDK + kk + cw * 8);
        cpasync16(st + row * ROWB + cw * 16, ga);
        cpasync16(st + (row + 64) * ROWB + cw * 16, ga + (size_t)64 * HIDK * 2);
        const char* gb = (const char*)(Bb + (size_t)(bcol + row) * HIDK + kk + cw * 8);
        cpasync16(st + STG_A + row * ROWB + cw * 16, gb);
        cpasync16(st + STG_A + (row + 64) * ROWB + cw * 16, gb + (size_t)64 * HIDK * 2);
    }
    cpcommit();
}

__device__ __forceinline__ void mma_gemm_body(const __half* __restrict__ Ah,
                                              const __half* __restrict__ As,
                                              const __half* __restrict__ Bh,
                                              const __half* __restrict__ Bl,
                                              void* __restrict__ Cv, bool half_out,
                                              int nstages) {
    extern __shared__ char sm_raw[];
    uint32_t sb = smem_u32(sm_raw);
    int tid = threadIdx.x, lane = tid & 31, wid = tid >> 5;
    int wm = wid & 3, wn = wid >> 2;
    int brow = blockIdx.y * 128, bcol = blockIdx.x * 128;

    float c[2][8][4];
#pragma unroll
    for (int i = 0; i < 2; i++)
#pragma unroll
        for (int j = 0; j < 8; j++)
#pragma unroll
            for (int l = 0; l < 4; l++) c[i][j][l] = 0.f;

    mm_issue(0, nstages, sb, tid, brow, bcol, Ah, As, Bh, Bl);
    mm_issue(1, nstages, sb, tid, brow, bcol, Ah, As, Bh, Bl);
    mm_issue(2, nstages, sb, tid, brow, bcol, Ah, As, Bh, Bl);

    int q = lane >> 3, r = lane & 7;

    for (int s = 0; s < nstages; s++) {
        asm volatile("cp.async.wait_group 2;" ::: "memory");
        __syncthreads();
        uint32_t st = sb + (uint32_t)(s & 3) * STG;
        uint32_t sA = st, sB = st + STG_A;
#pragma unroll
        for (int k0 = 0; k0 < 32; k0 += 16) {
            uint32_t a[2][4], b[8][2];
#pragma unroll
            for (int mf = 0; mf < 2; mf++) {
                int rrow = wm * 32 + mf * 16 + (q & 1) * 8 + r;
                int kc = k0 + (q >> 1) * 8;
                ldmx4(a[mf][0], a[mf][1], a[mf][2], a[mf][3], sA + rrow * ROWB + kc * 2);
            }
#pragma unroll
            for (int pb = 0; pb < 4; pb++) {
                int nrow = wn * 64 + pb * 16 + (q >> 1) * 8 + r;
                int kc = k0 + (q & 1) * 8;
                uint32_t r0, r1, r2, r3;
                ldmx4(r0, r1, r2, r3, sB + nrow * ROWB + kc * 2);
                b[pb * 2][0] = r0;
                b[pb * 2][1] = r1;
                b[pb * 2 + 1][0] = r2;
                b[pb * 2 + 1][1] = r3;
            }
#pragma unroll
            for (int mf = 0; mf < 2; mf++)
#pragma unroll
                for (int nf = 0; nf < 8; nf++) mma16816(c[mf][nf], a[mf], b[nf]);
        }
        mm_issue(s + 3, nstages, sb, tid, brow, bcol, Ah, As, Bh, Bl);
    }

    int qr = lane >> 2, qc = lane & 3;
    if (half_out) {
        __half* Ch = (__half*)Cv;
#pragma unroll
        for (int mf = 0; mf < 2; mf++)
#pragma unroll
            for (int nf = 0; nf < 8; nf++) {
                int row0 = brow + wm * 32 + mf * 16 + qr;
                int col = bcol + wn * 64 + nf * 8 + qc * 2;
                *(__half2*)&Ch[(size_t)row0 * HIDK + col] =
                    __floats2half2_rn(c[mf][nf][0], c[mf][nf][1]);
                *(__half2*)&Ch[(size_t)(row0 + 8) * HIDK + col] =
                    __floats2half2_rn(c[mf][nf][2], c[mf][nf][3]);
            }
    } else {
        float* Cf = (float*)Cv;
#pragma unroll
        for (int mf = 0; mf < 2; mf++)
#pragma unroll
            for (int nf = 0; nf < 8; nf++) {
                int row0 = brow + wm * 32 + mf * 16 + qr;
                int col = bcol + wn * 64 + nf * 8 + qc * 2;
                *(float2*)&Cf[(size_t)row0 * HIDK + col] =
                    make_float2(c[mf][nf][0], c[mf][nf][1]);
                *(float2*)&Cf[(size_t)(row0 + 8) * HIDK + col] =
                    make_float2(c[mf][nf][2], c[mf][nf][3]);
            }
    }
}

// z=0: gate (2-product, long CTAs scheduled first); z=1..3: q,k,v (1 product)
__global__ void __launch_bounds__(256, 2) mmproj_kernel() {
    int z = blockIdx.z;
    int wsel = (z == 0) ? 3 : (z - 1);  // weight index: Wg=3, Wq=0, Wk=1, Wv=2
    const __half* Bh = g_wh + (size_t)wsel * HIDK * HIDK;
    const __half* Bl = g_wl + (size_t)wsel * HIDK * HIDK;
    void* C;
    bool ho = true;
    int ns = 32;
    switch (z) {
        case 0: C = g_xg; ho = false; ns = 64; break;
        case 1: C = g_qh16; break;
        case 2: C = g_kh16; break;
        default: C = g_vh16; break;
    }
    mma_gemm_body(g_xh, g_xs, Bh, Bl, C, ho, ns);
}
// output GEMM: single hi product (y is fp16-rounded operand anyway)
__global__ void __launch_bounds__(256, 2) mmout_kernel(float* __restrict__ out) {
    mma_gemm_body(g_yh, g_yh, g_wh + (size_t)4 * HIDK * HIDK,
                  g_wh + (size_t)4 * HIDK * HIDK, out, false, 32);
}

// ======================= weight conversion =====================
#define SC_DN (1.f / 1024.f)
__global__ void __launch_bounds__(256) wconv_kernel(const float* __restrict__ W0,
                                                    const float* __restrict__ W1,
                                                    const float* __restrict__ W2,
                                                    const float* __restrict__ W3,
                                                    const float* __restrict__ W4) {
    int z = blockIdx.z;
    const float* W = (z == 0) ? W0 : (z == 1) ? W1 : (z == 2) ? W2 : (z == 3) ? W3 : W4;
    __half* Th = g_wh + (size_t)z * HIDK * HIDK;
    __half* Tl = g_wl + (size_t)z * HIDK * HIDK;
    __shared__ float t[32][33];
    int n0 = blockIdx.x * 32, k0 = blockIdx.y * 32;
    int lx = threadIdx.x & 31, ly = threadIdx.x >> 5;
#pragma unroll
    for (int i = 0; i < 4; i++) {
        int r = ly + i * 8;
        t[r][lx] = W[(size_t)(k0 + r) * HIDK + n0 + lx];
    }
    __syncthreads();
#pragma unroll
    for (int i = 0; i < 4; i++) {
        int r = ly + i * 8;
        float v = t[lx][r];
        __half h = __float2half(v);
        size_t o = (size_t)(n0 + r) * HIDK + k0 + lx;
        Th[o] = h;
        Tl[o] = __float2half((v - __half2float(h)) * 1024.f);
    }
}

// ---------------- fused x-convert + low-rank gate path ----------------------
#define SMEM_LR (32 * 1024 * sizeof(float))
__global__ void __launch_bounds__(256) lr_fused_kernel(const float* __restrict__ x,
                                                       const float* __restrict__ W1,
                                                       const float* __restrict__ W2,
                                                       const float* __restrict__ bias) {
    extern __shared__ float s[];
    float* w1s = s;
    float* w2s = s + 16384;
    __shared__ float ts[16][17];
    int tid = threadIdx.x;
    int m0 = blockIdx.x * 16;

#pragma unroll
    for (int i = 0; i < 16; i++) {
        int idx = tid + i * 256;
        ((float4*)w1s)[idx] = ((const float4*)W1)[idx];
        ((float4*)w2s)[idx] = ((const float4*)W2)[idx];
        float4 v = ((const float4*)x)[(size_t)m0 * (HIDK / 4) + idx];
        size_t eo = (size_t)m0 * HIDK + (size_t)idx * 4;
        *(__half2*)&g_xh[eo] = __floats2half2_rn(v.x, v.y);
        *(__half2*)&g_xh[eo + 2] = __floats2half2_rn(v.z, v.w);
        *(__half2*)&g_xs[eo] = __floats2half2_rn(v.x * SC_DN, v.y * SC_DN);
        *(__half2*)&g_xs[eo + 2] = __floats2half2_rn(v.z * SC_DN, v.w * SC_DN);
    }
    __syncthreads();

    {
        int mt = tid >> 4, r = tid & 15;
        const float* xr = x + (size_t)(m0 + mt) * HIDK;
        float acc = 0.f;
#pragma unroll 8
        for (int kk = 0; kk < HIDK; kk++) acc = fmaf(xr[kk], w1s[kk * 16 + r], acc);
        ts[mt][r] = acc;
    }
    __syncthreads();

    int n = tid * 4;
    float4 b4 = *(const float4*)(bias + n);
#pragma unroll 1
    for (int mi = 0; mi < 16; mi++) {
        float4 a = b4;
#pragma unroll
        for (int rr = 0; rr < 16; rr++) {
            float tv = ts[mi][rr];
            float4 w = *(float4*)&w2s[rr * 1024 + n];
            a.x = fmaf(tv, w.x, a.x);
            a.y = fmaf(tv, w.y, a.y);
            a.z = fmaf(tv, w.z, a.z);
            a.w = fmaf(tv, w.w, a.w);
        }
        float ox = (fminf(a.x, 0.f) - __logf(1.f + __expf(-fabsf(a.x)))) * 0.0625f;
        float oy = (fminf(a.y, 0.f) - __logf(1.f + __expf(-fabsf(a.y)))) * 0.0625f;
        float oz = (fminf(a.z, 0.f) - __logf(1.f + __expf(-fabsf(a.z)))) * 0.0625f;
        float ow = (fminf(a.w, 0.f) - __logf(1.f + __expf(-fabsf(a.w)))) * 0.0625f;
        size_t go = (size_t)(m0 + mi) * HIDK + n;
        *(__half2*)&g_gkh[go] = __floats2half2_rn(ox, oy);
        *(__half2*)&g_gkh[go + 2] = __floats2half2_rn(oz, ow);
    }
}

// ---------------- chunked GLA: kernel A — fp16 tensor cores -----------------
// smem: sGf fp32 [64][68]; Qh/Kh/Uh/Ah fp16 [64][72] (V staged in Uh, converted in place)
#define OFF_Q 17408
#define OFF_K 26624
#define OFF_U 35840
#define OFF_A 45056
#define SMEM_CH 54272

__global__ void __launch_bounds__(256) chunk_kernel() {
    extern __shared__ char smc[];
    float* sGf = (float*)smc;
    uint32_t sb = smem_u32(smc);
    uint32_t Qb = sb + OFF_Q, Kb = sb + OFF_K, Ub = sb + OFF_U, Ab = sb + OFF_A;
    __half* QhP = (__half*)(smc + OFF_Q);
    __half* KhP = (__half*)(smc + OFF_K);
    __half* UhP = (__half*)(smc + OFF_U);
    __half* AhP = (__half*)(smc + OFF_A);
    __shared__ float sTot[4][64];

    int c = blockIdx.x, bh = blockIdx.y;
    int b = bh >> 4, h = bh & 15;
    int tid = threadIdx.x;
    size_t rowbase = (size_t)(b * LSEQ + c * CT) * HIDK + h * HDIM;

    // stage fp16 q,k + v into U-slot + gk(fp16)->fp32
#pragma unroll
    for (int i = 0; i < 2; i++) {
        int idx = tid + i * 256;
        int t = idx >> 3, c8 = (idx & 7) << 3;
        size_t gi = rowbase + (size_t)t * HIDK + c8;
        *(uint4*)&QhP[t * PDH + c8] = *(const uint4*)(g_qh16 + gi);
        *(uint4*)&KhP[t * PDH + c8] = *(const uint4*)(g_kh16 + gi);
        *(uint4*)&UhP[t * PDH + c8] = *(const uint4*)(g_vh16 + gi);
        uint4 gg4 = *(const uint4*)(g_gkh + gi);
        const __half2* gh = (const __half2*)&gg4;
        float* dst = &sGf[t * PD + c8];
        float2 a0 = __half22float2(gh[0]);
        float2 a1 = __half22float2(gh[1]);
        float2 a2 = __half22float2(gh[2]);
        float2 a3 = __half22float2(gh[3]);
        dst[0] = a0.x; dst[1] = a0.y; dst[2] = a1.x; dst[3] = a1.y;
        dst[4] = a2.x; dst[5] = a2.y; dst[6] = a3.x; dst[7] = a3.y;
    }
    __syncthreads();

    // segment-parallel cumsum -> sGf = exp(D), U (in place) = fp16(exp(-D)*v)
    {
        int ch = tid & 63, seg = tid >> 6;
        int t0s = seg * 16;
        float run = 0.f;
#pragma unroll
        for (int t = t0s; t < t0s + 16; t++) {
            run += sGf[t * PD + ch];
            sGf[t * PD + ch] = run;
        }
        sTot[seg][ch] = run;
    }
    __syncthreads();
    {
        int ch = tid & 63, seg = tid >> 6;
        float off = 0.f;
        if (seg > 0) off += sTot[0][ch];
        if (seg > 1) off += sTot[1][ch];
        if (seg > 2) off += sTot[2][ch];
        int t0s = seg * 16;
#pragma unroll
        for (int t = t0s; t < t0s + 16; t++) {
            float D = sGf[t * PD + ch] + off;
            sGf[t * PD + ch] = __expf(D);
            UhP[t * PDH + ch] = __float2half(__expf(-D) * __half2float(UhP[t * PDH + ch]));
        }
    }
    __syncthreads();

    // write exp(D) fp16 to global
#pragma unroll
    for (int i = 0; i < 2; i++) {
        int idx = tid + i * 256;
        int t = idx >> 3, c8 = (idx & 7) << 3;
        __half h8[8];
#pragma unroll
        for (int j = 0; j < 8; j++) h8[j] = __float2half(sGf[t * PD + c8 + j]);
        *(uint4*)(g_expDh + rowbase + (size_t)t * HIDK + c8) = *(uint4*)h8;
    }

    int w = tid >> 5, l = tid & 31;
    int m0 = (w & 3) << 4, n0h = (w >> 2) << 5;
    int lr2 = l >> 2, lc2 = (l & 3) << 1;

    // GEMM1: A = Q.K^T masked -> fp16
    {
        float cc[4][4];
#pragma unroll
        for (int i = 0; i < 4; i++)
#pragma unroll
            for (int j = 0; j < 4; j++) cc[i][j] = 0.f;
#pragma unroll
        for (int k0 = 0; k0 < 64; k0 += 16) {
            uint32_t a[4], b0[4], b1[4];
            ldmx4(a[0], a[1], a[2], a[3],
                  Qb + ((m0 + (l & 15)) * PDH + k0 + ((l & 16) ? 8 : 0)) * 2);
            ldmx4(b0[0], b0[1], b0[2], b0[3],
                  Kb + ((n0h + (l & 7) + ((l & 16) ? 8 : 0)) * PDH + k0 + ((l & 8) ? 8 : 0)) * 2);
            ldmx4(b1[0], b1[1], b1[2], b1[3],
                  Kb + ((n0h + 16 + (l & 7) + ((l & 16) ? 8 : 0)) * PDH + k0 + ((l & 8) ? 8 : 0)) * 2);
            mma16816(cc[0], a, &b0[0]);
            mma16816(cc[1], a, &b0[2]);
            mma16816(cc[2], a, &b1[0]);
            mma16816(cc[3], a, &b1[2]);
        }
        int tr = m0 + lr2;
#pragma unroll
        for (int nf = 0; nf < 4; nf++) {
            int sc = n0h + nf * 8 + lc2;
            *(__half2*)&AhP[tr * PDH + sc] = __halves2half2(
                __float2half(sc <= tr ? cc[nf][0] : 0.f),
                __float2half(sc + 1 <= tr ? cc[nf][1] : 0.f));
            int tr2 = tr + 8;
            *(__half2*)&AhP[tr2 * PDH + sc] = __halves2half2(
                __float2half(sc <= tr2 ? cc[nf][2] : 0.f),
                __float2half(sc + 1 <= tr2 ? cc[nf][3] : 0.f));
        }
    }
    __syncthreads();

    // GEMM2: o_intra = A'.U; scale expD; store fp16
    {
        float cc[4][4];
#pragma unroll
        for (int i = 0; i < 4; i++)
#pragma unroll
            for (int j = 0; j < 4; j++) cc[i][j] = 0.f;
#pragma unroll
        for (int s0 = 0; s0 < 64; s0 += 16) {
            uint32_t a[4], b0[4], b1[4];
            ldmx4(a[0], a[1], a[2], a[3],
                  Ab + ((m0 + (l & 15)) * PDH + s0 + ((l & 16) ? 8 : 0)) * 2);
            ldmx4t(b0[0], b0[1], b0[2], b0[3],
                   Ub + ((s0 + (l & 15)) * PDH + n0h + ((l & 16) ? 8 : 0)) * 2);
            ldmx4t(b1[0], b1[1], b1[2], b1[3],
                   Ub + ((s0 + (l & 15)) * PDH + n0h + 16 + ((l & 16) ? 8 : 0)) * 2);
            mma16816(cc[0], a, &b0[0]);
            mma16816(cc[1], a, &b0[2]);
            mma16816(cc[2], a, &b1[0]);
            mma16816(cc[3], a, &b1[2]);
        }
        int tr = m0 + lr2;
#pragma unroll
        for (int nf = 0; nf < 4; nf++) {
            int v = n0h + nf * 8 + lc2;
            float2 e0 = *(float2*)&sGf[tr * PD + v];
            *(__half2*)&g_atth[rowbase + (size_t)tr * HIDK + v] =
                __floats2half2_rn(cc[nf][0] * e0.x, cc[nf][1] * e0.y);
            float2 e1 = *(float2*)&sGf[(tr + 8) * PD + v];
            *(__half2*)&g_atth[rowbase + (size_t)(tr + 8) * HIDK + v] =
                __floats2half2_rn(cc[nf][2] * e1.x, cc[nf][3] * e1.y);
        }
    }

    // GEMM3: P = U^T.K; scale expD_end; store fp16
    {
        float cc[4][4];
#pragma unroll
        for (int i = 0; i < 4; i++)
#pragma unroll
            for (int j = 0; j < 4; j++) cc[i][j] = 0.f;
#pragma unroll
        for (int s0 = 0; s0 < 64; s0 += 16) {
            uint32_t a[4], b0[4], b1[4];
            ldmx4t(a[0], a[1], a[2], a[3],
                   Ub + ((s0 + (l & 7) + ((l & 16) ? 8 : 0)) * PDH + m0 + ((l & 8) ? 8 : 0)) * 2);
            ldmx4t(b0[0], b0[1], b0[2], b0[3],
                   Kb + ((s0 + (l & 15)) * PDH + n0h + ((l & 16) ? 8 : 0)) * 2);
            ldmx4t(b1[0], b1[1], b1[2], b1[3],
                   Kb + ((s0 + (l & 15)) * PDH + n0h + 16 + ((l & 16) ? 8 : 0)) * 2);
            mma16816(cc[0], a, &b0[0]);
            mma16816(cc[1], a, &b0[2]);
            mma16816(cc[2], a, &b1[0]);
            mma16816(cc[3], a, &b1[2]);
        }
        size_t pbase = ((size_t)(bh * NCH + c)) << 12;
        int vr = m0 + lr2;
        float ev0 = sGf[63 * PD + vr];
        float ev1 = sGf[63 * PD + vr + 8];
#pragma unroll
        for (int nf = 0; nf < 4; nf++) {
            int kd = n0h + nf * 8 + lc2;
            *(__half2*)&g_Ph[pbase + ((size_t)vr << 6) + kd] =
                __floats2half2_rn(cc[nf][0] * ev0, cc[nf][1] * ev0);
            *(__half2*)&g_Ph[pbase + ((size_t)(vr + 8) << 6) + kd] =
                __floats2half2_rn(cc[nf][2] * ev1, cc[nf][3] * ev1);
        }
    }
}

// ---------------- kernel B: scan over chunk states (k-split, fp16 I/O) -----
__global__ void __launch_bounds__(512) chunkscan_kernel() {
    int ks = blockIdx.x;
    int bh = blockIdx.y;
    int b = bh >> 4, h = bh & 15;
    int tid = threadIdx.x;
    int v = tid >> 3;
    int k = ks * 16 + (tid & 7) * 2;
    float2 S = make_float2(0.f, 0.f);

    for (int c = 0; c < NCH; c++) {
        size_t base = (((size_t)(bh * NCH + c)) << 12) + ((size_t)v << 6) + k;
        *(__half2*)(g_Sh + base) = __floats2half2_rn(S.x, S.y);
        float E = __half2float(g_expDh[((size_t)(b * LSEQ + c * CT + 63)) * HIDK + h * HDIM + v]);
        float2 p = __half22float2(*(__half2*)(g_Ph + base));
        S.x = fmaf(S.x, E, p.x);
        S.y = fmaf(S.y, E, p.y);
    }
}

// ---------------- kernel C: inter-chunk output — fp16 tensor cores ---------
__global__ void __launch_bounds__(256) inter_kernel() {
    __shared__ __align__(16) __half sQ[64 * PDH];
    __shared__ __align__(16) __half sS[64 * PDH];
    int c = blockIdx.x, bh = blockIdx.y;
    int b = bh >> 4, h = bh & 15;
    int tid = threadIdx.x;
    size_t rowbase = (size_t)(b * LSEQ + c * CT) * HIDK + h * HDIM;
    size_t sbase = ((size_t)(bh * NCH + c)) << 12;
    uint32_t Qb = smem_u32(sQ), Sb = smem_u32(sS);

#pragma unroll
    for (int i = 0; i < 2; i++) {
        int idx = tid + i * 256;
        int t = idx >> 3, c8 = (idx & 7) << 3;
        *(uint4*)&sQ[t * PDH + c8] = *(const uint4*)(g_qh16 + rowbase + (size_t)t * HIDK + c8);
        *(uint4*)&sS[t * PDH + c8] = *(const uint4*)(g_Sh + sbase + ((size_t)t << 6) + c8);
    }
    __syncthreads();

    int w = tid >> 5, l = tid & 31;
    int m0 = (w & 3) << 4, n0h = (w >> 2) << 5;
    int lr2 = l >> 2, lc2 = (l & 3) << 1;

    float cc[4][4];
#pragma unroll
    for (int i = 0; i < 4; i++)
#pragma unroll
        for (int j = 0; j < 4; j++) cc[i][j] = 0.f;
#pragma unroll
    for (int k0 = 0; k0 < 64; k0 += 16) {
        uint32_t a[4], b0[4], b1[4];
        ldmx4(a[0], a[1], a[2], a[3],
              Qb + ((m0 + (l & 15)) * PDH + k0 + ((l & 16) ? 8 : 0)) * 2);
        ldmx4(b0[0], b0[1], b0[2], b0[3],
              Sb + ((n0h + (l & 7) + ((l & 16) ? 8 : 0)) * PDH + k0 + ((l & 8) ? 8 : 0)) * 2);
        ldmx4(b1[0], b1[1], b1[2], b1[3],
              Sb + ((n0h + 16 + (l & 7) + ((l & 16) ? 8 : 0)) * PDH + k0 + ((l & 8) ? 8 : 0)) * 2);
        mma16816(cc[0], a, &b0[0]);
        mma16816(cc[1], a, &b0[2]);
        mma16816(cc[2], a, &b1[0]);
        mma16816(cc[3], a, &b1[2]);
    }
    int tr = m0 + lr2;
#pragma unroll
    for (int nf = 0; nf < 4; nf++) {
        int v = n0h + nf * 8 + lc2;
        size_t gi0 = rowbase + (size_t)tr * HIDK + v;
        float2 e0 = __half22float2(*(__half2*)(g_expDh + gi0));
        float2 i0 = __half22float2(*(__half2*)(g_atth + gi0));
        *(float2*)(g_att + gi0) =
            make_float2(fmaf(cc[nf][0], e0.x, i0.x), fmaf(cc[nf][1], e0.y, i0.y));
        size_t gi1 = rowbase + (size_t)(tr + 8) * HIDK + v;
        float2 e1 = __half22float2(*(__half2*)(g_expDh + gi1));
        float2 i1 = __half22float2(*(__half2*)(g_atth + gi1));
        *(float2*)(g_att + gi1) =
            make_float2(fmaf(cc[nf][2], e1.x, i1.x), fmaf(cc[nf][3], e1.y, i1.y));
    }
}

// ---------------- LayerNorm + SiLU gate -> fp16 y ----------------
__global__ void __launch_bounds__(256) ln_gate_kernel(const float* __restrict__ gamma,
                                                      const float* __restrict__ beta) {
    int row = blockIdx.x;
    int tid = threadIdx.x;
    const float* a = g_att + (size_t)row * HIDK;
    float vals[4];
    float s = 0.f, s2 = 0.f;
#pragma unroll
    for (int i = 0; i < 4; i++) {
        vals[i] = a[i * 256 + tid];
        s += vals[i];
        s2 = fmaf(vals[i], vals[i], s2);
    }
#pragma unroll
    for (int o = 16; o; o >>= 1) {
        s += __shfl_xor_sync(0xffffffffu, s, o);
        s2 += __shfl_xor_sync(0xffffffffu, s2, o);
    }
    __shared__ float rs[8], rs2[8];
    int warp = tid >> 5;
    if ((tid & 31) == 0) { rs[warp] = s; rs2[warp] = s2; }
    __syncthreads();
    s = 0.f;
    s2 = 0.f;
#pragma unroll
    for (int w = 0; w < 8; w++) { s += rs[w]; s2 += rs2[w]; }
    float mean = s * (1.f / HIDK);
    float var = s2 * (1.f / HIDK) - mean * mean;
    float rstd = rsqrtf(var + 1e-5f);
#pragma unroll
    for (int i = 0; i < 4; i++) {
        int col = i * 256 + tid;
        float gv = g_xg[(size_t)row * HIDK + col];
        float sil = gv / (1.f + __expf(-gv));
        float yv = ((vals[i] - mean) * rstd * gamma[col] + beta[col]) * sil;
        g_yh[(size_t)row * HIDK + col] = __float2half(yv);
    }
}

// ---------------- launch --------------------------------------------------
extern "C" void kernel_launch(void* const* d_in, const int* in_sizes, int n_in,
                              void* d_out, int out_size) {
    const float* x = (const float*)d_in[0];
    const float* Wq = (const float*)d_in[1];
    const float* Wk = (const float*)d_in[2];
    const float* Wv = (const float*)d_in[3];
    const float* Wg = (const float*)d_in[4];
    const float* Wgk1 = (const float*)d_in[5];
    const float* Wgk2 = (const float*)d_in[6];
    const float* bgk2 = (const float*)d_in[7];
    const float* gamma = (const float*)d_in[8];
    const float* beta = (const float*)d_in[9];
    const float* Wout = (const float*)d_in[10];
    float* out = (float*)d_out;

    cudaFuncSetAttribute(chunk_kernel, cudaFuncAttributeMaxDynamicSharedMemorySize, SMEM_CH);
    cudaFuncSetAttribute(mmproj_kernel, cudaFuncAttributeMaxDynamicSharedMemorySize, SMEM_MM);
    cudaFuncSetAttribute(mmout_kernel, cudaFuncAttributeMaxDynamicSharedMemorySize, SMEM_MM);
    cudaFuncSetAttribute(lr_fused_kernel, cudaFuncAttributeMaxDynamicSharedMemorySize, SMEM_LR);

    wconv_kernel<<<dim3(32, 32, 5), 256>>>(Wq, Wk, Wv, Wg, Wout);
    lr_fused_kernel<<<MTOK / 16, 256, SMEM_LR>>>(x, Wgk1, Wgk2, bgk2);

    mmproj_kernel<<<dim3(8, 32, 4), 256, SMEM_MM>>>();

    chunk_kernel<<<dim3(NCH, 32), 256, SMEM_CH>>>();
    chunkscan_kernel<<<dim3(4, 32), 512>>>();
    inter_kernel<<<dim3(NCH, 32), 256>>>();
    ln_gate_kernel<<<MTOK, 256>>>(gamma, beta);

    mmout_kernel<<<dim3(8, 32, 1), 256, SMEM_MM>>>(out);
}

// round 13
// speedup vs baseline: 1.6181x; 1.0933x over previous
#include <cuda_runtime.h>
#include <cuda_fp16.h>
#include <math.h>
#include <stdint.h>

#define HIDK 1024
#define MTOK 4096
#define LSEQ 2048
#define NHEAD 16
#define HDIM 64
#define CT 64
#define NCH (LSEQ / CT)
#define PD 68
#define PDH 72

// ---------------- scratch (device globals; no allocations) ----------------
__device__ float g_xg[MTOK * HIDK];
__device__ float g_att[MTOK * HIDK];                      // final o (inter writes)
__device__ __align__(16) __half g_qh16[MTOK * HIDK];
__device__ __align__(16) __half g_kh16[MTOK * HIDK];
__device__ __align__(16) __half g_vh16[MTOK * HIDK];
__device__ __align__(16) __half g_gkh[MTOK * HIDK];
__device__ __align__(16) __half g_expDh[MTOK * HIDK];
__device__ __align__(16) __half g_atth[MTOK * HIDK];      // intra-chunk o
__device__ __align__(16) __half g_Ph[32 * NCH * HDIM * HDIM];
__device__ __align__(16) __half g_Sh[32 * NCH * HDIM * HDIM];
// fp16 GEMM operands (single-product everywhere)
__device__ __align__(16) __half g_xh[MTOK * HIDK];
__device__ __align__(16) __half g_yh[MTOK * HIDK];
__device__ __align__(16) __half g_wh[5 * HIDK * HIDK];

// ======================= helpers =======================
__device__ __forceinline__ uint32_t smem_u32(const void* p) {
    uint32_t a;
    asm("{ .reg .u64 t; cvta.to.shared.u64 t, %1; cvt.u32.u64 %0, t; }" : "=r"(a) : "l"(p));
    return a;
}
__device__ __forceinline__ void cpasync16(uint32_t s, const void* g) {
    asm volatile("cp.async.cg.shared.global [%0], [%1], 16;" ::"r"(s), "l"(g));
}
__device__ __forceinline__ void cpcommit() { asm volatile("cp.async.commit_group;"); }

__device__ __forceinline__ void ldmx4(uint32_t& r0, uint32_t& r1, uint32_t& r2,
                                      uint32_t& r3, uint32_t addr) {
    asm volatile("ldmatrix.sync.aligned.m8n8.x4.shared.b16 {%0,%1,%2,%3}, [%4];"
                 : "=r"(r0), "=r"(r1), "=r"(r2), "=r"(r3)
                 : "r"(addr));
}
__device__ __forceinline__ void ldmx4t(uint32_t& r0, uint32_t& r1, uint32_t& r2,
                                       uint32_t& r3, uint32_t addr) {
    asm volatile("ldmatrix.sync.aligned.m8n8.x4.trans.shared.b16 {%0,%1,%2,%3}, [%4];"
                 : "=r"(r0), "=r"(r1), "=r"(r2), "=r"(r3)
                 : "r"(addr));
}
__device__ __forceinline__ void mma16816(float* c, const uint32_t* a, const uint32_t* b) {
    asm volatile(
        "mma.sync.aligned.m16n8k16.row.col.f32.f16.f16.f32 "
        "{%0,%1,%2,%3}, {%4,%5,%6,%7}, {%8,%9}, {%0,%1,%2,%3};"
        : "+f"(c[0]), "+f"(c[1]), "+f"(c[2]), "+f"(c[3])
        : "r"(a[0]), "r"(a[1]), "r"(a[2]), "r"(a[3]), "r"(b[0]), "r"(b[1]));
}

// ======================= fp16 mma.sync big GEMM (single product) ============
#define ROWB 80
#define STG_A (128 * ROWB)
#define STG (2 * STG_A)
#define NSTG 4
#define SMEM_MM (NSTG * STG)
#define NSTAGES 32

__device__ __forceinline__ void mm_issue(int s, uint32_t sb, int tid,
                                         int brow, int bcol,
                                         const __half* A, const __half* B) {
    if (s < NSTAGES) {
        int kk = s << 5;
        uint32_t st = sb + (uint32_t)(s & 3) * STG;
        int row = tid >> 2, cw = tid & 3;
        const char* ga = (const char*)(A + (size_t)(brow + row) * HIDK + kk + cw * 8);
        cpasync16(st + row * ROWB + cw * 16, ga);
        cpasync16(st + (row + 64) * ROWB + cw * 16, ga + (size_t)64 * HIDK * 2);
        const char* gb = (const char*)(B + (size_t)(bcol + row) * HIDK + kk + cw * 8);
        cpasync16(st + STG_A + row * ROWB + cw * 16, gb);
        cpasync16(st + STG_A + (row + 64) * ROWB + cw * 16, gb + (size_t)64 * HIDK * 2);
    }
    cpcommit();
}

__device__ __forceinline__ void mma_gemm_body(const __half* __restrict__ A,
                                              const __half* __restrict__ B,
                                              void* __restrict__ Cv, bool half_out) {
    extern __shared__ char sm_raw[];
    uint32_t sb = smem_u32(sm_raw);
    int tid = threadIdx.x, lane = tid & 31, wid = tid >> 5;
    int wm = wid & 3, wn = wid >> 2;
    int brow = blockIdx.y * 128, bcol = blockIdx.x * 128;

    float c[2][8][4];
#pragma unroll
    for (int i = 0; i < 2; i++)
#pragma unroll
        for (int j = 0; j < 8; j++)
#pragma unroll
            for (int l = 0; l < 4; l++) c[i][j][l] = 0.f;

    mm_issue(0, sb, tid, brow, bcol, A, B);
    mm_issue(1, sb, tid, brow, bcol, A, B);
    mm_issue(2, sb, tid, brow, bcol, A, B);

    int q = lane >> 3, r = lane & 7;

    for (int s = 0; s < NSTAGES; s++) {
        asm volatile("cp.async.wait_group 2;" ::: "memory");
        __syncthreads();
        uint32_t st = sb + (uint32_t)(s & 3) * STG;
        uint32_t sA = st, sB = st + STG_A;
#pragma unroll
        for (int k0 = 0; k0 < 32; k0 += 16) {
            uint32_t a[2][4], b[8][2];
#pragma unroll
            for (int mf = 0; mf < 2; mf++) {
                int rrow = wm * 32 + mf * 16 + (q & 1) * 8 + r;
                int kc = k0 + (q >> 1) * 8;
                ldmx4(a[mf][0], a[mf][1], a[mf][2], a[mf][3], sA + rrow * ROWB + kc * 2);
            }
#pragma unroll
            for (int pb = 0; pb < 4; pb++) {
                int nrow = wn * 64 + pb * 16 + (q >> 1) * 8 + r;
                int kc = k0 + (q & 1) * 8;
                uint32_t r0, r1, r2, r3;
                ldmx4(r0, r1, r2, r3, sB + nrow * ROWB + kc * 2);
                b[pb * 2][0] = r0;
                b[pb * 2][1] = r1;
                b[pb * 2 + 1][0] = r2;
                b[pb * 2 + 1][1] = r3;
            }
#pragma unroll
            for (int mf = 0; mf < 2; mf++)
#pragma unroll
                for (int nf = 0; nf < 8; nf++) mma16816(c[mf][nf], a[mf], b[nf]);
        }
        mm_issue(s + 3, sb, tid, brow, bcol, A, B);
    }

    int qr = lane >> 2, qc = lane & 3;
    if (half_out) {
        __half* Ch = (__half*)Cv;
#pragma unroll
        for (int mf = 0; mf < 2; mf++)
#pragma unroll
            for (int nf = 0; nf < 8; nf++) {
                int row0 = brow + wm * 32 + mf * 16 + qr;
                int col = bcol + wn * 64 + nf * 8 + qc * 2;
                *(__half2*)&Ch[(size_t)row0 * HIDK + col] =
                    __floats2half2_rn(c[mf][nf][0], c[mf][nf][1]);
                *(__half2*)&Ch[(size_t)(row0 + 8) * HIDK + col] =
                    __floats2half2_rn(c[mf][nf][2], c[mf][nf][3]);
            }
    } else {
        float* Cf = (float*)Cv;
#pragma unroll
        for (int mf = 0; mf < 2; mf++)
#pragma unroll
            for (int nf = 0; nf < 8; nf++) {
                int row0 = brow + wm * 32 + mf * 16 + qr;
                int col = bcol + wn * 64 + nf * 8 + qc * 2;
                *(float2*)&Cf[(size_t)row0 * HIDK + col] =
                    make_float2(c[mf][nf][0], c[mf][nf][1]);
                *(float2*)&Cf[(size_t)(row0 + 8) * HIDK + col] =
                    make_float2(c[mf][nf][2], c[mf][nf][3]);
            }
    }
}

__global__ void __launch_bounds__(256, 2) mmproj_kernel() {
    int z = blockIdx.z;
    const __half* B = g_wh + (size_t)z * HIDK * HIDK;
    void* C;
    bool ho = true;
    switch (z) {
        case 0: C = g_qh16; break;
        case 1: C = g_kh16; break;
        case 2: C = g_vh16; break;
        default: C = g_xg; ho = false; break;
    }
    mma_gemm_body(g_xh, B, C, ho);
}
__global__ void __launch_bounds__(256, 2) mmout_kernel(float* __restrict__ out) {
    mma_gemm_body(g_yh, g_wh + (size_t)4 * HIDK * HIDK, out, false);
}

// ======================= weight conversion (hi only) =====================
__global__ void __launch_bounds__(256) wconv_kernel(const float* __restrict__ W0,
                                                    const float* __restrict__ W1,
                                                    const float* __restrict__ W2,
                                                    const float* __restrict__ W3,
                                                    const float* __restrict__ W4) {
    int z = blockIdx.z;
    const float* W = (z == 0) ? W0 : (z == 1) ? W1 : (z == 2) ? W2 : (z == 3) ? W3 : W4;
    __half* Th = g_wh + (size_t)z * HIDK * HIDK;
    __shared__ float t[32][33];
    int n0 = blockIdx.x * 32, k0 = blockIdx.y * 32;
    int lx = threadIdx.x & 31, ly = threadIdx.x >> 5;
#pragma unroll
    for (int i = 0; i < 4; i++) {
        int r = ly + i * 8;
        t[r][lx] = W[(size_t)(k0 + r) * HIDK + n0 + lx];
    }
    __syncthreads();
#pragma unroll
    for (int i = 0; i < 4; i++) {
        int r = ly + i * 8;
        Th[(size_t)(n0 + r) * HIDK + k0 + lx] = __float2half(t[lx][r]);
    }
}

// ---------------- fused x-convert + low-rank gate path ----------------------
#define SMEM_LR (32 * 1024 * sizeof(float))
__global__ void __launch_bounds__(256) lr_fused_kernel(const float* __restrict__ x,
                                                       const float* __restrict__ W1,
                                                       const float* __restrict__ W2,
                                                       const float* __restrict__ bias) {
    extern __shared__ float s[];
    float* w1s = s;
    float* w2s = s + 16384;
    __shared__ float ts[16][17];
    int tid = threadIdx.x;
    int m0 = blockIdx.x * 16;

#pragma unroll
    for (int i = 0; i < 16; i++) {
        int idx = tid + i * 256;
        ((float4*)w1s)[idx] = ((const float4*)W1)[idx];
        ((float4*)w2s)[idx] = ((const float4*)W2)[idx];
        float4 v = ((const float4*)x)[(size_t)m0 * (HIDK / 4) + idx];
        size_t eo = (size_t)m0 * HIDK + (size_t)idx * 4;
        *(__half2*)&g_xh[eo] = __floats2half2_rn(v.x, v.y);
        *(__half2*)&g_xh[eo + 2] = __floats2half2_rn(v.z, v.w);
    }
    __syncthreads();

    {
        int mt = tid >> 4, r = tid & 15;
        const float* xr = x + (size_t)(m0 + mt) * HIDK;
        float acc = 0.f;
#pragma unroll 8
        for (int kk = 0; kk < HIDK; kk++) acc = fmaf(xr[kk], w1s[kk * 16 + r], acc);
        ts[mt][r] = acc;
    }
    __syncthreads();

    int n = tid * 4;
    float4 b4 = *(const float4*)(bias + n);
#pragma unroll 1
    for (int mi = 0; mi < 16; mi++) {
        float4 a = b4;
#pragma unroll
        for (int rr = 0; rr < 16; rr++) {
            float tv = ts[mi][rr];
            float4 w = *(float4*)&w2s[rr * 1024 + n];
            a.x = fmaf(tv, w.x, a.x);
            a.y = fmaf(tv, w.y, a.y);
            a.z = fmaf(tv, w.z, a.z);
            a.w = fmaf(tv, w.w, a.w);
        }
        float ox = (fminf(a.x, 0.f) - __logf(1.f + __expf(-fabsf(a.x)))) * 0.0625f;
        float oy = (fminf(a.y, 0.f) - __logf(1.f + __expf(-fabsf(a.y)))) * 0.0625f;
        float oz = (fminf(a.z, 0.f) - __logf(1.f + __expf(-fabsf(a.z)))) * 0.0625f;
        float ow = (fminf(a.w, 0.f) - __logf(1.f + __expf(-fabsf(a.w)))) * 0.0625f;
        size_t go = (size_t)(m0 + mi) * HIDK + n;
        *(__half2*)&g_gkh[go] = __floats2half2_rn(ox, oy);
        *(__half2*)&g_gkh[go + 2] = __floats2half2_rn(oz, ow);
    }
}

// ---------------- chunked GLA: kernel A — fp16 tensor cores -----------------
// smem: sGf fp32 [64][68]; Qh/Kh/Uh/Ah fp16 [64][72] (V staged in Uh, converted in place)
#define OFF_Q 17408
#define OFF_K 26624
#define OFF_U 35840
#define OFF_A 45056
#define SMEM_CH 54272

__global__ void __launch_bounds__(256) chunk_kernel() {
    extern __shared__ char smc[];
    float* sGf = (float*)smc;
    uint32_t sb = smem_u32(smc);
    uint32_t Qb = sb + OFF_Q, Kb = sb + OFF_K, Ub = sb + OFF_U, Ab = sb + OFF_A;
    __half* QhP = (__half*)(smc + OFF_Q);
    __half* KhP = (__half*)(smc + OFF_K);
    __half* UhP = (__half*)(smc + OFF_U);
    __half* AhP = (__half*)(smc + OFF_A);
    __shared__ float sTot[4][64];

    int c = blockIdx.x, bh = blockIdx.y;
    int b = bh >> 4, h = bh & 15;
    int tid = threadIdx.x;
    size_t rowbase = (size_t)(b * LSEQ + c * CT) * HIDK + h * HDIM;

#pragma unroll
    for (int i = 0; i < 2; i++) {
        int idx = tid + i * 256;
        int t = idx >> 3, c8 = (idx & 7) << 3;
        size_t gi = rowbase + (size_t)t * HIDK + c8;
        *(uint4*)&QhP[t * PDH + c8] = *(const uint4*)(g_qh16 + gi);
        *(uint4*)&KhP[t * PDH + c8] = *(const uint4*)(g_kh16 + gi);
        *(uint4*)&UhP[t * PDH + c8] = *(const uint4*)(g_vh16 + gi);
        uint4 gg4 = *(const uint4*)(g_gkh + gi);
        const __half2* gh = (const __half2*)&gg4;
        float* dst = &sGf[t * PD + c8];
        float2 a0 = __half22float2(gh[0]);
        float2 a1 = __half22float2(gh[1]);
        float2 a2 = __half22float2(gh[2]);
        float2 a3 = __half22float2(gh[3]);
        dst[0] = a0.x; dst[1] = a0.y; dst[2] = a1.x; dst[3] = a1.y;
        dst[4] = a2.x; dst[5] = a2.y; dst[6] = a3.x; dst[7] = a3.y;
    }
    __syncthreads();

    {
        int ch = tid & 63, seg = tid >> 6;
        int t0s = seg * 16;
        float run = 0.f;
#pragma unroll
        for (int t = t0s; t < t0s + 16; t++) {
            run += sGf[t * PD + ch];
            sGf[t * PD + ch] = run;
        }
        sTot[seg][ch] = run;
    }
    __syncthreads();
    {
        int ch = tid & 63, seg = tid >> 6;
        float off = 0.f;
        if (seg > 0) off += sTot[0][ch];
        if (seg > 1) off += sTot[1][ch];
        if (seg > 2) off += sTot[2][ch];
        int t0s = seg * 16;
#pragma unroll
        for (int t = t0s; t < t0s + 16; t++) {
            float D = sGf[t * PD + ch] + off;
            sGf[t * PD + ch] = __expf(D);
            UhP[t * PDH + ch] = __float2half(__expf(-D) * __half2float(UhP[t * PDH + ch]));
        }
    }
    __syncthreads();

#pragma unroll
    for (int i = 0; i < 2; i++) {
        int idx = tid + i * 256;
        int t = idx >> 3, c8 = (idx & 7) << 3;
        __half h8[8];
#pragma unroll
        for (int j = 0; j < 8; j++) h8[j] = __float2half(sGf[t * PD + c8 + j]);
        *(uint4*)(g_expDh + rowbase + (size_t)t * HIDK + c8) = *(uint4*)h8;
    }

    int w = tid >> 5, l = tid & 31;
    int m0 = (w & 3) << 4, n0h = (w >> 2) << 5;
    int lr2 = l >> 2, lc2 = (l & 3) << 1;

    // GEMM1: A = Q.K^T masked -> fp16
    {
        float cc[4][4];
#pragma unroll
        for (int i = 0; i < 4; i++)
#pragma unroll
            for (int j = 0; j < 4; j++) cc[i][j] = 0.f;
#pragma unroll
        for (int k0 = 0; k0 < 64; k0 += 16) {
            uint32_t a[4], b0[4], b1[4];
            ldmx4(a[0], a[1], a[2], a[3],
                  Qb + ((m0 + (l & 15)) * PDH + k0 + ((l & 16) ? 8 : 0)) * 2);
            ldmx4(b0[0], b0[1], b0[2], b0[3],
                  Kb + ((n0h + (l & 7) + ((l & 16) ? 8 : 0)) * PDH + k0 + ((l & 8) ? 8 : 0)) * 2);
            ldmx4(b1[0], b1[1], b1[2], b1[3],
                  Kb + ((n0h + 16 + (l & 7) + ((l & 16) ? 8 : 0)) * PDH + k0 + ((l & 8) ? 8 : 0)) * 2);
            mma16816(cc[0], a, &b0[0]);
            mma16816(cc[1], a, &b0[2]);
            mma16816(cc[2], a, &b1[0]);
            mma16816(cc[3], a, &b1[2]);
        }
        int tr = m0 + lr2;
#pragma unroll
        for (int nf = 0; nf < 4; nf++) {
            int sc = n0h + nf * 8 + lc2;
            *(__half2*)&AhP[tr * PDH + sc] = __halves2half2(
                __float2half(sc <= tr ? cc[nf][0] : 0.f),
                __float2half(sc + 1 <= tr ? cc[nf][1] : 0.f));
            int tr2 = tr + 8;
            *(__half2*)&AhP[tr2 * PDH + sc] = __halves2half2(
                __float2half(sc <= tr2 ? cc[nf][2] : 0.f),
                __float2half(sc + 1 <= tr2 ? cc[nf][3] : 0.f));
        }
    }
    __syncthreads();

    // GEMM2: o_intra = A'.U; scale expD; store fp16
    {
        float cc[4][4];
#pragma unroll
        for (int i = 0; i < 4; i++)
#pragma unroll
            for (int j = 0; j < 4; j++) cc[i][j] = 0.f;
#pragma unroll
        for (int s0 = 0; s0 < 64; s0 += 16) {
            uint32_t a[4], b0[4], b1[4];
            ldmx4(a[0], a[1], a[2], a[3],
                  Ab + ((m0 + (l & 15)) * PDH + s0 + ((l & 16) ? 8 : 0)) * 2);
            ldmx4t(b0[0], b0[1], b0[2], b0[3],
                   Ub + ((s0 + (l & 15)) * PDH + n0h + ((l & 16) ? 8 : 0)) * 2);
            ldmx4t(b1[0], b1[1], b1[2], b1[3],
                   Ub + ((s0 + (l & 15)) * PDH + n0h + 16 + ((l & 16) ? 8 : 0)) * 2);
            mma16816(cc[0], a, &b0[0]);
            mma16816(cc[1], a, &b0[2]);
            mma16816(cc[2], a, &b1[0]);
            mma16816(cc[3], a, &b1[2]);
        }
        int tr = m0 + lr2;
#pragma unroll
        for (int nf = 0; nf < 4; nf++) {
            int v = n0h + nf * 8 + lc2;
            float2 e0 = *(float2*)&sGf[tr * PD + v];
            *(__half2*)&g_atth[rowbase + (size_t)tr * HIDK + v] =
                __floats2half2_rn(cc[nf][0] * e0.x, cc[nf][1] * e0.y);
            float2 e1 = *(float2*)&sGf[(tr + 8) * PD + v];
            *(__half2*)&g_atth[rowbase + (size_t)(tr + 8) * HIDK + v] =
                __floats2half2_rn(cc[nf][2] * e1.x, cc[nf][3] * e1.y);
        }
    }

    // GEMM3: P = U^T.K; scale expD_end; store fp16
    {
        float cc[4][4];
#pragma unroll
        for (int i = 0; i < 4; i++)
#pragma unroll
            for (int j = 0; j < 4; j++) cc[i][j] = 0.f;
#pragma unroll
        for (int s0 = 0; s0 < 64; s0 += 16) {
            uint32_t a[4], b0[4], b1[4];
            ldmx4t(a[0], a[1], a[2], a[3],
                   Ub + ((s0 + (l & 7) + ((l & 16) ? 8 : 0)) * PDH + m0 + ((l & 8) ? 8 : 0)) * 2);
            ldmx4t(b0[0], b0[1], b0[2], b0[3],
                   Kb + ((s0 + (l & 15)) * PDH + n0h + ((l & 16) ? 8 : 0)) * 2);
            ldmx4t(b1[0], b1[1], b1[2], b1[3],
                   Kb + ((s0 + (l & 15)) * PDH + n0h + 16 + ((l & 16) ? 8 : 0)) * 2);
            mma16816(cc[0], a, &b0[0]);
            mma16816(cc[1], a, &b0[2]);
            mma16816(cc[2], a, &b1[0]);
            mma16816(cc[3], a, &b1[2]);
        }
        size_t pbase = ((size_t)(bh * NCH + c)) << 12;
        int vr = m0 + lr2;
        float ev0 = sGf[63 * PD + vr];
        float ev1 = sGf[63 * PD + vr + 8];
#pragma unroll
        for (int nf = 0; nf < 4; nf++) {
            int kd = n0h + nf * 8 + lc2;
            *(__half2*)&g_Ph[pbase + ((size_t)vr << 6) + kd] =
                __floats2half2_rn(cc[nf][0] * ev0, cc[nf][1] * ev0);
            *(__half2*)&g_Ph[pbase + ((size_t)(vr + 8) << 6) + kd] =
                __floats2half2_rn(cc[nf][2] * ev1, cc[nf][3] * ev1);
        }
    }
}

// ---------------- kernel B: scan over chunk states (k-split, fp16 I/O) -----
__global__ void __launch_bounds__(512) chunkscan_kernel() {
    int ks = blockIdx.x;
    int bh = blockIdx.y;
    int b = bh >> 4, h = bh & 15;
    int tid = threadIdx.x;
    int v = tid >> 3;
    int k = ks * 16 + (tid & 7) * 2;
    float2 S = make_float2(0.f, 0.f);

    for (int c = 0; c < NCH; c++) {
        size_t base = (((size_t)(bh * NCH + c)) << 12) + ((size_t)v << 6) + k;
        *(__half2*)(g_Sh + base) = __floats2half2_rn(S.x, S.y);
        float E = __half2float(g_expDh[((size_t)(b * LSEQ + c * CT + 63)) * HIDK + h * HDIM + v]);
        float2 p = __half22float2(*(__half2*)(g_Ph + base));
        S.x = fmaf(S.x, E, p.x);
        S.y = fmaf(S.y, E, p.y);
    }
}

// ---------------- kernel C: inter-chunk output — fp16 tensor cores ---------
__global__ void __launch_bounds__(256) inter_kernel() {
    __shared__ __align__(16) __half sQ[64 * PDH];
    __shared__ __align__(16) __half sS[64 * PDH];
    int c = blockIdx.x, bh = blockIdx.y;
    int b = bh >> 4, h = bh & 15;
    int tid = threadIdx.x;
    size_t rowbase = (size_t)(b * LSEQ + c * CT) * HIDK + h * HDIM;
    size_t sbase = ((size_t)(bh * NCH + c)) << 12;
    uint32_t Qb = smem_u32(sQ), Sb = smem_u32(sS);

#pragma unroll
    for (int i = 0; i < 2; i++) {
        int idx = tid + i * 256;
        int t = idx >> 3, c8 = (idx & 7) << 3;
        *(uint4*)&sQ[t * PDH + c8] = *(const uint4*)(g_qh16 + rowbase + (size_t)t * HIDK + c8);
        *(uint4*)&sS[t * PDH + c8] = *(const uint4*)(g_Sh + sbase + ((size_t)t << 6) + c8);
    }
    __syncthreads();

    int w = tid >> 5, l = tid & 31;
    int m0 = (w & 3) << 4, n0h = (w >> 2) << 5;
    int lr2 = l >> 2, lc2 = (l & 3) << 1;

    float cc[4][4];
#pragma unroll
    for (int i = 0; i < 4; i++)
#pragma unroll
        for (int j = 0; j < 4; j++) cc[i][j] = 0.f;
#pragma unroll
    for (int k0 = 0; k0 < 64; k0 += 16) {
        uint32_t a[4], b0[4], b1[4];
        ldmx4(a[0], a[1], a[2], a[3],
              Qb + ((m0 + (l & 15)) * PDH + k0 + ((l & 16) ? 8 : 0)) * 2);
        ldmx4(b0[0], b0[1], b0[2], b0[3],
              Sb + ((n0h + (l & 7) + ((l & 16) ? 8 : 0)) * PDH + k0 + ((l & 8) ? 8 : 0)) * 2);
        ldmx4(b1[0], b1[1], b1[2], b1[3],
              Sb + ((n0h + 16 + (l & 7) + ((l & 16) ? 8 : 0)) * PDH + k0 + ((l & 8) ? 8 : 0)) * 2);
        mma16816(cc[0], a, &b0[0]);
        mma16816(cc[1], a, &b0[2]);
        mma16816(cc[2], a, &b1[0]);
        mma16816(cc[3], a, &b1[2]);
    }
    int tr = m0 + lr2;
#pragma unroll
    for (int nf = 0; nf < 4; nf++) {
        int v = n0h + nf * 8 + lc2;
        size_t gi0 = rowbase + (size_t)tr * HIDK + v;
        float2 e0 = __half22float2(*(__half2*)(g_expDh + gi0));
        float2 i0 = __half22float2(*(__half2*)(g_atth + gi0));
        *(float2*)(g_att + gi0) =
            make_float2(fmaf(cc[nf][0], e0.x, i0.x), fmaf(cc[nf][1], e0.y, i0.y));
        size_t gi1 = rowbase + (size_t)(tr + 8) * HIDK + v;
        float2 e1 = __half22float2(*(__half2*)(g_expDh + gi1));
        float2 i1 = __half22float2(*(__half2*)(g_atth + gi1));
        *(float2*)(g_att + gi1) =
            make_float2(fmaf(cc[nf][2], e1.x, i1.x), fmaf(cc[nf][3], e1.y, i1.y));
    }
}

// ---------------- LayerNorm + SiLU gate -> fp16 y ----------------
__global__ void __launch_bounds__(256) ln_gate_kernel(const float* __restrict__ gamma,
                                                      const float* __restrict__ beta) {
    int row = blockIdx.x;
    int tid = threadIdx.x;
    const float* a = g_att + (size_t)row * HIDK;
    float vals[4];
    float s = 0.f, s2 = 0.f;
#pragma unroll
    for (int i = 0; i < 4; i++) {
        vals[i] = a[i * 256 + tid];
        s += vals[i];
        s2 = fmaf(vals[i], vals[i], s2);
    }
#pragma unroll
    for (int o = 16; o; o >>= 1) {
        s += __shfl_xor_sync(0xffffffffu, s, o);
        s2 += __shfl_xor_sync(0xffffffffu, s2, o);
    }
    __shared__ float rs[8], rs2[8];
    int warp = tid >> 5;
    if ((tid & 31) == 0) { rs[warp] = s; rs2[warp] = s2; }
    __syncthreads();
    s = 0.f;
    s2 = 0.f;
#pragma unroll
    for (int w = 0; w < 8; w++) { s += rs[w]; s2 += rs2[w]; }
    float mean = s * (1.f / HIDK);
    float var = s2 * (1.f / HIDK) - mean * mean;
    float rstd = rsqrtf(var + 1e-5f);
#pragma unroll
    for (int i = 0; i < 4; i++) {
        int col = i * 256 + tid;
        float gv = g_xg[(size_t)row * HIDK + col];
        float sil = gv / (1.f + __expf(-gv));
        float yv = ((vals[i] - mean) * rstd * gamma[col] + beta[col]) * sil;
        g_yh[(size_t)row * HIDK + col] = __float2half(yv);
    }
}

// ---------------- launch --------------------------------------------------
extern "C" void kernel_launch(void* const* d_in, const int* in_sizes, int n_in,
                              void* d_out, int out_size) {
    const float* x = (const float*)d_in[0];
    const float* Wq = (const float*)d_in[1];
    const float* Wk = (const float*)d_in[2];
    const float* Wv = (const float*)d_in[3];
    const float* Wg = (const float*)d_in[4];
    const float* Wgk1 = (const float*)d_in[5];
    const float* Wgk2 = (const float*)d_in[6];
    const float* bgk2 = (const float*)d_in[7];
    const float* gamma = (const float*)d_in[8];
    const float* beta = (const float*)d_in[9];
    const float* Wout = (const float*)d_in[10];
    float* out = (float*)d_out;

    cudaFuncSetAttribute(chunk_kernel, cudaFuncAttributeMaxDynamicSharedMemorySize, SMEM_CH);
    cudaFuncSetAttribute(mmproj_kernel, cudaFuncAttributeMaxDynamicSharedMemorySize, SMEM_MM);
    cudaFuncSetAttribute(mmout_kernel, cudaFuncAttributeMaxDynamicSharedMemorySize, SMEM_MM);
    cudaFuncSetAttribute(lr_fused_kernel, cudaFuncAttributeMaxDynamicSharedMemorySize, SMEM_LR);

    wconv_kernel<<<dim3(32, 32, 5), 256>>>(Wq, Wk, Wv, Wg, Wout);
    lr_fused_kernel<<<MTOK / 16, 256, SMEM_LR>>>(x, Wgk1, Wgk2, bgk2);

    mmproj_kernel<<<dim3(8, 32, 4), 256, SMEM_MM>>>();

    chunk_kernel<<<dim3(NCH, 32), 256, SMEM_CH>>>();
    chunkscan_kernel<<<dim3(4, 32), 512>>>();
    inter_kernel<<<dim3(NCH, 32), 256>>>();
    ln_gate_kernel<<<MTOK, 256>>>(gamma, beta);

    mmout_kernel<<<dim3(8, 32, 1), 256, SMEM_MM>>>(out);
}

// round 14
// speedup vs baseline: 1.8465x; 1.1412x over previous
#include <cuda_runtime.h>
#include <cuda_fp16.h>
#include <math.h>
#include <stdint.h>

#define HIDK 1024
#define MTOK 4096
#define LSEQ 2048
#define NHEAD 16
#define HDIM 64
#define CT 64
#define NCH (LSEQ / CT)
#define PD 68
#define PDH 72

// ---------------- scratch (device globals; no allocations) ----------------
__device__ float g_xg[MTOK * HIDK];
__device__ __align__(16) __half g_attf[MTOK * HIDK];      // final o (fp16)
__device__ __align__(16) __half g_qh16[MTOK * HIDK];
__device__ __align__(16) __half g_kh16[MTOK * HIDK];
__device__ __align__(16) __half g_vh16[MTOK * HIDK];
__device__ __align__(16) __half g_gkh[MTOK * HIDK];
__device__ __align__(16) __half g_expDh[MTOK * HIDK];
__device__ __align__(16) __half g_atth[MTOK * HIDK];      // intra-chunk o
__device__ __align__(16) __half g_Ph[32 * NCH * HDIM * HDIM];
__device__ __align__(16) __half g_Sh[32 * NCH * HDIM * HDIM];
// fp16 GEMM operands (single-product everywhere)
__device__ __align__(16) __half g_xh[MTOK * HIDK];
__device__ __align__(16) __half g_yh[MTOK * HIDK];
__device__ __align__(16) __half g_wh[5 * HIDK * HIDK];

// ======================= helpers =======================
__device__ __forceinline__ uint32_t smem_u32(const void* p) {
    uint32_t a;
    asm("{ .reg .u64 t; cvta.to.shared.u64 t, %1; cvt.u32.u64 %0, t; }" : "=r"(a) : "l"(p));
    return a;
}
__device__ __forceinline__ void cpasync16(uint32_t s, const void* g) {
    asm volatile("cp.async.cg.shared.global [%0], [%1], 16;" ::"r"(s), "l"(g));
}
__device__ __forceinline__ void cpcommit() { asm volatile("cp.async.commit_group;"); }

__device__ __forceinline__ void ldmx4(uint32_t& r0, uint32_t& r1, uint32_t& r2,
                                      uint32_t& r3, uint32_t addr) {
    asm volatile("ldmatrix.sync.aligned.m8n8.x4.shared.b16 {%0,%1,%2,%3}, [%4];"
                 : "=r"(r0), "=r"(r1), "=r"(r2), "=r"(r3)
                 : "r"(addr));
}
__device__ __forceinline__ void ldmx4t(uint32_t& r0, uint32_t& r1, uint32_t& r2,
                                       uint32_t& r3, uint32_t addr) {
    asm volatile("ldmatrix.sync.aligned.m8n8.x4.trans.shared.b16 {%0,%1,%2,%3}, [%4];"
                 : "=r"(r0), "=r"(r1), "=r"(r2), "=r"(r3)
                 : "r"(addr));
}
__device__ __forceinline__ void mma16816(float* c, const uint32_t* a, const uint32_t* b) {
    asm volatile(
        "mma.sync.aligned.m16n8k16.row.col.f32.f16.f16.f32 "
        "{%0,%1,%2,%3}, {%4,%5,%6,%7}, {%8,%9}, {%0,%1,%2,%3};"
        : "+f"(c[0]), "+f"(c[1]), "+f"(c[2]), "+f"(c[3])
        : "r"(a[0]), "r"(a[1]), "r"(a[2]), "r"(a[3]), "r"(b[0]), "r"(b[1]));
}

// ======================= fp16 mma.sync big GEMM (BK=64, 3-stage) ============
#define ROWB2 144                 // 64 fp16 (128B) + 16B pad
#define BLK2 (128 * ROWB2)        // 18432 bytes per operand block
#define STG2 (2 * BLK2)           // 36864 bytes per stage
#define NSTG2 3
#define SMEM_MM (NSTG2 * STG2)    // 110592 bytes
#define NSTAGES 16                // 1024 / 64

__device__ __forceinline__ void mm_issue(int s, uint32_t sb, int tid,
                                         int brow, int bcol,
                                         const __half* A, const __half* B) {
    if (s < NSTAGES) {
        int kk = s << 6;
        uint32_t st = sb + (uint32_t)(s % NSTG2) * STG2;
        int row0 = tid >> 3, cw = tid & 7;
        uint32_t so = row0 * ROWB2 + cw * 16;
        size_t go = (size_t)(brow + row0) * HIDK + kk + cw * 8;
#pragma unroll
        for (int p = 0; p < 4; p++)
            cpasync16(st + so + p * 32 * ROWB2, A + go + (size_t)p * 32 * HIDK);
        size_t gob = (size_t)(bcol + row0) * HIDK + kk + cw * 8;
#pragma unroll
        for (int p = 0; p < 4; p++)
            cpasync16(st + BLK2 + so + p * 32 * ROWB2, B + gob + (size_t)p * 32 * HIDK);
    }
    cpcommit();
}

__device__ __forceinline__ void mma_gemm_body(const __half* __restrict__ A,
                                              const __half* __restrict__ B,
                                              void* __restrict__ Cv, bool half_out) {
    extern __shared__ char sm_raw[];
    uint32_t sb = smem_u32(sm_raw);
    int tid = threadIdx.x, lane = tid & 31, wid = tid >> 5;
    int wm = wid & 3, wn = wid >> 2;
    int brow = blockIdx.y * 128, bcol = blockIdx.x * 128;

    float c[2][8][4];
#pragma unroll
    for (int i = 0; i < 2; i++)
#pragma unroll
        for (int j = 0; j < 8; j++)
#pragma unroll
            for (int l = 0; l < 4; l++) c[i][j][l] = 0.f;

    mm_issue(0, sb, tid, brow, bcol, A, B);
    mm_issue(1, sb, tid, brow, bcol, A, B);

    int q = lane >> 3, r = lane & 7;

    for (int s = 0; s < NSTAGES; s++) {
        asm volatile("cp.async.wait_group 1;" ::: "memory");
        __syncthreads();
        uint32_t st = sb + (uint32_t)(s % NSTG2) * STG2;
        uint32_t sA = st, sB = st + BLK2;
#pragma unroll
        for (int k0 = 0; k0 < 64; k0 += 16) {
            uint32_t a[2][4], b[8][2];
#pragma unroll
            for (int mf = 0; mf < 2; mf++) {
                int rrow = wm * 32 + mf * 16 + (q & 1) * 8 + r;
                int kc = k0 + (q >> 1) * 8;
                ldmx4(a[mf][0], a[mf][1], a[mf][2], a[mf][3], sA + rrow * ROWB2 + kc * 2);
            }
#pragma unroll
            for (int pb = 0; pb < 4; pb++) {
                int nrow = wn * 64 + pb * 16 + (q >> 1) * 8 + r;
                int kc = k0 + (q & 1) * 8;
                uint32_t r0, r1, r2, r3;
                ldmx4(r0, r1, r2, r3, sB + nrow * ROWB2 + kc * 2);
                b[pb * 2][0] = r0;
                b[pb * 2][1] = r1;
                b[pb * 2 + 1][0] = r2;
                b[pb * 2 + 1][1] = r3;
            }
#pragma unroll
            for (int mf = 0; mf < 2; mf++)
#pragma unroll
                for (int nf = 0; nf < 8; nf++) mma16816(c[mf][nf], a[mf], b[nf]);
        }
        mm_issue(s + 2, sb, tid, brow, bcol, A, B);
    }

    int qr = lane >> 2, qc = lane & 3;
    if (half_out) {
        __half* Ch = (__half*)Cv;
#pragma unroll
        for (int mf = 0; mf < 2; mf++)
#pragma unroll
            for (int nf = 0; nf < 8; nf++) {
                int row0 = brow + wm * 32 + mf * 16 + qr;
                int col = bcol + wn * 64 + nf * 8 + qc * 2;
                *(__half2*)&Ch[(size_t)row0 * HIDK + col] =
                    __floats2half2_rn(c[mf][nf][0], c[mf][nf][1]);
                *(__half2*)&Ch[(size_t)(row0 + 8) * HIDK + col] =
                    __floats2half2_rn(c[mf][nf][2], c[mf][nf][3]);
            }
    } else {
        float* Cf = (float*)Cv;
#pragma unroll
        for (int mf = 0; mf < 2; mf++)
#pragma unroll
            for (int nf = 0; nf < 8; nf++) {
                int row0 = brow + wm * 32 + mf * 16 + qr;
                int col = bcol + wn * 64 + nf * 8 + qc * 2;
                *(float2*)&Cf[(size_t)row0 * HIDK + col] =
                    make_float2(c[mf][nf][0], c[mf][nf][1]);
                *(float2*)&Cf[(size_t)(row0 + 8) * HIDK + col] =
                    make_float2(c[mf][nf][2], c[mf][nf][3]);
            }
    }
}

__global__ void __launch_bounds__(256, 2) mmproj_kernel() {
    int z = blockIdx.z;
    const __half* B = g_wh + (size_t)z * HIDK * HIDK;
    void* C;
    bool ho = true;
    switch (z) {
        case 0: C = g_qh16; break;
        case 1: C = g_kh16; break;
        case 2: C = g_vh16; break;
        default: C = g_xg; ho = false; break;
    }
    mma_gemm_body(g_xh, B, C, ho);
}
__global__ void __launch_bounds__(256, 2) mmout_kernel(float* __restrict__ out) {
    mma_gemm_body(g_yh, g_wh + (size_t)4 * HIDK * HIDK, out, false);
}

// ======================= weight conversion (hi only) =====================
__global__ void __launch_bounds__(256) wconv_kernel(const float* __restrict__ W0,
                                                    const float* __restrict__ W1,
                                                    const float* __restrict__ W2,
                                                    const float* __restrict__ W3,
                                                    const float* __restrict__ W4) {
    int z = blockIdx.z;
    const float* W = (z == 0) ? W0 : (z == 1) ? W1 : (z == 2) ? W2 : (z == 3) ? W3 : W4;
    __half* Th = g_wh + (size_t)z * HIDK * HIDK;
    __shared__ float t[32][33];
    int n0 = blockIdx.x * 32, k0 = blockIdx.y * 32;
    int lx = threadIdx.x & 31, ly = threadIdx.x >> 5;
#pragma unroll
    for (int i = 0; i < 4; i++) {
        int r = ly + i * 8;
        t[r][lx] = W[(size_t)(k0 + r) * HIDK + n0 + lx];
    }
    __syncthreads();
#pragma unroll
    for (int i = 0; i < 4; i++) {
        int r = ly + i * 8;
        Th[(size_t)(n0 + r) * HIDK + k0 + lx] = __float2half(t[lx][r]);
    }
}

// ---------------- fused x-convert + low-rank gate path ----------------------
#define SMEM_LR (32 * 1024 * sizeof(float))
__global__ void __launch_bounds__(256) lr_fused_kernel(const float* __restrict__ x,
                                                       const float* __restrict__ W1,
                                                       const float* __restrict__ W2,
                                                       const float* __restrict__ bias) {
    extern __shared__ float s[];
    float* w1s = s;
    float* w2s = s + 16384;
    __shared__ float ts[16][17];
    int tid = threadIdx.x;
    int m0 = blockIdx.x * 16;

#pragma unroll
    for (int i = 0; i < 16; i++) {
        int idx = tid + i * 256;
        ((float4*)w1s)[idx] = ((const float4*)W1)[idx];
        ((float4*)w2s)[idx] = ((const float4*)W2)[idx];
        float4 v = ((const float4*)x)[(size_t)m0 * (HIDK / 4) + idx];
        size_t eo = (size_t)m0 * HIDK + (size_t)idx * 4;
        *(__half2*)&g_xh[eo] = __floats2half2_rn(v.x, v.y);
        *(__half2*)&g_xh[eo + 2] = __floats2half2_rn(v.z, v.w);
    }
    __syncthreads();

    {
        int mt = tid >> 4, r = tid & 15;
        const float4* xr4 = (const float4*)(x + (size_t)(m0 + mt) * HIDK);
        float acc = 0.f;
#pragma unroll 4
        for (int k4 = 0; k4 < 256; k4++) {
            float4 xv = xr4[k4];
            int kb = k4 * 4;
            acc = fmaf(xv.x, w1s[(kb + 0) * 16 + r], acc);
            acc = fmaf(xv.y, w1s[(kb + 1) * 16 + r], acc);
            acc = fmaf(xv.z, w1s[(kb + 2) * 16 + r], acc);
            acc = fmaf(xv.w, w1s[(kb + 3) * 16 + r], acc);
        }
        ts[mt][r] = acc;
    }
    __syncthreads();

    int n = tid * 4;
    float4 b4 = *(const float4*)(bias + n);
#pragma unroll 1
    for (int mi = 0; mi < 16; mi++) {
        float4 a = b4;
#pragma unroll
        for (int rr = 0; rr < 16; rr++) {
            float tv = ts[mi][rr];
            float4 w = *(float4*)&w2s[rr * 1024 + n];
            a.x = fmaf(tv, w.x, a.x);
            a.y = fmaf(tv, w.y, a.y);
            a.z = fmaf(tv, w.z, a.z);
            a.w = fmaf(tv, w.w, a.w);
        }
        float ox = (fminf(a.x, 0.f) - __logf(1.f + __expf(-fabsf(a.x)))) * 0.0625f;
        float oy = (fminf(a.y, 0.f) - __logf(1.f + __expf(-fabsf(a.y)))) * 0.0625f;
        float oz = (fminf(a.z, 0.f) - __logf(1.f + __expf(-fabsf(a.z)))) * 0.0625f;
        float ow = (fminf(a.w, 0.f) - __logf(1.f + __expf(-fabsf(a.w)))) * 0.0625f;
        size_t go = (size_t)(m0 + mi) * HIDK + n;
        *(__half2*)&g_gkh[go] = __floats2half2_rn(ox, oy);
        *(__half2*)&g_gkh[go + 2] = __floats2half2_rn(oz, ow);
    }
}

// ---------------- chunked GLA: kernel A — fp16 tensor cores -----------------
// smem: sGf fp32 [64][68]; Qh/Kh/Uh/Ah fp16 [64][72] (V staged in Uh, converted in place)
#define OFF_Q 17408
#define OFF_K 26624
#define OFF_U 35840
#define OFF_A 45056
#define SMEM_CH 54272

__global__ void __launch_bounds__(256) chunk_kernel() {
    extern __shared__ char smc[];
    float* sGf = (float*)smc;
    uint32_t sb = smem_u32(smc);
    uint32_t Qb = sb + OFF_Q, Kb = sb + OFF_K, Ub = sb + OFF_U, Ab = sb + OFF_A;
    __half* QhP = (__half*)(smc + OFF_Q);
    __half* KhP = (__half*)(smc + OFF_K);
    __half* UhP = (__half*)(smc + OFF_U);
    __half* AhP = (__half*)(smc + OFF_A);
    __shared__ float sTot[4][64];

    int c = blockIdx.x, bh = blockIdx.y;
    int b = bh >> 4, h = bh & 15;
    int tid = threadIdx.x;
    size_t rowbase = (size_t)(b * LSEQ + c * CT) * HIDK + h * HDIM;

#pragma unroll
    for (int i = 0; i < 2; i++) {
        int idx = tid + i * 256;
        int t = idx >> 3, c8 = (idx & 7) << 3;
        size_t gi = rowbase + (size_t)t * HIDK + c8;
        *(uint4*)&QhP[t * PDH + c8] = *(const uint4*)(g_qh16 + gi);
        *(uint4*)&KhP[t * PDH + c8] = *(const uint4*)(g_kh16 + gi);
        *(uint4*)&UhP[t * PDH + c8] = *(const uint4*)(g_vh16 + gi);
        uint4 gg4 = *(const uint4*)(g_gkh + gi);
        const __half2* gh = (const __half2*)&gg4;
        float* dst = &sGf[t * PD + c8];
        float2 a0 = __half22float2(gh[0]);
        float2 a1 = __half22float2(gh[1]);
        float2 a2 = __half22float2(gh[2]);
        float2 a3 = __half22float2(gh[3]);
        dst[0] = a0.x; dst[1] = a0.y; dst[2] = a1.x; dst[3] = a1.y;
        dst[4] = a2.x; dst[5] = a2.y; dst[6] = a3.x; dst[7] = a3.y;
    }
    __syncthreads();

    {
        int ch = tid & 63, seg = tid >> 6;
        int t0s = seg * 16;
        float run = 0.f;
#pragma unroll
        for (int t = t0s; t < t0s + 16; t++) {
            run += sGf[t * PD + ch];
            sGf[t * PD + ch] = run;
        }
        sTot[seg][ch] = run;
    }
    __syncthreads();
    {
        int ch = tid & 63, seg = tid >> 6;
        float off = 0.f;
        if (seg > 0) off += sTot[0][ch];
        if (seg > 1) off += sTot[1][ch];
        if (seg > 2) off += sTot[2][ch];
        int t0s = seg * 16;
#pragma unroll
        for (int t = t0s; t < t0s + 16; t++) {
            float D = sGf[t * PD + ch] + off;
            sGf[t * PD + ch] = __expf(D);
            UhP[t * PDH + ch] = __float2half(__expf(-D) * __half2float(UhP[t * PDH + ch]));
        }
    }
    __syncthreads();

#pragma unroll
    for (int i = 0; i < 2; i++) {
        int idx = tid + i * 256;
        int t = idx >> 3, c8 = (idx & 7) << 3;
        __half h8[8];
#pragma unroll
        for (int j = 0; j < 8; j++) h8[j] = __float2half(sGf[t * PD + c8 + j]);
        *(uint4*)(g_expDh + rowbase + (size_t)t * HIDK + c8) = *(uint4*)h8;
    }

    int w = tid >> 5, l = tid & 31;
    int m0 = (w & 3) << 4, n0h = (w >> 2) << 5;
    int lr2 = l >> 2, lc2 = (l & 3) << 1;

    // GEMM1: A = Q.K^T masked -> fp16
    {
        float cc[4][4];
#pragma unroll
        for (int i = 0; i < 4; i++)
#pragma unroll
            for (int j = 0; j < 4; j++) cc[i][j] = 0.f;
#pragma unroll
        for (int k0 = 0; k0 < 64; k0 += 16) {
            uint32_t a[4], b0[4], b1[4];
            ldmx4(a[0], a[1], a[2], a[3],
                  Qb + ((m0 + (l & 15)) * PDH + k0 + ((l & 16) ? 8 : 0)) * 2);
            ldmx4(b0[0], b0[1], b0[2], b0[3],
                  Kb + ((n0h + (l & 7) + ((l & 16) ? 8 : 0)) * PDH + k0 + ((l & 8) ? 8 : 0)) * 2);
            ldmx4(b1[0], b1[1], b1[2], b1[3],
                  Kb + ((n0h + 16 + (l & 7) + ((l & 16) ? 8 : 0)) * PDH + k0 + ((l & 8) ? 8 : 0)) * 2);
            mma16816(cc[0], a, &b0[0]);
            mma16816(cc[1], a, &b0[2]);
            mma16816(cc[2], a, &b1[0]);
            mma16816(cc[3], a, &b1[2]);
        }
        int tr = m0 + lr2;
#pragma unroll
        for (int nf = 0; nf < 4; nf++) {
            int sc = n0h + nf * 8 + lc2;
            *(__half2*)&AhP[tr * PDH + sc] = __halves2half2(
                __float2half(sc <= tr ? cc[nf][0] : 0.f),
                __float2half(sc + 1 <= tr ? cc[nf][1] : 0.f));
            int tr2 = tr + 8;
            *(__half2*)&AhP[tr2 * PDH + sc] = __halves2half2(
                __float2half(sc <= tr2 ? cc[nf][2] : 0.f),
                __float2half(sc + 1 <= tr2 ? cc[nf][3] : 0.f));
        }
    }
    __syncthreads();

    // GEMM2: o_intra = A'.U; scale expD; store fp16
    {
        float cc[4][4];
#pragma unroll
        for (int i = 0; i < 4; i++)
#pragma unroll
            for (int j = 0; j < 4; j++) cc[i][j] = 0.f;
#pragma unroll
        for (int s0 = 0; s0 < 64; s0 += 16) {
            uint32_t a[4], b0[4], b1[4];
            ldmx4(a[0], a[1], a[2], a[3],
                  Ab + ((m0 + (l & 15)) * PDH + s0 + ((l & 16) ? 8 : 0)) * 2);
            ldmx4t(b0[0], b0[1], b0[2], b0[3],
                   Ub + ((s0 + (l & 15)) * PDH + n0h + ((l & 16) ? 8 : 0)) * 2);
            ldmx4t(b1[0], b1[1], b1[2], b1[3],
                   Ub + ((s0 + (l & 15)) * PDH + n0h + 16 + ((l & 16) ? 8 : 0)) * 2);
            mma16816(cc[0], a, &b0[0]);
            mma16816(cc[1], a, &b0[2]);
            mma16816(cc[2], a, &b1[0]);
            mma16816(cc[3], a, &b1[2]);
        }
        int tr = m0 + lr2;
#pragma unroll
        for (int nf = 0; nf < 4; nf++) {
            int v = n0h + nf * 8 + lc2;
            float2 e0 = *(float2*)&sGf[tr * PD + v];
            *(__half2*)&g_atth[rowbase + (size_t)tr * HIDK + v] =
                __floats2half2_rn(cc[nf][0] * e0.x, cc[nf][1] * e0.y);
            float2 e1 = *(float2*)&sGf[(tr + 8) * PD + v];
            *(__half2*)&g_atth[rowbase + (size_t)(tr + 8) * HIDK + v] =
                __floats2half2_rn(cc[nf][2] * e1.x, cc[nf][3] * e1.y);
        }
    }

    // GEMM3: P = U^T.K; scale expD_end; store fp16
    {
        float cc[4][4];
#pragma unroll
        for (int i = 0; i < 4; i++)
#pragma unroll
            for (int j = 0; j < 4; j++) cc[i][j] = 0.f;
#pragma unroll
        for (int s0 = 0; s0 < 64; s0 += 16) {
            uint32_t a[4], b0[4], b1[4];
            ldmx4t(a[0], a[1], a[2], a[3],
                   Ub + ((s0 + (l & 7) + ((l & 16) ? 8 : 0)) * PDH + m0 + ((l & 8) ? 8 : 0)) * 2);
            ldmx4t(b0[0], b0[1], b0[2], b0[3],
                   Kb + ((s0 + (l & 15)) * PDH + n0h + ((l & 16) ? 8 : 0)) * 2);
            ldmx4t(b1[0], b1[1], b1[2], b1[3],
                   Kb + ((s0 + (l & 15)) * PDH + n0h + 16 + ((l & 16) ? 8 : 0)) * 2);
            mma16816(cc[0], a, &b0[0]);
            mma16816(cc[1], a, &b0[2]);
            mma16816(cc[2], a, &b1[0]);
            mma16816(cc[3], a, &b1[2]);
        }
        size_t pbase = ((size_t)(bh * NCH + c)) << 12;
        int vr = m0 + lr2;
        float ev0 = sGf[63 * PD + vr];
        float ev1 = sGf[63 * PD + vr + 8];
#pragma unroll
        for (int nf = 0; nf < 4; nf++) {
            int kd = n0h + nf * 8 + lc2;
            *(__half2*)&g_Ph[pbase + ((size_t)vr << 6) + kd] =
                __floats2half2_rn(cc[nf][0] * ev0, cc[nf][1] * ev0);
            *(__half2*)&g_Ph[pbase + ((size_t)(vr + 8) << 6) + kd] =
                __floats2half2_rn(cc[nf][2] * ev1, cc[nf][3] * ev1);
        }
    }
}

// ---------------- kernel B: scan over chunk states (k-split, fp16 I/O) -----
__global__ void __launch_bounds__(512) chunkscan_kernel() {
    int ks = blockIdx.x;
    int bh = blockIdx.y;
    int b = bh >> 4, h = bh & 15;
    int tid = threadIdx.x;
    int v = tid >> 3;
    int k = ks * 16 + (tid & 7) * 2;
    float2 S = make_float2(0.f, 0.f);

    for (int c = 0; c < NCH; c++) {
        size_t base = (((size_t)(bh * NCH + c)) << 12) + ((size_t)v << 6) + k;
        *(__half2*)(g_Sh + base) = __floats2half2_rn(S.x, S.y);
        float E = __half2float(g_expDh[((size_t)(b * LSEQ + c * CT + 63)) * HIDK + h * HDIM + v]);
        float2 p = __half22float2(*(__half2*)(g_Ph + base));
        S.x = fmaf(S.x, E, p.x);
        S.y = fmaf(S.y, E, p.y);
    }
}

// ---------------- kernel C: inter-chunk output — fp16 tensor cores ---------
__global__ void __launch_bounds__(256) inter_kernel() {
    __shared__ __align__(16) __half sQ[64 * PDH];
    __shared__ __align__(16) __half sS[64 * PDH];
    int c = blockIdx.x, bh = blockIdx.y;
    int b = bh >> 4, h = bh & 15;
    int tid = threadIdx.x;
    size_t rowbase = (size_t)(b * LSEQ + c * CT) * HIDK + h * HDIM;
    size_t sbase = ((size_t)(bh * NCH + c)) << 12;
    uint32_t Qb = smem_u32(sQ), Sb = smem_u32(sS);

#pragma unroll
    for (int i = 0; i < 2; i++) {
        int idx = tid + i * 256;
        int t = idx >> 3, c8 = (idx & 7) << 3;
        *(uint4*)&sQ[t * PDH + c8] = *(const uint4*)(g_qh16 + rowbase + (size_t)t * HIDK + c8);
        *(uint4*)&sS[t * PDH + c8] = *(const uint4*)(g_Sh + sbase + ((size_t)t << 6) + c8);
    }
    __syncthreads();

    int w = tid >> 5, l = tid & 31;
    int m0 = (w & 3) << 4, n0h = (w >> 2) << 5;
    int lr2 = l >> 2, lc2 = (l & 3) << 1;

    float cc[4][4];
#pragma unroll
    for (int i = 0; i < 4; i++)
#pragma unroll
        for (int j = 0; j < 4; j++) cc[i][j] = 0.f;
#pragma unroll
    for (int k0 = 0; k0 < 64; k0 += 16) {
        uint32_t a[4], b0[4], b1[4];
        ldmx4(a[0], a[1], a[2], a[3],
              Qb + ((m0 + (l & 15)) * PDH + k0 + ((l & 16) ? 8 : 0)) * 2);
        ldmx4(b0[0], b0[1], b0[2], b0[3],
              Sb + ((n0h + (l & 7) + ((l & 16) ? 8 : 0)) * PDH + k0 + ((l & 8) ? 8 : 0)) * 2);
        ldmx4(b1[0], b1[1], b1[2], b1[3],
              Sb + ((n0h + 16 + (l & 7) + ((l & 16) ? 8 : 0)) * PDH + k0 + ((l & 8) ? 8 : 0)) * 2);
        mma16816(cc[0], a, &b0[0]);
        mma16816(cc[1], a, &b0[2]);
        mma16816(cc[2], a, &b1[0]);
        mma16816(cc[3], a, &b1[2]);
    }
    int tr = m0 + lr2;
#pragma unroll
    for (int nf = 0; nf < 4; nf++) {
        int v = n0h + nf * 8 + lc2;
        size_t gi0 = rowbase + (size_t)tr * HIDK + v;
        float2 e0 = __half22float2(*(__half2*)(g_expDh + gi0));
        float2 i0 = __half22float2(*(__half2*)(g_atth + gi0));
        *(__half2*)(g_attf + gi0) =
            __floats2half2_rn(fmaf(cc[nf][0], e0.x, i0.x), fmaf(cc[nf][1], e0.y, i0.y));
        size_t gi1 = rowbase + (size_t)(tr + 8) * HIDK + v;
        float2 e1 = __half22float2(*(__half2*)(g_expDh + gi1));
        float2 i1 = __half22float2(*(__half2*)(g_atth + gi1));
        *(__half2*)(g_attf + gi1) =
            __floats2half2_rn(fmaf(cc[nf][2], e1.x, i1.x), fmaf(cc[nf][3], e1.y, i1.y));
    }
}

// ---------------- LayerNorm + SiLU gate -> fp16 y ----------------
__global__ void __launch_bounds__(256) ln_gate_kernel(const float* __restrict__ gamma,
                                                      const float* __restrict__ beta) {
    int row = blockIdx.x;
    int tid = threadIdx.x;
    const __half* a = g_attf + (size_t)row * HIDK;
    float vals[4];
    float s = 0.f, s2 = 0.f;
#pragma unroll
    for (int i = 0; i < 4; i++) {
        vals[i] = __half2float(a[i * 256 + tid]);
        s += vals[i];
        s2 = fmaf(vals[i], vals[i], s2);
    }
#pragma unroll
    for (int o = 16; o; o >>= 1) {
        s += __shfl_xor_sync(0xffffffffu, s, o);
        s2 += __shfl_xor_sync(0xffffffffu, s2, o);
    }
    __shared__ float rs[8], rs2[8];
    int warp = tid >> 5;
    if ((tid & 31) == 0) { rs[warp] = s; rs2[warp] = s2; }
    __syncthreads();
    s = 0.f;
    s2 = 0.f;
#pragma unroll
    for (int w = 0; w < 8; w++) { s += rs[w]; s2 += rs2[w]; }
    float mean = s * (1.f / HIDK);
    float var = s2 * (1.f / HIDK) - mean * mean;
    float rstd = rsqrtf(var + 1e-5f);
#pragma unroll
    for (int i = 0; i < 4; i++) {
        int col = i * 256 + tid;
        float gv = g_xg[(size_t)row * HIDK + col];
        float sil = gv / (1.f + __expf(-gv));
        float yv = ((vals[i] - mean) * rstd * gamma[col] + beta[col]) * sil;
        g_yh[(size_t)row * HIDK + col] = __float2half(yv);
    }
}

// ---------------- launch --------------------------------------------------
extern "C" void kernel_launch(void* const* d_in, const int* in_sizes, int n_in,
                              void* d_out, int out_size) {
    const float* x = (const float*)d_in[0];
    const float* Wq = (const float*)d_in[1];
    const float* Wk = (const float*)d_in[2];
    const float* Wv = (const float*)d_in[3];
    const float* Wg = (const float*)d_in[4];
    const float* Wgk1 = (const float*)d_in[5];
    const float* Wgk2 = (const float*)d_in[6];
    const float* bgk2 = (const float*)d_in[7];
    const float* gamma = (const float*)d_in[8];
    const float* beta = (const float*)d_in[9];
    const float* Wout = (const float*)d_in[10];
    float* out = (float*)d_out;

    cudaFuncSetAttribute(chunk_kernel, cudaFuncAttributeMaxDynamicSharedMemorySize, SMEM_CH);
    cudaFuncSetAttribute(mmproj_kernel, cudaFuncAttributeMaxDynamicSharedMemorySize, SMEM_MM);
    cudaFuncSetAttribute(mmout_kernel, cudaFuncAttributeMaxDynamicSharedMemorySize, SMEM_MM);
    cudaFuncSetAttribute(lr_fused_kernel, cudaFuncAttributeMaxDynamicSharedMemorySize, SMEM_LR);

    wconv_kernel<<<dim3(32, 32, 5), 256>>>(Wq, Wk, Wv, Wg, Wout);
    lr_fused_kernel<<<MTOK / 16, 256, SMEM_LR>>>(x, Wgk1, Wgk2, bgk2);

    mmproj_kernel<<<dim3(8, 32, 4), 256, SMEM_MM>>>();

    chunk_kernel<<<dim3(NCH, 32), 256, SMEM_CH>>>();
    chunkscan_kernel<<<dim3(4, 32), 512>>>();
    inter_kernel<<<dim3(NCH, 32), 256>>>();
    ln_gate_kernel<<<MTOK, 256>>>(gamma, beta);

    mmout_kernel<<<dim3(8, 32, 1), 256, SMEM_MM>>>(out);
}

// round 15
// speedup vs baseline: 1.9149x; 1.0370x over previous
#include <cuda_runtime.h>
#include <cuda_fp16.h>
#include <math.h>
#include <stdint.h>

#define HIDK 1024
#define MTOK 4096
#define LSEQ 2048
#define NHEAD 16
#define HDIM 64
#define CT 64
#define NCH (LSEQ / CT)
#define PD 68
#define PDH 72

// ---------------- scratch (device globals; no allocations) ----------------
__device__ __align__(16) __half g_xgh[MTOK * HIDK];       // gate pre-activation (fp16)
__device__ __align__(16) __half g_attf[MTOK * HIDK];      // final o (fp16)
__device__ __align__(16) __half g_qh16[MTOK * HIDK];
__device__ __align__(16) __half g_kh16[MTOK * HIDK];
__device__ __align__(16) __half g_vh16[MTOK * HIDK];
__device__ __align__(16) __half g_gkh[MTOK * HIDK];
__device__ __align__(16) __half g_expDh[MTOK * HIDK];
__device__ __align__(16) __half g_atth[MTOK * HIDK];      // intra-chunk o
__device__ __align__(16) __half g_Ph[32 * NCH * HDIM * HDIM];
__device__ __align__(16) __half g_Sh[32 * NCH * HDIM * HDIM];
// fp16 GEMM operands (single-product everywhere)
__device__ __align__(16) __half g_xh[MTOK * HIDK];
__device__ __align__(16) __half g_yh[MTOK * HIDK];
__device__ __align__(16) __half g_wh[5 * HIDK * HIDK];

// ======================= helpers =======================
__device__ __forceinline__ uint32_t smem_u32(const void* p) {
    uint32_t a;
    asm("{ .reg .u64 t; cvta.to.shared.u64 t, %1; cvt.u32.u64 %0, t; }" : "=r"(a) : "l"(p));
    return a;
}
__device__ __forceinline__ void cpasync16(uint32_t s, const void* g) {
    asm volatile("cp.async.cg.shared.global [%0], [%1], 16;" ::"r"(s), "l"(g));
}
__device__ __forceinline__ void cpcommit() { asm volatile("cp.async.commit_group;"); }

__device__ __forceinline__ void ldmx4(uint32_t& r0, uint32_t& r1, uint32_t& r2,
                                      uint32_t& r3, uint32_t addr) {
    asm volatile("ldmatrix.sync.aligned.m8n8.x4.shared.b16 {%0,%1,%2,%3}, [%4];"
                 : "=r"(r0), "=r"(r1), "=r"(r2), "=r"(r3)
                 : "r"(addr));
}
__device__ __forceinline__ void ldmx4t(uint32_t& r0, uint32_t& r1, uint32_t& r2,
                                       uint32_t& r3, uint32_t addr) {
    asm volatile("ldmatrix.sync.aligned.m8n8.x4.trans.shared.b16 {%0,%1,%2,%3}, [%4];"
                 : "=r"(r0), "=r"(r1), "=r"(r2), "=r"(r3)
                 : "r"(addr));
}
__device__ __forceinline__ void mma16816(float* c, const uint32_t* a, const uint32_t* b) {
    asm volatile(
        "mma.sync.aligned.m16n8k16.row.col.f32.f16.f16.f32 "
        "{%0,%1,%2,%3}, {%4,%5,%6,%7}, {%8,%9}, {%0,%1,%2,%3};"
        : "+f"(c[0]), "+f"(c[1]), "+f"(c[2]), "+f"(c[3])
        : "r"(a[0]), "r"(a[1]), "r"(a[2]), "r"(a[3]), "r"(b[0]), "r"(b[1]));
}

// ======================= fp16 mma.sync big GEMM (BK=64, 3-stage) ============
#define ROWB2 144                 // 64 fp16 (128B) + 16B pad
#define BLK2 (128 * ROWB2)        // 18432 bytes per operand block
#define STG2 (2 * BLK2)           // 36864 bytes per stage
#define NSTG2 3
#define SMEM_MM (NSTG2 * STG2)    // 110592 bytes
#define NSTAGES 16                // 1024 / 64

__device__ __forceinline__ void mm_issue(int s, uint32_t sb, int tid,
                                         int brow, int bcol,
                                         const __half* A, const __half* B) {
    if (s < NSTAGES) {
        int kk = s << 6;
        uint32_t st = sb + (uint32_t)(s % NSTG2) * STG2;
        int row0 = tid >> 3, cw = tid & 7;
        uint32_t so = row0 * ROWB2 + cw * 16;
        size_t go = (size_t)(brow + row0) * HIDK + kk + cw * 8;
#pragma unroll
        for (int p = 0; p < 4; p++)
            cpasync16(st + so + p * 32 * ROWB2, A + go + (size_t)p * 32 * HIDK);
        size_t gob = (size_t)(bcol + row0) * HIDK + kk + cw * 8;
#pragma unroll
        for (int p = 0; p < 4; p++)
            cpasync16(st + BLK2 + so + p * 32 * ROWB2, B + gob + (size_t)p * 32 * HIDK);
    }
    cpcommit();
}

__device__ __forceinline__ void mma_gemm_body(const __half* __restrict__ A,
                                              const __half* __restrict__ B,
                                              void* __restrict__ Cv, bool half_out) {
    extern __shared__ char sm_raw[];
    uint32_t sb = smem_u32(sm_raw);
    int tid = threadIdx.x, lane = tid & 31, wid = tid >> 5;
    int wm = wid & 3, wn = wid >> 2;
    int brow = blockIdx.y * 128, bcol = blockIdx.x * 128;

    float c[2][8][4];
#pragma unroll
    for (int i = 0; i < 2; i++)
#pragma unroll
        for (int j = 0; j < 8; j++)
#pragma unroll
            for (int l = 0; l < 4; l++) c[i][j][l] = 0.f;

    mm_issue(0, sb, tid, brow, bcol, A, B);
    mm_issue(1, sb, tid, brow, bcol, A, B);

    int q = lane >> 3, r = lane & 7;

    for (int s = 0; s < NSTAGES; s++) {
        asm volatile("cp.async.wait_group 1;" ::: "memory");
        __syncthreads();
        uint32_t st = sb + (uint32_t)(s % NSTG2) * STG2;
        uint32_t sA = st, sB = st + BLK2;
#pragma unroll
        for (int k0 = 0; k0 < 64; k0 += 16) {
            uint32_t a[2][4], b[8][2];
#pragma unroll
            for (int mf = 0; mf < 2; mf++) {
                int rrow = wm * 32 + mf * 16 + (q & 1) * 8 + r;
                int kc = k0 + (q >> 1) * 8;
                ldmx4(a[mf][0], a[mf][1], a[mf][2], a[mf][3], sA + rrow * ROWB2 + kc * 2);
            }
#pragma unroll
            for (int pb = 0; pb < 4; pb++) {
                int nrow = wn * 64 + pb * 16 + (q >> 1) * 8 + r;
                int kc = k0 + (q & 1) * 8;
                uint32_t r0, r1, r2, r3;
                ldmx4(r0, r1, r2, r3, sB + nrow * ROWB2 + kc * 2);
                b[pb * 2][0] = r0;
                b[pb * 2][1] = r1;
                b[pb * 2 + 1][0] = r2;
                b[pb * 2 + 1][1] = r3;
            }
#pragma unroll
            for (int mf = 0; mf < 2; mf++)
#pragma unroll
                for (int nf = 0; nf < 8; nf++) mma16816(c[mf][nf], a[mf], b[nf]);
        }
        mm_issue(s + 2, sb, tid, brow, bcol, A, B);
    }

    int qr = lane >> 2, qc = lane & 3;
    if (half_out) {
        __half* Ch = (__half*)Cv;
#pragma unroll
        for (int mf = 0; mf < 2; mf++)
#pragma unroll
            for (int nf = 0; nf < 8; nf++) {
                int row0 = brow + wm * 32 + mf * 16 + qr;
                int col = bcol + wn * 64 + nf * 8 + qc * 2;
                *(__half2*)&Ch[(size_t)row0 * HIDK + col] =
                    __floats2half2_rn(c[mf][nf][0], c[mf][nf][1]);
                *(__half2*)&Ch[(size_t)(row0 + 8) * HIDK + col] =
                    __floats2half2_rn(c[mf][nf][2], c[mf][nf][3]);
            }
    } else {
        float* Cf = (float*)Cv;
#pragma unroll
        for (int mf = 0; mf < 2; mf++)
#pragma unroll
            for (int nf = 0; nf < 8; nf++) {
                int row0 = brow + wm * 32 + mf * 16 + qr;
                int col = bcol + wn * 64 + nf * 8 + qc * 2;
                *(float2*)&Cf[(size_t)row0 * HIDK + col] =
                    make_float2(c[mf][nf][0], c[mf][nf][1]);
                *(float2*)&Cf[(size_t)(row0 + 8) * HIDK + col] =
                    make_float2(c[mf][nf][2], c[mf][nf][3]);
            }
    }
}

__global__ void __launch_bounds__(256, 2) mmproj_kernel() {
    int z = blockIdx.z;
    const __half* B = g_wh + (size_t)z * HIDK * HIDK;
    void* C;
    switch (z) {
        case 0: C = g_qh16; break;
        case 1: C = g_kh16; break;
        case 2: C = g_vh16; break;
        default: C = g_xgh; break;
    }
    mma_gemm_body(g_xh, B, C, true);
}
__global__ void __launch_bounds__(256, 2) mmout_kernel(float* __restrict__ out) {
    mma_gemm_body(g_yh, g_wh + (size_t)4 * HIDK * HIDK, out, false);
}

// ======================= weight conversion (hi only) =====================
__global__ void __launch_bounds__(256) wconv_kernel(const float* __restrict__ W0,
                                                    const float* __restrict__ W1,
                                                    const float* __restrict__ W2,
                                                    const float* __restrict__ W3,
                                                    const float* __restrict__ W4) {
    int z = blockIdx.z;
    const float* W = (z == 0) ? W0 : (z == 1) ? W1 : (z == 2) ? W2 : (z == 3) ? W3 : W4;
    __half* Th = g_wh + (size_t)z * HIDK * HIDK;
    __shared__ float t[32][33];
    int n0 = blockIdx.x * 32, k0 = blockIdx.y * 32;
    int lx = threadIdx.x & 31, ly = threadIdx.x >> 5;
#pragma unroll
    for (int i = 0; i < 4; i++) {
        int r = ly + i * 8;
        t[r][lx] = W[(size_t)(k0 + r) * HIDK + n0 + lx];
    }
    __syncthreads();
#pragma unroll
    for (int i = 0; i < 4; i++) {
        int r = ly + i * 8;
        Th[(size_t)(n0 + r) * HIDK + k0 + lx] = __float2half(t[lx][r]);
    }
}

// ---------------- fused x-convert + low-rank gate path ----------------------
#define SMEM_LR (32 * 1024 * sizeof(float))
__global__ void __launch_bounds__(256) lr_fused_kernel(const float* __restrict__ x,
                                                       const float* __restrict__ W1,
                                                       const float* __restrict__ W2,
                                                       const float* __restrict__ bias) {
    extern __shared__ float s[];
    float* w1s = s;
    float* w2s = s + 16384;
    __shared__ float ts[16][17];
    int tid = threadIdx.x;
    int m0 = blockIdx.x * 16;

#pragma unroll
    for (int i = 0; i < 16; i++) {
        int idx = tid + i * 256;
        ((float4*)w1s)[idx] = ((const float4*)W1)[idx];
        ((float4*)w2s)[idx] = ((const float4*)W2)[idx];
        float4 v = ((const float4*)x)[(size_t)m0 * (HIDK / 4) + idx];
        size_t eo = (size_t)m0 * HIDK + (size_t)idx * 4;
        *(__half2*)&g_xh[eo] = __floats2half2_rn(v.x, v.y);
        *(__half2*)&g_xh[eo + 2] = __floats2half2_rn(v.z, v.w);
    }
    __syncthreads();

    {
        int mt = tid >> 4, r = tid & 15;
        const float4* xr4 = (const float4*)(x + (size_t)(m0 + mt) * HIDK);
        float acc = 0.f;
#pragma unroll 4
        for (int k4 = 0; k4 < 256; k4++) {
            float4 xv = xr4[k4];
            int kb = k4 * 4;
            acc = fmaf(xv.x, w1s[(kb + 0) * 16 + r], acc);
            acc = fmaf(xv.y, w1s[(kb + 1) * 16 + r], acc);
            acc = fmaf(xv.z, w1s[(kb + 2) * 16 + r], acc);
            acc = fmaf(xv.w, w1s[(kb + 3) * 16 + r], acc);
        }
        ts[mt][r] = acc;
    }
    __syncthreads();

    int n = tid * 4;
    float4 b4 = *(const float4*)(bias + n);
#pragma unroll 1
    for (int mi = 0; mi < 16; mi++) {
        float4 a = b4;
#pragma unroll
        for (int rr = 0; rr < 16; rr++) {
            float tv = ts[mi][rr];
            float4 w = *(float4*)&w2s[rr * 1024 + n];
            a.x = fmaf(tv, w.x, a.x);
            a.y = fmaf(tv, w.y, a.y);
            a.z = fmaf(tv, w.z, a.z);
            a.w = fmaf(tv, w.w, a.w);
        }
        float ox = (fminf(a.x, 0.f) - __logf(1.f + __expf(-fabsf(a.x)))) * 0.0625f;
        float oy = (fminf(a.y, 0.f) - __logf(1.f + __expf(-fabsf(a.y)))) * 0.0625f;
        float oz = (fminf(a.z, 0.f) - __logf(1.f + __expf(-fabsf(a.z)))) * 0.0625f;
        float ow = (fminf(a.w, 0.f) - __logf(1.f + __expf(-fabsf(a.w)))) * 0.0625f;
        size_t go = (size_t)(m0 + mi) * HIDK + n;
        *(__half2*)&g_gkh[go] = __floats2half2_rn(ox, oy);
        *(__half2*)&g_gkh[go + 2] = __floats2half2_rn(oz, ow);
    }
}

// ---------------- chunked GLA: kernel A — fp16 tensor cores -----------------
// smem: sGf fp32 [64][68]; Qh/Kh/Uh/Ah fp16 [64][72] (V staged in Uh, converted in place)
#define OFF_Q 17408
#define OFF_K 26624
#define OFF_U 35840
#define OFF_A 45056
#define SMEM_CH 54272

__global__ void __launch_bounds__(256) chunk_kernel() {
    extern __shared__ char smc[];
    float* sGf = (float*)smc;
    uint32_t sb = smem_u32(smc);
    uint32_t Qb = sb + OFF_Q, Kb = sb + OFF_K, Ub = sb + OFF_U, Ab = sb + OFF_A;
    __half* QhP = (__half*)(smc + OFF_Q);
    __half* KhP = (__half*)(smc + OFF_K);
    __half* UhP = (__half*)(smc + OFF_U);
    __half* AhP = (__half*)(smc + OFF_A);
    __shared__ float sTot[4][64];

    int c = blockIdx.x, bh = blockIdx.y;
    int b = bh >> 4, h = bh & 15;
    int tid = threadIdx.x;
    size_t rowbase = (size_t)(b * LSEQ + c * CT) * HIDK + h * HDIM;

#pragma unroll
    for (int i = 0; i < 2; i++) {
        int idx = tid + i * 256;
        int t = idx >> 3, c8 = (idx & 7) << 3;
        size_t gi = rowbase + (size_t)t * HIDK + c8;
        *(uint4*)&QhP[t * PDH + c8] = *(const uint4*)(g_qh16 + gi);
        *(uint4*)&KhP[t * PDH + c8] = *(const uint4*)(g_kh16 + gi);
        *(uint4*)&UhP[t * PDH + c8] = *(const uint4*)(g_vh16 + gi);
        uint4 gg4 = *(const uint4*)(g_gkh + gi);
        const __half2* gh = (const __half2*)&gg4;
        float* dst = &sGf[t * PD + c8];
        float2 a0 = __half22float2(gh[0]);
        float2 a1 = __half22float2(gh[1]);
        float2 a2 = __half22float2(gh[2]);
        float2 a3 = __half22float2(gh[3]);
        dst[0] = a0.x; dst[1] = a0.y; dst[2] = a1.x; dst[3] = a1.y;
        dst[4] = a2.x; dst[5] = a2.y; dst[6] = a3.x; dst[7] = a3.y;
    }
    __syncthreads();

    {
        int ch = tid & 63, seg = tid >> 6;
        int t0s = seg * 16;
        float run = 0.f;
#pragma unroll
        for (int t = t0s; t < t0s + 16; t++) {
            run += sGf[t * PD + ch];
            sGf[t * PD + ch] = run;
        }
        sTot[seg][ch] = run;
    }
    __syncthreads();
    {
        int ch = tid & 63, seg = tid >> 6;
        float off = 0.f;
        if (seg > 0) off += sTot[0][ch];
        if (seg > 1) off += sTot[1][ch];
        if (seg > 2) off += sTot[2][ch];
        int t0s = seg * 16;
#pragma unroll
        for (int t = t0s; t < t0s + 16; t++) {
            float D = sGf[t * PD + ch] + off;
            sGf[t * PD + ch] = __expf(D);
            UhP[t * PDH + ch] = __float2half(__expf(-D) * __half2float(UhP[t * PDH + ch]));
        }
    }
    __syncthreads();

#pragma unroll
    for (int i = 0; i < 2; i++) {
        int idx = tid + i * 256;
        int t = idx >> 3, c8 = (idx & 7) << 3;
        __half h8[8];
#pragma unroll
        for (int j = 0; j < 8; j++) h8[j] = __float2half(sGf[t * PD + c8 + j]);
        *(uint4*)(g_expDh + rowbase + (size_t)t * HIDK + c8) = *(uint4*)h8;
    }

    int w = tid >> 5, l = tid & 31;
    int m0 = (w & 3) << 4, n0h = (w >> 2) << 5;
    int lr2 = l >> 2, lc2 = (l & 3) << 1;

    // GEMM1: A = Q.K^T masked -> fp16
    {
        float cc[4][4];
#pragma unroll
        for (int i = 0; i < 4; i++)
#pragma unroll
            for (int j = 0; j < 4; j++) cc[i][j] = 0.f;
#pragma unroll
        for (int k0 = 0; k0 < 64; k0 += 16) {
            uint32_t a[4], b0[4], b1[4];
            ldmx4(a[0], a[1], a[2], a[3],
                  Qb + ((m0 + (l & 15)) * PDH + k0 + ((l & 16) ? 8 : 0)) * 2);
            ldmx4(b0[0], b0[1], b0[2], b0[3],
                  Kb + ((n0h + (l & 7) + ((l & 16) ? 8 : 0)) * PDH + k0 + ((l & 8) ? 8 : 0)) * 2);
            ldmx4(b1[0], b1[1], b1[2], b1[3],
                  Kb + ((n0h + 16 + (l & 7) + ((l & 16) ? 8 : 0)) * PDH + k0 + ((l & 8) ? 8 : 0)) * 2);
            mma16816(cc[0], a, &b0[0]);
            mma16816(cc[1], a, &b0[2]);
            mma16816(cc[2], a, &b1[0]);
            mma16816(cc[3], a, &b1[2]);
        }
        int tr = m0 + lr2;
#pragma unroll
        for (int nf = 0; nf < 4; nf++) {
            int sc = n0h + nf * 8 + lc2;
            *(__half2*)&AhP[tr * PDH + sc] = __halves2half2(
                __float2half(sc <= tr ? cc[nf][0] : 0.f),
                __float2half(sc + 1 <= tr ? cc[nf][1] : 0.f));
            int tr2 = tr + 8;
            *(__half2*)&AhP[tr2 * PDH + sc] = __halves2half2(
                __float2half(sc <= tr2 ? cc[nf][2] : 0.f),
                __float2half(sc + 1 <= tr2 ? cc[nf][3] : 0.f));
        }
    }
    __syncthreads();

    // GEMM2: o_intra = A'.U; scale expD; store fp16
    {
        float cc[4][4];
#pragma unroll
        for (int i = 0; i < 4; i++)
#pragma unroll
            for (int j = 0; j < 4; j++) cc[i][j] = 0.f;
#pragma unroll
        for (int s0 = 0; s0 < 64; s0 += 16) {
            uint32_t a[4], b0[4], b1[4];
            ldmx4(a[0], a[1], a[2], a[3],
                  Ab + ((m0 + (l & 15)) * PDH + s0 + ((l & 16) ? 8 : 0)) * 2);
            ldmx4t(b0[0], b0[1], b0[2], b0[3],
                   Ub + ((s0 + (l & 15)) * PDH + n0h + ((l & 16) ? 8 : 0)) * 2);
            ldmx4t(b1[0], b1[1], b1[2], b1[3],
                   Ub + ((s0 + (l & 15)) * PDH + n0h + 16 + ((l & 16) ? 8 : 0)) * 2);
            mma16816(cc[0], a, &b0[0]);
            mma16816(cc[1], a, &b0[2]);
            mma16816(cc[2], a, &b1[0]);
            mma16816(cc[3], a, &b1[2]);
        }
        int tr = m0 + lr2;
#pragma unroll
        for (int nf = 0; nf < 4; nf++) {
            int v = n0h + nf * 8 + lc2;
            float2 e0 = *(float2*)&sGf[tr * PD + v];
            *(__half2*)&g_atth[rowbase + (size_t)tr * HIDK + v] =
                __floats2half2_rn(cc[nf][0] * e0.x, cc[nf][1] * e0.y);
            float2 e1 = *(float2*)&sGf[(tr + 8) * PD + v];
            *(__half2*)&g_atth[rowbase + (size_t)(tr + 8) * HIDK + v] =
                __floats2half2_rn(cc[nf][2] * e1.x, cc[nf][3] * e1.y);
        }
    }

    // GEMM3: P = U^T.K; scale expD_end; store fp16
    {
        float cc[4][4];
#pragma unroll
        for (int i = 0; i < 4; i++)
#pragma unroll
            for (int j = 0; j < 4; j++) cc[i][j] = 0.f;
#pragma unroll
        for (int s0 = 0; s0 < 64; s0 += 16) {
            uint32_t a[4], b0[4], b1[4];
            ldmx4t(a[0], a[1], a[2], a[3],
                   Ub + ((s0 + (l & 7) + ((l & 16) ? 8 : 0)) * PDH + m0 + ((l & 8) ? 8 : 0)) * 2);
            ldmx4t(b0[0], b0[1], b0[2], b0[3],
                   Kb + ((s0 + (l & 15)) * PDH + n0h + ((l & 16) ? 8 : 0)) * 2);
            ldmx4t(b1[0], b1[1], b1[2], b1[3],
                   Kb + ((s0 + (l & 15)) * PDH + n0h + 16 + ((l & 16) ? 8 : 0)) * 2);
            mma16816(cc[0], a, &b0[0]);
            mma16816(cc[1], a, &b0[2]);
            mma16816(cc[2], a, &b1[0]);
            mma16816(cc[3], a, &b1[2]);
        }
        size_t pbase = ((size_t)(bh * NCH + c)) << 12;
        int vr = m0 + lr2;
        float ev0 = sGf[63 * PD + vr];
        float ev1 = sGf[63 * PD + vr + 8];
#pragma unroll
        for (int nf = 0; nf < 4; nf++) {
            int kd = n0h + nf * 8 + lc2;
            *(__half2*)&g_Ph[pbase + ((size_t)vr << 6) + kd] =
                __floats2half2_rn(cc[nf][0] * ev0, cc[nf][1] * ev0);
            *(__half2*)&g_Ph[pbase + ((size_t)(vr + 8) << 6) + kd] =
                __floats2half2_rn(cc[nf][2] * ev1, cc[nf][3] * ev1);
        }
    }
}

// ---------------- kernel B: scan over chunk states (pipelined loads) -------
__global__ void __launch_bounds__(512) chunkscan_kernel() {
    int ks = blockIdx.x;
    int bh = blockIdx.y;
    int b = bh >> 4, h = bh & 15;
    int tid = threadIdx.x;
    int v = tid >> 3;
    int k = ks * 16 + (tid & 7) * 2;
    float2 S = make_float2(0.f, 0.f);

    size_t base0 = (((size_t)(bh * NCH)) << 12) + ((size_t)v << 6) + k;
    float2 p = __half22float2(*(__half2*)(g_Ph + base0));
    float E = __half2float(g_expDh[((size_t)(b * LSEQ + 63)) * HIDK + h * HDIM + v]);

    for (int c = 0; c < NCH; c++) {
        size_t base = (((size_t)(bh * NCH + c)) << 12) + ((size_t)v << 6) + k;
        *(__half2*)(g_Sh + base) = __floats2half2_rn(S.x, S.y);
        float2 pn;
        float En;
        if (c + 1 < NCH) {
            size_t basen = base + 4096;
            pn = __half22float2(*(__half2*)(g_Ph + basen));
            En = __half2float(
                g_expDh[((size_t)(b * LSEQ + (c + 1) * CT + 63)) * HIDK + h * HDIM + v]);
        }
        S.x = fmaf(S.x, E, p.x);
        S.y = fmaf(S.y, E, p.y);
        p = pn;
        E = En;
    }
}

// ---------------- kernel C: inter-chunk output — fp16 tensor cores ---------
__global__ void __launch_bounds__(256) inter_kernel() {
    __shared__ __align__(16) __half sQ[64 * PDH];
    __shared__ __align__(16) __half sS[64 * PDH];
    int c = blockIdx.x, bh = blockIdx.y;
    int b = bh >> 4, h = bh & 15;
    int tid = threadIdx.x;
    size_t rowbase = (size_t)(b * LSEQ + c * CT) * HIDK + h * HDIM;
    size_t sbase = ((size_t)(bh * NCH + c)) << 12;
    uint32_t Qb = smem_u32(sQ), Sb = smem_u32(sS);

#pragma unroll
    for (int i = 0; i < 2; i++) {
        int idx = tid + i * 256;
        int t = idx >> 3, c8 = (idx & 7) << 3;
        *(uint4*)&sQ[t * PDH + c8] = *(const uint4*)(g_qh16 + rowbase + (size_t)t * HIDK + c8);
        *(uint4*)&sS[t * PDH + c8] = *(const uint4*)(g_Sh + sbase + ((size_t)t << 6) + c8);
    }
    __syncthreads();

    int w = tid >> 5, l = tid & 31;
    int m0 = (w & 3) << 4, n0h = (w >> 2) << 5;
    int lr2 = l >> 2, lc2 = (l & 3) << 1;

    float cc[4][4];
#pragma unroll
    for (int i = 0; i < 4; i++)
#pragma unroll
        for (int j = 0; j < 4; j++) cc[i][j] = 0.f;
#pragma unroll
    for (int k0 = 0; k0 < 64; k0 += 16) {
        uint32_t a[4], b0[4], b1[4];
        ldmx4(a[0], a[1], a[2], a[3],
              Qb + ((m0 + (l & 15)) * PDH + k0 + ((l & 16) ? 8 : 0)) * 2);
        ldmx4(b0[0], b0[1], b0[2], b0[3],
              Sb + ((n0h + (l & 7) + ((l & 16) ? 8 : 0)) * PDH + k0 + ((l & 8) ? 8 : 0)) * 2);
        ldmx4(b1[0], b1[1], b1[2], b1[3],
              Sb + ((n0h + 16 + (l & 7) + ((l & 16) ? 8 : 0)) * PDH + k0 + ((l & 8) ? 8 : 0)) * 2);
        mma16816(cc[0], a, &b0[0]);
        mma16816(cc[1], a, &b0[2]);
        mma16816(cc[2], a, &b1[0]);
        mma16816(cc[3], a, &b1[2]);
    }
    int tr = m0 + lr2;
#pragma unroll
    for (int nf = 0; nf < 4; nf++) {
        int v = n0h + nf * 8 + lc2;
        size_t gi0 = rowbase + (size_t)tr * HIDK + v;
        float2 e0 = __half22float2(*(__half2*)(g_expDh + gi0));
        float2 i0 = __half22float2(*(__half2*)(g_atth + gi0));
        *(__half2*)(g_attf + gi0) =
            __floats2half2_rn(fmaf(cc[nf][0], e0.x, i0.x), fmaf(cc[nf][1], e0.y, i0.y));
        size_t gi1 = rowbase + (size_t)(tr + 8) * HIDK + v;
        float2 e1 = __half22float2(*(__half2*)(g_expDh + gi1));
        float2 i1 = __half22float2(*(__half2*)(g_atth + gi1));
        *(__half2*)(g_attf + gi1) =
            __floats2half2_rn(fmaf(cc[nf][2], e1.x, i1.x), fmaf(cc[nf][3], e1.y, i1.y));
    }
}

// ---------------- LayerNorm + SiLU gate -> fp16 y (vectorized) --------------
__global__ void __launch_bounds__(256) ln_gate_kernel(const float* __restrict__ gamma,
                                                      const float* __restrict__ beta) {
    int row = blockIdx.x;
    int tid = threadIdx.x;
    int col0 = tid * 4;
    size_t rb = (size_t)row * HIDK;

    // 4 contiguous fp16 per thread: one 8B load
    uint2 av = *(const uint2*)(g_attf + rb + col0);
    const __half2* ah = (const __half2*)&av;
    float2 a01 = __half22float2(ah[0]);
    float2 a23 = __half22float2(ah[1]);
    float vals[4] = {a01.x, a01.y, a23.x, a23.y};

    float s = vals[0] + vals[1] + vals[2] + vals[3];
    float s2 = fmaf(vals[0], vals[0],
                    fmaf(vals[1], vals[1], fmaf(vals[2], vals[2], vals[3] * vals[3])));
#pragma unroll
    for (int o = 16; o; o >>= 1) {
        s += __shfl_xor_sync(0xffffffffu, s, o);
        s2 += __shfl_xor_sync(0xffffffffu, s2, o);
    }
    __shared__ float rs[8], rs2[8];
    int warp = tid >> 5;
    if ((tid & 31) == 0) { rs[warp] = s; rs2[warp] = s2; }
    __syncthreads();
    s = 0.f;
    s2 = 0.f;
#pragma unroll
    for (int w = 0; w < 8; w++) { s += rs[w]; s2 += rs2[w]; }
    float mean = s * (1.f / HIDK);
    float var = s2 * (1.f / HIDK) - mean * mean;
    float rstd = rsqrtf(var + 1e-5f);

    uint2 gv2 = *(const uint2*)(g_xgh + rb + col0);
    const __half2* gh = (const __half2*)&gv2;
    float2 g01 = __half22float2(gh[0]);
    float2 g23 = __half22float2(gh[1]);
    float gvs[4] = {g01.x, g01.y, g23.x, g23.y};

    float4 gm = *(const float4*)(gamma + col0);
    float4 bt = *(const float4*)(beta + col0);
    float gmv[4] = {gm.x, gm.y, gm.z, gm.w};
    float btv[4] = {bt.x, bt.y, bt.z, bt.w};

    __half yh4[4];
#pragma unroll
    for (int i = 0; i < 4; i++) {
        float sil = gvs[i] / (1.f + __expf(-gvs[i]));
        float yv = ((vals[i] - mean) * rstd * gmv[i] + btv[i]) * sil;
        yh4[i] = __float2half(yv);
    }
    *(uint2*)(g_yh + rb + col0) = *(uint2*)yh4;
}

// ---------------- launch --------------------------------------------------
extern "C" void kernel_launch(void* const* d_in, const int* in_sizes, int n_in,
                              void* d_out, int out_size) {
    const float* x = (const float*)d_in[0];
    const float* Wq = (const float*)d_in[1];
    const float* Wk = (const float*)d_in[2];
    const float* Wv = (const float*)d_in[3];
    const float* Wg = (const float*)d_in[4];
    const float* Wgk1 = (const float*)d_in[5];
    const float* Wgk2 = (const float*)d_in[6];
    const float* bgk2 = (const float*)d_in[7];
    const float* gamma = (const float*)d_in[8];
    const float* beta = (const float*)d_in[9];
    const float* Wout = (const float*)d_in[10];
    float* out = (float*)d_out;

    cudaFuncSetAttribute(chunk_kernel, cudaFuncAttributeMaxDynamicSharedMemorySize, SMEM_CH);
    cudaFuncSetAttribute(mmproj_kernel, cudaFuncAttributeMaxDynamicSharedMemorySize, SMEM_MM);
    cudaFuncSetAttribute(mmout_kernel, cudaFuncAttributeMaxDynamicSharedMemorySize, SMEM_MM);
    cudaFuncSetAttribute(lr_fused_kernel, cudaFuncAttributeMaxDynamicSharedMemorySize, SMEM_LR);

    wconv_kernel<<<dim3(32, 32, 5), 256>>>(Wq, Wk, Wv, Wg, Wout);
    lr_fused_kernel<<<MTOK / 16, 256, SMEM_LR>>>(x, Wgk1, Wgk2, bgk2);

    mmproj_kernel<<<dim3(8, 32, 4), 256, SMEM_MM>>>();

    chunk_kernel<<<dim3(NCH, 32), 256, SMEM_CH>>>();
    chunkscan_kernel<<<dim3(4, 32), 512>>>();
    inter_kernel<<<dim3(NCH, 32), 256>>>();
    ln_gate_kernel<<<MTOK, 256>>>(gamma, beta);

    mmout_kernel<<<dim3(8, 32, 1), 256, SMEM_MM>>>(out);
}

// round 16
// speedup vs baseline: 1.9492x; 1.0179x over previous
#include <cuda_runtime.h>
#include <cuda_fp16.h>
#include <math.h>
#include <stdint.h>

#define HIDK 1024
#define MTOK 4096
#define LSEQ 2048
#define NHEAD 16
#define HDIM 64
#define CT 64
#define NCH (LSEQ / CT)
#define PD 68
#define PDH 72

// ---------------- scratch (device globals; no allocations) ----------------
__device__ __align__(16) __half g_xgh[MTOK * HIDK];       // gate pre-activation (fp16)
__device__ __align__(16) __half g_attf[MTOK * HIDK];      // final o (fp16)
__device__ __align__(16) __half g_qh16[MTOK * HIDK];
__device__ __align__(16) __half g_kh16[MTOK * HIDK];
__device__ __align__(16) __half g_vh16[MTOK * HIDK];
__device__ __align__(16) __half g_gkh[MTOK * HIDK];
__device__ float g_lastE[32 * NCH * HDIM];                // expD at t=63 per (bh,c,v)
__device__ __align__(16) __half g_Ph[32 * NCH * HDIM * HDIM];
__device__ __align__(16) __half g_Sh[32 * NCH * HDIM * HDIM];
// fp16 GEMM operands (single-product everywhere)
__device__ __align__(16) __half g_xh[MTOK * HIDK];
__device__ __align__(16) __half g_yh[MTOK * HIDK];
__device__ __align__(16) __half g_wh[5 * HIDK * HIDK];

// ======================= helpers =======================
__device__ __forceinline__ uint32_t smem_u32(const void* p) {
    uint32_t a;
    asm("{ .reg .u64 t; cvta.to.shared.u64 t, %1; cvt.u32.u64 %0, t; }" : "=r"(a) : "l"(p));
    return a;
}
__device__ __forceinline__ void cpasync16(uint32_t s, const void* g) {
    asm volatile("cp.async.cg.shared.global [%0], [%1], 16;" ::"r"(s), "l"(g));
}
__device__ __forceinline__ void cpcommit() { asm volatile("cp.async.commit_group;"); }

__device__ __forceinline__ void ldmx4(uint32_t& r0, uint32_t& r1, uint32_t& r2,
                                      uint32_t& r3, uint32_t addr) {
    asm volatile("ldmatrix.sync.aligned.m8n8.x4.shared.b16 {%0,%1,%2,%3}, [%4];"
                 : "=r"(r0), "=r"(r1), "=r"(r2), "=r"(r3)
                 : "r"(addr));
}
__device__ __forceinline__ void ldmx4t(uint32_t& r0, uint32_t& r1, uint32_t& r2,
                                       uint32_t& r3, uint32_t addr) {
    asm volatile("ldmatrix.sync.aligned.m8n8.x4.trans.shared.b16 {%0,%1,%2,%3}, [%4];"
                 : "=r"(r0), "=r"(r1), "=r"(r2), "=r"(r3)
                 : "r"(addr));
}
__device__ __forceinline__ void mma16816(float* c, const uint32_t* a, const uint32_t* b) {
    asm volatile(
        "mma.sync.aligned.m16n8k16.row.col.f32.f16.f16.f32 "
        "{%0,%1,%2,%3}, {%4,%5,%6,%7}, {%8,%9}, {%0,%1,%2,%3};"
        : "+f"(c[0]), "+f"(c[1]), "+f"(c[2]), "+f"(c[3])
        : "r"(a[0]), "r"(a[1]), "r"(a[2]), "r"(a[3]), "r"(b[0]), "r"(b[1]));
}

// ======================= fp16 mma.sync big GEMM (BK=64, 3-stage) ============
#define ROWB2 144
#define BLK2 (128 * ROWB2)
#define STG2 (2 * BLK2)
#define NSTG2 3
#define SMEM_MM (NSTG2 * STG2)
#define NSTAGES 16

__device__ __forceinline__ void mm_issue(int s, uint32_t sb, int tid,
                                         int brow, int bcol,
                                         const __half* A, const __half* B) {
    if (s < NSTAGES) {
        int kk = s << 6;
        uint32_t st = sb + (uint32_t)(s % NSTG2) * STG2;
        int row0 = tid >> 3, cw = tid & 7;
        uint32_t so = row0 * ROWB2 + cw * 16;
        size_t go = (size_t)(brow + row0) * HIDK + kk + cw * 8;
#pragma unroll
        for (int p = 0; p < 4; p++)
            cpasync16(st + so + p * 32 * ROWB2, A + go + (size_t)p * 32 * HIDK);
        size_t gob = (size_t)(bcol + row0) * HIDK + kk + cw * 8;
#pragma unroll
        for (int p = 0; p < 4; p++)
            cpasync16(st + BLK2 + so + p * 32 * ROWB2, B + gob + (size_t)p * 32 * HIDK);
    }
    cpcommit();
}

__device__ __forceinline__ void mma_gemm_body(const __half* __restrict__ A,
                                              const __half* __restrict__ B,
                                              void* __restrict__ Cv, bool half_out) {
    extern __shared__ char sm_raw[];
    uint32_t sb = smem_u32(sm_raw);
    int tid = threadIdx.x, lane = tid & 31, wid = tid >> 5;
    int wm = wid & 3, wn = wid >> 2;
    int brow = blockIdx.y * 128, bcol = blockIdx.x * 128;

    float c[2][8][4];
#pragma unroll
    for (int i = 0; i < 2; i++)
#pragma unroll
        for (int j = 0; j < 8; j++)
#pragma unroll
            for (int l = 0; l < 4; l++) c[i][j][l] = 0.f;

    mm_issue(0, sb, tid, brow, bcol, A, B);
    mm_issue(1, sb, tid, brow, bcol, A, B);

    int q = lane >> 3, r = lane & 7;

    for (int s = 0; s < NSTAGES; s++) {
        asm volatile("cp.async.wait_group 1;" ::: "memory");
        __syncthreads();
        uint32_t st = sb + (uint32_t)(s % NSTG2) * STG2;
        uint32_t sA = st, sB = st + BLK2;
#pragma unroll
        for (int k0 = 0; k0 < 64; k0 += 16) {
            uint32_t a[2][4], b[8][2];
#pragma unroll
            for (int mf = 0; mf < 2; mf++) {
                int rrow = wm * 32 + mf * 16 + (q & 1) * 8 + r;
                int kc = k0 + (q >> 1) * 8;
                ldmx4(a[mf][0], a[mf][1], a[mf][2], a[mf][3], sA + rrow * ROWB2 + kc * 2);
            }
#pragma unroll
            for (int pb = 0; pb < 4; pb++) {
                int nrow = wn * 64 + pb * 16 + (q >> 1) * 8 + r;
                int kc = k0 + (q & 1) * 8;
                uint32_t r0, r1, r2, r3;
                ldmx4(r0, r1, r2, r3, sB + nrow * ROWB2 + kc * 2);
                b[pb * 2][0] = r0;
                b[pb * 2][1] = r1;
                b[pb * 2 + 1][0] = r2;
                b[pb * 2 + 1][1] = r3;
            }
#pragma unroll
            for (int mf = 0; mf < 2; mf++)
#pragma unroll
                for (int nf = 0; nf < 8; nf++) mma16816(c[mf][nf], a[mf], b[nf]);
        }
        mm_issue(s + 2, sb, tid, brow, bcol, A, B);
    }

    int qr = lane >> 2, qc = lane & 3;
    if (half_out) {
        __half* Ch = (__half*)Cv;
#pragma unroll
        for (int mf = 0; mf < 2; mf++)
#pragma unroll
            for (int nf = 0; nf < 8; nf++) {
                int row0 = brow + wm * 32 + mf * 16 + qr;
                int col = bcol + wn * 64 + nf * 8 + qc * 2;
                *(__half2*)&Ch[(size_t)row0 * HIDK + col] =
                    __floats2half2_rn(c[mf][nf][0], c[mf][nf][1]);
                *(__half2*)&Ch[(size_t)(row0 + 8) * HIDK + col] =
                    __floats2half2_rn(c[mf][nf][2], c[mf][nf][3]);
            }
    } else {
        float* Cf = (float*)Cv;
#pragma unroll
        for (int mf = 0; mf < 2; mf++)
#pragma unroll
            for (int nf = 0; nf < 8; nf++) {
                int row0 = brow + wm * 32 + mf * 16 + qr;
                int col = bcol + wn * 64 + nf * 8 + qc * 2;
                *(float2*)&Cf[(size_t)row0 * HIDK + col] =
                    make_float2(c[mf][nf][0], c[mf][nf][1]);
                *(float2*)&Cf[(size_t)(row0 + 8) * HIDK + col] =
                    make_float2(c[mf][nf][2], c[mf][nf][3]);
            }
    }
}

__global__ void __launch_bounds__(256, 2) mmproj_kernel() {
    int z = blockIdx.z;
    const __half* B = g_wh + (size_t)z * HIDK * HIDK;
    void* C;
    switch (z) {
        case 0: C = g_qh16; break;
        case 1: C = g_kh16; break;
        case 2: C = g_vh16; break;
        default: C = g_xgh; break;
    }
    mma_gemm_body(g_xh, B, C, true);
}
__global__ void __launch_bounds__(256, 2) mmout_kernel(float* __restrict__ out) {
    mma_gemm_body(g_yh, g_wh + (size_t)4 * HIDK * HIDK, out, false);
}

// ======================= weight conversion (hi only) =====================
__global__ void __launch_bounds__(256) wconv_kernel(const float* __restrict__ W0,
                                                    const float* __restrict__ W1,
                                                    const float* __restrict__ W2,
                                                    const float* __restrict__ W3,
                                                    const float* __restrict__ W4) {
    int z = blockIdx.z;
    const float* W = (z == 0) ? W0 : (z == 1) ? W1 : (z == 2) ? W2 : (z == 3) ? W3 : W4;
    __half* Th = g_wh + (size_t)z * HIDK * HIDK;
    __shared__ float t[32][33];
    int n0 = blockIdx.x * 32, k0 = blockIdx.y * 32;
    int lx = threadIdx.x & 31, ly = threadIdx.x >> 5;
#pragma unroll
    for (int i = 0; i < 4; i++) {
        int r = ly + i * 8;
        t[r][lx] = W[(size_t)(k0 + r) * HIDK + n0 + lx];
    }
    __syncthreads();
#pragma unroll
    for (int i = 0; i < 4; i++) {
        int r = ly + i * 8;
        Th[(size_t)(n0 + r) * HIDK + k0 + lx] = __float2half(t[lx][r]);
    }
}

// ---------------- fused x-convert + low-rank gate path ----------------------
#define SMEM_LR (32 * 1024 * sizeof(float))
__global__ void __launch_bounds__(256) lr_fused_kernel(const float* __restrict__ x,
                                                       const float* __restrict__ W1,
                                                       const float* __restrict__ W2,
                                                       const float* __restrict__ bias) {
    extern __shared__ float s[];
    float* w1s = s;
    float* w2s = s + 16384;
    __shared__ float ts[16][17];
    int tid = threadIdx.x;
    int m0 = blockIdx.x * 16;

#pragma unroll
    for (int i = 0; i < 16; i++) {
        int idx = tid + i * 256;
        ((float4*)w1s)[idx] = ((const float4*)W1)[idx];
        ((float4*)w2s)[idx] = ((const float4*)W2)[idx];
        float4 v = ((const float4*)x)[(size_t)m0 * (HIDK / 4) + idx];
        size_t eo = (size_t)m0 * HIDK + (size_t)idx * 4;
        *(__half2*)&g_xh[eo] = __floats2half2_rn(v.x, v.y);
        *(__half2*)&g_xh[eo + 2] = __floats2half2_rn(v.z, v.w);
    }
    __syncthreads();

    {
        int mt = tid >> 4, r = tid & 15;
        const float4* xr4 = (const float4*)(x + (size_t)(m0 + mt) * HIDK);
        float acc = 0.f;
#pragma unroll 4
        for (int k4 = 0; k4 < 256; k4++) {
            float4 xv = xr4[k4];
            int kb = k4 * 4;
            acc = fmaf(xv.x, w1s[(kb + 0) * 16 + r], acc);
            acc = fmaf(xv.y, w1s[(kb + 1) * 16 + r], acc);
            acc = fmaf(xv.z, w1s[(kb + 2) * 16 + r], acc);
            acc = fmaf(xv.w, w1s[(kb + 3) * 16 + r], acc);
        }
        ts[mt][r] = acc;
    }
    __syncthreads();

    int n = tid * 4;
    float4 b4 = *(const float4*)(bias + n);
#pragma unroll 1
    for (int mi = 0; mi < 16; mi++) {
        float4 a = b4;
#pragma unroll
        for (int rr = 0; rr < 16; rr++) {
            float tv = ts[mi][rr];
            float4 w = *(float4*)&w2s[rr * 1024 + n];
            a.x = fmaf(tv, w.x, a.x);
            a.y = fmaf(tv, w.y, a.y);
            a.z = fmaf(tv, w.z, a.z);
            a.w = fmaf(tv, w.w, a.w);
        }
        float ox = (fminf(a.x, 0.f) - __logf(1.f + __expf(-fabsf(a.x)))) * 0.0625f;
        float oy = (fminf(a.y, 0.f) - __logf(1.f + __expf(-fabsf(a.y)))) * 0.0625f;
        float oz = (fminf(a.z, 0.f) - __logf(1.f + __expf(-fabsf(a.z)))) * 0.0625f;
        float ow = (fminf(a.w, 0.f) - __logf(1.f + __expf(-fabsf(a.w)))) * 0.0625f;
        size_t go = (size_t)(m0 + mi) * HIDK + n;
        *(__half2*)&g_gkh[go] = __floats2half2_rn(ox, oy);
        *(__half2*)&g_gkh[go + 2] = __floats2half2_rn(oz, ow);
    }
}

// ---------------- shared cumsum helper (sGf [64][PD] fp32, U in place) ------
__device__ __forceinline__ void cumsum_gate(float* sGf, __half* UhP, float sTot[4][64],
                                            int tid) {
    {
        int ch = tid & 63, seg = tid >> 6;
        int t0s = seg * 16;
        float run = 0.f;
#pragma unroll
        for (int t = t0s; t < t0s + 16; t++) {
            run += sGf[t * PD + ch];
            sGf[t * PD + ch] = run;
        }
        sTot[seg][ch] = run;
    }
    __syncthreads();
    {
        int ch = tid & 63, seg = tid >> 6;
        float off = 0.f;
        if (seg > 0) off += sTot[0][ch];
        if (seg > 1) off += sTot[1][ch];
        if (seg > 2) off += sTot[2][ch];
        int t0s = seg * 16;
#pragma unroll
        for (int t = t0s; t < t0s + 16; t++) {
            float D = sGf[t * PD + ch] + off;
            sGf[t * PD + ch] = __expf(D);
            UhP[t * PDH + ch] = __float2half(__expf(-D) * __half2float(UhP[t * PDH + ch]));
        }
    }
    __syncthreads();
}

// ---------------- chunkP: cumsum + GEMM3 (P, lastE) -------------------------
#define OFFP_K 17408
#define OFFP_U 26624
#define SMEM_CP 35840

__global__ void __launch_bounds__(256) chunkP_kernel() {
    extern __shared__ char smc[];
    float* sGf = (float*)smc;
    uint32_t sb = smem_u32(smc);
    uint32_t Kb = sb + OFFP_K, Ub = sb + OFFP_U;
    __half* KhP = (__half*)(smc + OFFP_K);
    __half* UhP = (__half*)(smc + OFFP_U);
    __shared__ float sTot[4][64];

    int c = blockIdx.x, bh = blockIdx.y;
    int b = bh >> 4, h = bh & 15;
    int tid = threadIdx.x;
    size_t rowbase = (size_t)(b * LSEQ + c * CT) * HIDK + h * HDIM;

#pragma unroll
    for (int i = 0; i < 2; i++) {
        int idx = tid + i * 256;
        int t = idx >> 3, c8 = (idx & 7) << 3;
        size_t gi = rowbase + (size_t)t * HIDK + c8;
        *(uint4*)&KhP[t * PDH + c8] = *(const uint4*)(g_kh16 + gi);
        *(uint4*)&UhP[t * PDH + c8] = *(const uint4*)(g_vh16 + gi);
        uint4 gg4 = *(const uint4*)(g_gkh + gi);
        const __half2* gh = (const __half2*)&gg4;
        float* dst = &sGf[t * PD + c8];
        float2 a0 = __half22float2(gh[0]);
        float2 a1 = __half22float2(gh[1]);
        float2 a2 = __half22float2(gh[2]);
        float2 a3 = __half22float2(gh[3]);
        dst[0] = a0.x; dst[1] = a0.y; dst[2] = a1.x; dst[3] = a1.y;
        dst[4] = a2.x; dst[5] = a2.y; dst[6] = a3.x; dst[7] = a3.y;
    }
    __syncthreads();

    cumsum_gate(sGf, UhP, sTot, tid);

    if (tid < 64) g_lastE[(size_t)(bh * NCH + c) * 64 + tid] = sGf[63 * PD + tid];

    int w = tid >> 5, l = tid & 31;
    int m0 = (w & 3) << 4, n0h = (w >> 2) << 5;
    int lr2 = l >> 2, lc2 = (l & 3) << 1;

    // GEMM3: P = U^T.K; scale expD_end; store fp16
    float cc[4][4];
#pragma unroll
    for (int i = 0; i < 4; i++)
#pragma unroll
        for (int j = 0; j < 4; j++) cc[i][j] = 0.f;
#pragma unroll
    for (int s0 = 0; s0 < 64; s0 += 16) {
        uint32_t a[4], b0[4], b1[4];
        ldmx4t(a[0], a[1], a[2], a[3],
               Ub + ((s0 + (l & 7) + ((l & 16) ? 8 : 0)) * PDH + m0 + ((l & 8) ? 8 : 0)) * 2);
        ldmx4t(b0[0], b0[1], b0[2], b0[3],
               Kb + ((s0 + (l & 15)) * PDH + n0h + ((l & 16) ? 8 : 0)) * 2);
        ldmx4t(b1[0], b1[1], b1[2], b1[3],
               Kb + ((s0 + (l & 15)) * PDH + n0h + 16 + ((l & 16) ? 8 : 0)) * 2);
        mma16816(cc[0], a, &b0[0]);
        mma16816(cc[1], a, &b0[2]);
        mma16816(cc[2], a, &b1[0]);
        mma16816(cc[3], a, &b1[2]);
    }
    size_t pbase = ((size_t)(bh * NCH + c)) << 12;
    int vr = m0 + lr2;
    float ev0 = sGf[63 * PD + vr];
    float ev1 = sGf[63 * PD + vr + 8];
#pragma unroll
    for (int nf = 0; nf < 4; nf++) {
        int kd = n0h + nf * 8 + lc2;
        *(__half2*)&g_Ph[pbase + ((size_t)vr << 6) + kd] =
            __floats2half2_rn(cc[nf][0] * ev0, cc[nf][1] * ev0);
        *(__half2*)&g_Ph[pbase + ((size_t)(vr + 8) << 6) + kd] =
            __floats2half2_rn(cc[nf][2] * ev1, cc[nf][3] * ev1);
    }
}

// ---------------- kernel B: scan over chunk states (pipelined loads) -------
__global__ void __launch_bounds__(512) chunkscan_kernel() {
    int ks = blockIdx.x;
    int bh = blockIdx.y;
    int tid = threadIdx.x;
    int v = tid >> 3;
    int k = ks * 16 + (tid & 7) * 2;
    float2 S = make_float2(0.f, 0.f);

    size_t base0 = (((size_t)(bh * NCH)) << 12) + ((size_t)v << 6) + k;
    float2 p = __half22float2(*(__half2*)(g_Ph + base0));
    float E = g_lastE[(size_t)(bh * NCH) * 64 + v];

    for (int c = 0; c < NCH; c++) {
        size_t base = (((size_t)(bh * NCH + c)) << 12) + ((size_t)v << 6) + k;
        *(__half2*)(g_Sh + base) = __floats2half2_rn(S.x, S.y);
        float2 pn;
        float En;
        if (c + 1 < NCH) {
            pn = __half22float2(*(__half2*)(g_Ph + base + 4096));
            En = g_lastE[(size_t)(bh * NCH + c + 1) * 64 + v];
        }
        S.x = fmaf(S.x, E, p.x);
        S.y = fmaf(S.y, E, p.y);
        p = pn;
        E = En;
    }
}

// ---------------- bigInter: cumsum + GEMM1 + (GEMM2 + interGEMM) fused -----
#define OFF_Q 17408
#define OFF_K 26624
#define OFF_U 35840
#define OFF_A 45056
#define OFF_S 54272
#define SMEM_BI 63488

__global__ void __launch_bounds__(256) biginter_kernel() {
    extern __shared__ char smc[];
    float* sGf = (float*)smc;
    uint32_t sb = smem_u32(smc);
    uint32_t Qb = sb + OFF_Q, Kb = sb + OFF_K, Ub = sb + OFF_U, Ab = sb + OFF_A,
             Sb = sb + OFF_S;
    __half* QhP = (__half*)(smc + OFF_Q);
    __half* KhP = (__half*)(smc + OFF_K);
    __half* UhP = (__half*)(smc + OFF_U);
    __half* AhP = (__half*)(smc + OFF_A);
    __half* ShP = (__half*)(smc + OFF_S);
    __shared__ float sTot[4][64];

    int c = blockIdx.x, bh = blockIdx.y;
    int b = bh >> 4, h = bh & 15;
    int tid = threadIdx.x;
    size_t rowbase = (size_t)(b * LSEQ + c * CT) * HIDK + h * HDIM;
    size_t sbase = ((size_t)(bh * NCH + c)) << 12;

#pragma unroll
    for (int i = 0; i < 2; i++) {
        int idx = tid + i * 256;
        int t = idx >> 3, c8 = (idx & 7) << 3;
        size_t gi = rowbase + (size_t)t * HIDK + c8;
        *(uint4*)&QhP[t * PDH + c8] = *(const uint4*)(g_qh16 + gi);
        *(uint4*)&KhP[t * PDH + c8] = *(const uint4*)(g_kh16 + gi);
        *(uint4*)&UhP[t * PDH + c8] = *(const uint4*)(g_vh16 + gi);
        *(uint4*)&ShP[t * PDH + c8] = *(const uint4*)(g_Sh + sbase + ((size_t)t << 6) + c8);
        uint4 gg4 = *(const uint4*)(g_gkh + gi);
        const __half2* gh = (const __half2*)&gg4;
        float* dst = &sGf[t * PD + c8];
        float2 a0 = __half22float2(gh[0]);
        float2 a1 = __half22float2(gh[1]);
        float2 a2 = __half22float2(gh[2]);
        float2 a3 = __half22float2(gh[3]);
        dst[0] = a0.x; dst[1] = a0.y; dst[2] = a1.x; dst[3] = a1.y;
        dst[4] = a2.x; dst[5] = a2.y; dst[6] = a3.x; dst[7] = a3.y;
    }
    __syncthreads();

    cumsum_gate(sGf, UhP, sTot, tid);

    int w = tid >> 5, l = tid & 31;
    int m0 = (w & 3) << 4, n0h = (w >> 2) << 5;
    int lr2 = l >> 2, lc2 = (l & 3) << 1;

    // GEMM1: A = Q.K^T masked -> fp16
    {
        float cc[4][4];
#pragma unroll
        for (int i = 0; i < 4; i++)
#pragma unroll
            for (int j = 0; j < 4; j++) cc[i][j] = 0.f;
#pragma unroll
        for (int k0 = 0; k0 < 64; k0 += 16) {
            uint32_t a[4], b0[4], b1[4];
            ldmx4(a[0], a[1], a[2], a[3],
                  Qb + ((m0 + (l & 15)) * PDH + k0 + ((l & 16) ? 8 : 0)) * 2);
            ldmx4(b0[0], b0[1], b0[2], b0[3],
                  Kb + ((n0h + (l & 7) + ((l & 16) ? 8 : 0)) * PDH + k0 + ((l & 8) ? 8 : 0)) * 2);
            ldmx4(b1[0], b1[1], b1[2], b1[3],
                  Kb + ((n0h + 16 + (l & 7) + ((l & 16) ? 8 : 0)) * PDH + k0 + ((l & 8) ? 8 : 0)) * 2);
            mma16816(cc[0], a, &b0[0]);
            mma16816(cc[1], a, &b0[2]);
            mma16816(cc[2], a, &b1[0]);
            mma16816(cc[3], a, &b1[2]);
        }
        int tr = m0 + lr2;
#pragma unroll
        for (int nf = 0; nf < 4; nf++) {
            int sc = n0h + nf * 8 + lc2;
            *(__half2*)&AhP[tr * PDH + sc] = __halves2half2(
                __float2half(sc <= tr ? cc[nf][0] : 0.f),
                __float2half(sc + 1 <= tr ? cc[nf][1] : 0.f));
            int tr2 = tr + 8;
            *(__half2*)&AhP[tr2 * PDH + sc] = __halves2half2(
                __float2half(sc <= tr2 ? cc[nf][2] : 0.f),
                __float2half(sc + 1 <= tr2 ? cc[nf][3] : 0.f));
        }
    }
    __syncthreads();

    // GEMM2 (A'.U) + interGEMM (Q.S^T) accumulated into one fragment set
    {
        float cc[4][4];
#pragma unroll
        for (int i = 0; i < 4; i++)
#pragma unroll
            for (int j = 0; j < 4; j++) cc[i][j] = 0.f;
#pragma unroll
        for (int s0 = 0; s0 < 64; s0 += 16) {
            uint32_t a[4], b0[4], b1[4];
            ldmx4(a[0], a[1], a[2], a[3],
                  Ab + ((m0 + (l & 15)) * PDH + s0 + ((l & 16) ? 8 : 0)) * 2);
            ldmx4t(b0[0], b0[1], b0[2], b0[3],
                   Ub + ((s0 + (l & 15)) * PDH + n0h + ((l & 16) ? 8 : 0)) * 2);
            ldmx4t(b1[0], b1[1], b1[2], b1[3],
                   Ub + ((s0 + (l & 15)) * PDH + n0h + 16 + ((l & 16) ? 8 : 0)) * 2);
            mma16816(cc[0], a, &b0[0]);
            mma16816(cc[1], a, &b0[2]);
            mma16816(cc[2], a, &b1[0]);
            mma16816(cc[3], a, &b1[2]);
        }
#pragma unroll
        for (int k0 = 0; k0 < 64; k0 += 16) {
            uint32_t a[4], b0[4], b1[4];
            ldmx4(a[0], a[1], a[2], a[3],
                  Qb + ((m0 + (l & 15)) * PDH + k0 + ((l & 16) ? 8 : 0)) * 2);
            ldmx4(b0[0], b0[1], b0[2], b0[3],
                  Sb + ((n0h + (l & 7) + ((l & 16) ? 8 : 0)) * PDH + k0 + ((l & 8) ? 8 : 0)) * 2);
            ldmx4(b1[0], b1[1], b1[2], b1[3],
                  Sb + ((n0h + 16 + (l & 7) + ((l & 16) ? 8 : 0)) * PDH + k0 + ((l & 8) ? 8 : 0)) * 2);
            mma16816(cc[0], a, &b0[0]);
            mma16816(cc[1], a, &b0[2]);
            mma16816(cc[2], a, &b1[0]);
            mma16816(cc[3], a, &b1[2]);
        }
        int tr = m0 + lr2;
#pragma unroll
        for (int nf = 0; nf < 4; nf++) {
            int v = n0h + nf * 8 + lc2;
            float2 e0 = *(float2*)&sGf[tr * PD + v];
            *(__half2*)&g_attf[rowbase + (size_t)tr * HIDK + v] =
                __floats2half2_rn(cc[nf][0] * e0.x, cc[nf][1] * e0.y);
            float2 e1 = *(float2*)&sGf[(tr + 8) * PD + v];
            *(__half2*)&g_attf[rowbase + (size_t)(tr + 8) * HIDK + v] =
                __floats2half2_rn(cc[nf][2] * e1.x, cc[nf][3] * e1.y);
        }
    }
}

// ---------------- LayerNorm + SiLU gate -> fp16 y (vectorized) --------------
__global__ void __launch_bounds__(256) ln_gate_kernel(const float* __restrict__ gamma,
                                                      const float* __restrict__ beta) {
    int row = blockIdx.x;
    int tid = threadIdx.x;
    int col0 = tid * 4;
    size_t rb = (size_t)row * HIDK;

    uint2 av = *(const uint2*)(g_attf + rb + col0);
    const __half2* ah = (const __half2*)&av;
    float2 a01 = __half22float2(ah[0]);
    float2 a23 = __half22float2(ah[1]);
    float vals[4] = {a01.x, a01.y, a23.x, a23.y};

    float s = vals[0] + vals[1] + vals[2] + vals[3];
    float s2 = fmaf(vals[0], vals[0],
                    fmaf(vals[1], vals[1], fmaf(vals[2], vals[2], vals[3] * vals[3])));
#pragma unroll
    for (int o = 16; o; o >>= 1) {
        s += __shfl_xor_sync(0xffffffffu, s, o);
        s2 += __shfl_xor_sync(0xffffffffu, s2, o);
    }
    __shared__ float rs[8], rs2[8];
    int warp = tid >> 5;
    if ((tid & 31) == 0) { rs[warp] = s; rs2[warp] = s2; }
    __syncthreads();
    s = 0.f;
    s2 = 0.f;
#pragma unroll
    for (int w = 0; w < 8; w++) { s += rs[w]; s2 += rs2[w]; }
    float mean = s * (1.f / HIDK);
    float var = s2 * (1.f / HIDK) - mean * mean;
    float rstd = rsqrtf(var + 1e-5f);

    uint2 gv2 = *(const uint2*)(g_xgh + rb + col0);
    const __half2* gh = (const __half2*)&gv2;
    float2 g01 = __half22float2(gh[0]);
    float2 g23 = __half22float2(gh[1]);
    float gvs[4] = {g01.x, g01.y, g23.x, g23.y};

    float4 gm = *(const float4*)(gamma + col0);
    float4 bt = *(const float4*)(beta + col0);
    float gmv[4] = {gm.x, gm.y, gm.z, gm.w};
    float btv[4] = {bt.x, bt.y, bt.z, bt.w};

    __half yh4[4];
#pragma unroll
    for (int i = 0; i < 4; i++) {
        float sil = gvs[i] / (1.f + __expf(-gvs[i]));
        float yv = ((vals[i] - mean) * rstd * gmv[i] + btv[i]) * sil;
        yh4[i] = __float2half(yv);
    }
    *(uint2*)(g_yh + rb + col0) = *(uint2*)yh4;
}

// ---------------- launch --------------------------------------------------
extern "C" void kernel_launch(void* const* d_in, const int* in_sizes, int n_in,
                              void* d_out, int out_size) {
    const float* x = (const float*)d_in[0];
    const float* Wq = (const float*)d_in[1];
    const float* Wk = (const float*)d_in[2];
    const float* Wv = (const float*)d_in[3];
    const float* Wg = (const float*)d_in[4];
    const float* Wgk1 = (const float*)d_in[5];
    const float* Wgk2 = (const float*)d_in[6];
    const float* bgk2 = (const float*)d_in[7];
    const float* gamma = (const float*)d_in[8];
    const float* beta = (const float*)d_in[9];
    const float* Wout = (const float*)d_in[10];
    float* out = (float*)d_out;

    cudaFuncSetAttribute(chunkP_kernel, cudaFuncAttributeMaxDynamicSharedMemorySize, SMEM_CP);
    cudaFuncSetAttribute(biginter_kernel, cudaFuncAttributeMaxDynamicSharedMemorySize, SMEM_BI);
    cudaFuncSetAttribute(mmproj_kernel, cudaFuncAttributeMaxDynamicSharedMemorySize, SMEM_MM);
    cudaFuncSetAttribute(mmout_kernel, cudaFuncAttributeMaxDynamicSharedMemorySize, SMEM_MM);
    cudaFuncSetAttribute(lr_fused_kernel, cudaFuncAttributeMaxDynamicSharedMemorySize, SMEM_LR);

    wconv_kernel<<<dim3(32, 32, 5), 256>>>(Wq, Wk, Wv, Wg, Wout);
    lr_fused_kernel<<<MTOK / 16, 256, SMEM_LR>>>(x, Wgk1, Wgk2, bgk2);

    mmproj_kernel<<<dim3(8, 32, 4), 256, SMEM_MM>>>();

    chunkP_kernel<<<dim3(NCH, 32), 256, SMEM_CP>>>();
    chunkscan_kernel<<<dim3(4, 32), 512>>>();
    biginter_kernel<<<dim3(NCH, 32), 256, SMEM_BI>>>();
    ln_gate_kernel<<<MTOK, 256>>>(gamma, beta);

    mmout_kernel<<<dim3(8, 32, 1), 256, SMEM_MM>>>(out);
}

// round 17
// speedup vs baseline: 1.9900x; 1.0210x over previous
#include <cuda_runtime.h>
#include <cuda_fp16.h>
#include <math.h>
#include <stdint.h>

#define HIDK 1024
#define MTOK 4096
#define LSEQ 2048
#define NHEAD 16
#define HDIM 64
#define CT 64
#define NCH (LSEQ / CT)
#define PD 68
#define PDH 72

// ---------------- scratch (device globals; no allocations) ----------------
__device__ __align__(16) __half g_xgh[MTOK * HIDK];       // gate pre-activation (fp16)
__device__ __align__(16) __half g_attf[MTOK * HIDK];      // final o (fp16)
__device__ __align__(16) __half g_qh16[MTOK * HIDK];
__device__ __align__(16) __half g_kh16[MTOK * HIDK];
__device__ __align__(16) __half g_vh16[MTOK * HIDK];
__device__ __align__(16) __half g_gkh[MTOK * HIDK];
__device__ float g_lastE[32 * NCH * HDIM];                // expD at t=63 per (bh,c,v)
__device__ __align__(16) __half g_Ph[32 * NCH * HDIM * HDIM];
__device__ __align__(16) __half g_Sh[32 * NCH * HDIM * HDIM];
// fp16 GEMM operands (single-product everywhere)
__device__ __align__(16) __half g_xh[MTOK * HIDK];
__device__ __align__(16) __half g_yh[MTOK * HIDK];
__device__ __align__(16) __half g_wh[5 * HIDK * HIDK];

// ---------------- host-side streams/events (created pre-main) --------------
struct GpuRes {
    cudaStream_t s1 = nullptr;
    cudaEvent_t eA = nullptr, eW = nullptr, eL = nullptr, eQ = nullptr;
    GpuRes() {
        int lo = 0, hi = 0;
        cudaDeviceGetStreamPriorityRange(&lo, &hi);  // lo = least priority
        cudaStreamCreateWithPriority(&s1, cudaStreamNonBlocking, lo);
        cudaEventCreateWithFlags(&eA, cudaEventDisableTiming);
        cudaEventCreateWithFlags(&eW, cudaEventDisableTiming);
        cudaEventCreateWithFlags(&eL, cudaEventDisableTiming);
        cudaEventCreateWithFlags(&eQ, cudaEventDisableTiming);
    }
};
static GpuRes g_res;

// ======================= helpers =======================
__device__ __forceinline__ uint32_t smem_u32(const void* p) {
    uint32_t a;
    asm("{ .reg .u64 t; cvta.to.shared.u64 t, %1; cvt.u32.u64 %0, t; }" : "=r"(a) : "l"(p));
    return a;
}
__device__ __forceinline__ void cpasync16(uint32_t s, const void* g) {
    asm volatile("cp.async.cg.shared.global [%0], [%1], 16;" ::"r"(s), "l"(g));
}
__device__ __forceinline__ void cpcommit() { asm volatile("cp.async.commit_group;"); }

__device__ __forceinline__ void ldmx4(uint32_t& r0, uint32_t& r1, uint32_t& r2,
                                      uint32_t& r3, uint32_t addr) {
    asm volatile("ldmatrix.sync.aligned.m8n8.x4.shared.b16 {%0,%1,%2,%3}, [%4];"
                 : "=r"(r0), "=r"(r1), "=r"(r2), "=r"(r3)
                 : "r"(addr));
}
__device__ __forceinline__ void ldmx4t(uint32_t& r0, uint32_t& r1, uint32_t& r2,
                                       uint32_t& r3, uint32_t addr) {
    asm volatile("ldmatrix.sync.aligned.m8n8.x4.trans.shared.b16 {%0,%1,%2,%3}, [%4];"
                 : "=r"(r0), "=r"(r1), "=r"(r2), "=r"(r3)
                 : "r"(addr));
}
__device__ __forceinline__ void mma16816(float* c, const uint32_t* a, const uint32_t* b) {
    asm volatile(
        "mma.sync.aligned.m16n8k16.row.col.f32.f16.f16.f32 "
        "{%0,%1,%2,%3}, {%4,%5,%6,%7}, {%8,%9}, {%0,%1,%2,%3};"
        : "+f"(c[0]), "+f"(c[1]), "+f"(c[2]), "+f"(c[3])
        : "r"(a[0]), "r"(a[1]), "r"(a[2]), "r"(a[3]), "r"(b[0]), "r"(b[1]));
}

// ======================= fp16 mma.sync big GEMM (BK=64, 3-stage) ============
#define ROWB2 144
#define BLK2 (128 * ROWB2)
#define STG2 (2 * BLK2)
#define NSTG2 3
#define SMEM_MM (NSTG2 * STG2)
#define NSTAGES 16

__device__ __forceinline__ void mm_issue(int s, uint32_t sb, int tid,
                                         int brow, int bcol,
                                         const __half* A, const __half* B) {
    if (s < NSTAGES) {
        int kk = s << 6;
        uint32_t st = sb + (uint32_t)(s % NSTG2) * STG2;
        int row0 = tid >> 3, cw = tid & 7;
        uint32_t so = row0 * ROWB2 + cw * 16;
        size_t go = (size_t)(brow + row0) * HIDK + kk + cw * 8;
#pragma unroll
        for (int p = 0; p < 4; p++)
            cpasync16(st + so + p * 32 * ROWB2, A + go + (size_t)p * 32 * HIDK);
        size_t gob = (size_t)(bcol + row0) * HIDK + kk + cw * 8;
#pragma unroll
        for (int p = 0; p < 4; p++)
            cpasync16(st + BLK2 + so + p * 32 * ROWB2, B + gob + (size_t)p * 32 * HIDK);
    }
    cpcommit();
}

__device__ __forceinline__ void mma_gemm_body(const __half* __restrict__ A,
                                              const __half* __restrict__ B,
                                              void* __restrict__ Cv, bool half_out) {
    extern __shared__ char sm_raw[];
    uint32_t sb = smem_u32(sm_raw);
    int tid = threadIdx.x, lane = tid & 31, wid = tid >> 5;
    int wm = wid & 3, wn = wid >> 2;
    int brow = blockIdx.y * 128, bcol = blockIdx.x * 128;

    float c[2][8][4];
#pragma unroll
    for (int i = 0; i < 2; i++)
#pragma unroll
        for (int j = 0; j < 8; j++)
#pragma unroll
            for (int l = 0; l < 4; l++) c[i][j][l] = 0.f;

    mm_issue(0, sb, tid, brow, bcol, A, B);
    mm_issue(1, sb, tid, brow, bcol, A, B);

    int q = lane >> 3, r = lane & 7;

    for (int s = 0; s < NSTAGES; s++) {
        asm volatile("cp.async.wait_group 1;" ::: "memory");
        __syncthreads();
        uint32_t st = sb + (uint32_t)(s % NSTG2) * STG2;
        uint32_t sA = st, sB = st + BLK2;
#pragma unroll
        for (int k0 = 0; k0 < 64; k0 += 16) {
            uint32_t a[2][4], b[8][2];
#pragma unroll
            for (int mf = 0; mf < 2; mf++) {
                int rrow = wm * 32 + mf * 16 + (q & 1) * 8 + r;
                int kc = k0 + (q >> 1) * 8;
                ldmx4(a[mf][0], a[mf][1], a[mf][2], a[mf][3], sA + rrow * ROWB2 + kc * 2);
            }
#pragma unroll
            for (int pb = 0; pb < 4; pb++) {
                int nrow = wn * 64 + pb * 16 + (q >> 1) * 8 + r;
                int kc = k0 + (q & 1) * 8;
                uint32_t r0, r1, r2, r3;
                ldmx4(r0, r1, r2, r3, sB + nrow * ROWB2 + kc * 2);
                b[pb * 2][0] = r0;
                b[pb * 2][1] = r1;
                b[pb * 2 + 1][0] = r2;
                b[pb * 2 + 1][1] = r3;
            }
#pragma unroll
            for (int mf = 0; mf < 2; mf++)
#pragma unroll
                for (int nf = 0; nf < 8; nf++) mma16816(c[mf][nf], a[mf], b[nf]);
        }
        mm_issue(s + 2, sb, tid, brow, bcol, A, B);
    }

    int qr = lane >> 2, qc = lane & 3;
    if (half_out) {
        __half* Ch = (__half*)Cv;
#pragma unroll
        for (int mf = 0; mf < 2; mf++)
#pragma unroll
            for (int nf = 0; nf < 8; nf++) {
                int row0 = brow + wm * 32 + mf * 16 + qr;
                int col = bcol + wn * 64 + nf * 8 + qc * 2;
                *(__half2*)&Ch[(size_t)row0 * HIDK + col] =
                    __floats2half2_rn(c[mf][nf][0], c[mf][nf][1]);
                *(__half2*)&Ch[(size_t)(row0 + 8) * HIDK + col] =
                    __floats2half2_rn(c[mf][nf][2], c[mf][nf][3]);
            }
    } else {
        float* Cf = (float*)Cv;
#pragma unroll
        for (int mf = 0; mf < 2; mf++)
#pragma unroll
            for (int nf = 0; nf < 8; nf++) {
                int row0 = brow + wm * 32 + mf * 16 + qr;
                int col = bcol + wn * 64 + nf * 8 + qc * 2;
                *(float2*)&Cf[(size_t)row0 * HIDK + col] =
                    make_float2(c[mf][nf][0], c[mf][nf][1]);
                *(float2*)&Cf[(size_t)(row0 + 8) * HIDK + col] =
                    make_float2(c[mf][nf][2], c[mf][nf][3]);
            }
    }
}

// critical path: k,v projections
__global__ void __launch_bounds__(256, 2) mmproj_kv_kernel() {
    int z = blockIdx.z;  // 0->k (w1), 1->v (w2)
    const __half* B = g_wh + (size_t)(z + 1) * HIDK * HIDK;
    mma_gemm_body(g_xh, B, z == 0 ? (void*)g_kh16 : (void*)g_vh16, true);
}
// side path: q, xg projections
__global__ void __launch_bounds__(256, 2) mmproj_qg_kernel() {
    int z = blockIdx.z;  // 0->q (w0), 1->xg (w3)
    const __half* B = g_wh + (size_t)(z == 0 ? 0 : 3) * HIDK * HIDK;
    mma_gemm_body(g_xh, B, z == 0 ? (void*)g_qh16 : (void*)g_xgh, true);
}
__global__ void __launch_bounds__(256, 2) mmout_kernel(float* __restrict__ out) {
    mma_gemm_body(g_yh, g_wh + (size_t)4 * HIDK * HIDK, out, false);
}

// ======================= weight conversion (hi only) =====================
__global__ void __launch_bounds__(256) wconv_kernel(const float* __restrict__ W0,
                                                    const float* __restrict__ W1,
                                                    const float* __restrict__ W2,
                                                    const float* __restrict__ W3,
                                                    const float* __restrict__ W4) {
    int z = blockIdx.z;
    const float* W = (z == 0) ? W0 : (z == 1) ? W1 : (z == 2) ? W2 : (z == 3) ? W3 : W4;
    __half* Th = g_wh + (size_t)z * HIDK * HIDK;
    __shared__ float t[32][33];
    int n0 = blockIdx.x * 32, k0 = blockIdx.y * 32;
    int lx = threadIdx.x & 31, ly = threadIdx.x >> 5;
#pragma unroll
    for (int i = 0; i < 4; i++) {
        int r = ly + i * 8;
        t[r][lx] = W[(size_t)(k0 + r) * HIDK + n0 + lx];
    }
    __syncthreads();
#pragma unroll
    for (int i = 0; i < 4; i++) {
        int r = ly + i * 8;
        Th[(size_t)(n0 + r) * HIDK + k0 + lx] = __float2half(t[lx][r]);
    }
}

// ---------------- fused x-convert + low-rank gate path ----------------------
#define SMEM_LR (32 * 1024 * sizeof(float))
__global__ void __launch_bounds__(256) lr_fused_kernel(const float* __restrict__ x,
                                                       const float* __restrict__ W1,
                                                       const float* __restrict__ W2,
                                                       const float* __restrict__ bias) {
    extern __shared__ float s[];
    float* w1s = s;
    float* w2s = s + 16384;
    __shared__ float ts[16][17];
    int tid = threadIdx.x;
    int m0 = blockIdx.x * 16;

#pragma unroll
    for (int i = 0; i < 16; i++) {
        int idx = tid + i * 256;
        ((float4*)w1s)[idx] = ((const float4*)W1)[idx];
        ((float4*)w2s)[idx] = ((const float4*)W2)[idx];
        float4 v = ((const float4*)x)[(size_t)m0 * (HIDK / 4) + idx];
        size_t eo = (size_t)m0 * HIDK + (size_t)idx * 4;
        *(__half2*)&g_xh[eo] = __floats2half2_rn(v.x, v.y);
        *(__half2*)&g_xh[eo + 2] = __floats2half2_rn(v.z, v.w);
    }
    __syncthreads();

    {
        int mt = tid >> 4, r = tid & 15;
        const float4* xr4 = (const float4*)(x + (size_t)(m0 + mt) * HIDK);
        float acc = 0.f;
#pragma unroll 4
        for (int k4 = 0; k4 < 256; k4++) {
            float4 xv = xr4[k4];
            int kb = k4 * 4;
            acc = fmaf(xv.x, w1s[(kb + 0) * 16 + r], acc);
            acc = fmaf(xv.y, w1s[(kb + 1) * 16 + r], acc);
            acc = fmaf(xv.z, w1s[(kb + 2) * 16 + r], acc);
            acc = fmaf(xv.w, w1s[(kb + 3) * 16 + r], acc);
        }
        ts[mt][r] = acc;
    }
    __syncthreads();

    int n = tid * 4;
    float4 b4 = *(const float4*)(bias + n);
#pragma unroll 1
    for (int mi = 0; mi < 16; mi++) {
        float4 a = b4;
#pragma unroll
        for (int rr = 0; rr < 16; rr++) {
            float tv = ts[mi][rr];
            float4 w = *(float4*)&w2s[rr * 1024 + n];
            a.x = fmaf(tv, w.x, a.x);
            a.y = fmaf(tv, w.y, a.y);
            a.z = fmaf(tv, w.z, a.z);
            a.w = fmaf(tv, w.w, a.w);
        }
        float ox = (fminf(a.x, 0.f) - __logf(1.f + __expf(-fabsf(a.x)))) * 0.0625f;
        float oy = (fminf(a.y, 0.f) - __logf(1.f + __expf(-fabsf(a.y)))) * 0.0625f;
        float oz = (fminf(a.z, 0.f) - __logf(1.f + __expf(-fabsf(a.z)))) * 0.0625f;
        float ow = (fminf(a.w, 0.f) - __logf(1.f + __expf(-fabsf(a.w)))) * 0.0625f;
        size_t go = (size_t)(m0 + mi) * HIDK + n;
        *(__half2*)&g_gkh[go] = __floats2half2_rn(ox, oy);
        *(__half2*)&g_gkh[go + 2] = __floats2half2_rn(oz, ow);
    }
}

// ---------------- shared cumsum helper (sGf [64][PD] fp32, U in place) ------
__device__ __forceinline__ void cumsum_gate(float* sGf, __half* UhP, float sTot[4][64],
                                            int tid) {
    {
        int ch = tid & 63, seg = tid >> 6;
        int t0s = seg * 16;
        float run = 0.f;
#pragma unroll
        for (int t = t0s; t < t0s + 16; t++) {
            run += sGf[t * PD + ch];
            sGf[t * PD + ch] = run;
        }
        sTot[seg][ch] = run;
    }
    __syncthreads();
    {
        int ch = tid & 63, seg = tid >> 6;
        float off = 0.f;
        if (seg > 0) off += sTot[0][ch];
        if (seg > 1) off += sTot[1][ch];
        if (seg > 2) off += sTot[2][ch];
        int t0s = seg * 16;
#pragma unroll
        for (int t = t0s; t < t0s + 16; t++) {
            float D = sGf[t * PD + ch] + off;
            sGf[t * PD + ch] = __expf(D);
            UhP[t * PDH + ch] = __float2half(__expf(-D) * __half2float(UhP[t * PDH + ch]));
        }
    }
    __syncthreads();
}

// ---------------- chunkP: cumsum + GEMM3 (P, lastE) -------------------------
#define OFFP_K 17408
#define OFFP_U 26624
#define SMEM_CP 35840

__global__ void __launch_bounds__(256) chunkP_kernel() {
    extern __shared__ char smc[];
    float* sGf = (float*)smc;
    uint32_t sb = smem_u32(smc);
    uint32_t Kb = sb + OFFP_K, Ub = sb + OFFP_U;
    __half* KhP = (__half*)(smc + OFFP_K);
    __half* UhP = (__half*)(smc + OFFP_U);
    __shared__ float sTot[4][64];

    int c = blockIdx.x, bh = blockIdx.y;
    int b = bh >> 4, h = bh & 15;
    int tid = threadIdx.x;
    size_t rowbase = (size_t)(b * LSEQ + c * CT) * HIDK + h * HDIM;

#pragma unroll
    for (int i = 0; i < 2; i++) {
        int idx = tid + i * 256;
        int t = idx >> 3, c8 = (idx & 7) << 3;
        size_t gi = rowbase + (size_t)t * HIDK + c8;
        *(uint4*)&KhP[t * PDH + c8] = *(const uint4*)(g_kh16 + gi);
        *(uint4*)&UhP[t * PDH + c8] = *(const uint4*)(g_vh16 + gi);
        uint4 gg4 = *(const uint4*)(g_gkh + gi);
        const __half2* gh = (const __half2*)&gg4;
        float* dst = &sGf[t * PD + c8];
        float2 a0 = __half22float2(gh[0]);
        float2 a1 = __half22float2(gh[1]);
        float2 a2 = __half22float2(gh[2]);
        float2 a3 = __half22float2(gh[3]);
        dst[0] = a0.x; dst[1] = a0.y; dst[2] = a1.x; dst[3] = a1.y;
        dst[4] = a2.x; dst[5] = a2.y; dst[6] = a3.x; dst[7] = a3.y;
    }
    __syncthreads();

    cumsum_gate(sGf, UhP, sTot, tid);

    if (tid < 64) g_lastE[(size_t)(bh * NCH + c) * 64 + tid] = sGf[63 * PD + tid];

    int w = tid >> 5, l = tid & 31;
    int m0 = (w & 3) << 4, n0h = (w >> 2) << 5;
    int lr2 = l >> 2, lc2 = (l & 3) << 1;

    float cc[4][4];
#pragma unroll
    for (int i = 0; i < 4; i++)
#pragma unroll
        for (int j = 0; j < 4; j++) cc[i][j] = 0.f;
#pragma unroll
    for (int s0 = 0; s0 < 64; s0 += 16) {
        uint32_t a[4], b0[4], b1[4];
        ldmx4t(a[0], a[1], a[2], a[3],
               Ub + ((s0 + (l & 7) + ((l & 16) ? 8 : 0)) * PDH + m0 + ((l & 8) ? 8 : 0)) * 2);
        ldmx4t(b0[0], b0[1], b0[2], b0[3],
               Kb + ((s0 + (l & 15)) * PDH + n0h + ((l & 16) ? 8 : 0)) * 2);
        ldmx4t(b1[0], b1[1], b1[2], b1[3],
               Kb + ((s0 + (l & 15)) * PDH + n0h + 16 + ((l & 16) ? 8 : 0)) * 2);
        mma16816(cc[0], a, &b0[0]);
        mma16816(cc[1], a, &b0[2]);
        mma16816(cc[2], a, &b1[0]);
        mma16816(cc[3], a, &b1[2]);
    }
    size_t pbase = ((size_t)(bh * NCH + c)) << 12;
    int vr = m0 + lr2;
    float ev0 = sGf[63 * PD + vr];
    float ev1 = sGf[63 * PD + vr + 8];
#pragma unroll
    for (int nf = 0; nf < 4; nf++) {
        int kd = n0h + nf * 8 + lc2;
        *(__half2*)&g_Ph[pbase + ((size_t)vr << 6) + kd] =
            __floats2half2_rn(cc[nf][0] * ev0, cc[nf][1] * ev0);
        *(__half2*)&g_Ph[pbase + ((size_t)(vr + 8) << 6) + kd] =
            __floats2half2_rn(cc[nf][2] * ev1, cc[nf][3] * ev1);
    }
}

// ---------------- kernel B: scan over chunk states (pipelined loads) -------
__global__ void __launch_bounds__(512) chunkscan_kernel() {
    int ks = blockIdx.x;
    int bh = blockIdx.y;
    int tid = threadIdx.x;
    int v = tid >> 3;
    int k = ks * 16 + (tid & 7) * 2;
    float2 S = make_float2(0.f, 0.f);

    size_t base0 = (((size_t)(bh * NCH)) << 12) + ((size_t)v << 6) + k;
    float2 p = __half22float2(*(__half2*)(g_Ph + base0));
    float E = g_lastE[(size_t)(bh * NCH) * 64 + v];

    for (int c = 0; c < NCH; c++) {
        size_t base = (((size_t)(bh * NCH + c)) << 12) + ((size_t)v << 6) + k;
        *(__half2*)(g_Sh + base) = __floats2half2_rn(S.x, S.y);
        float2 pn;
        float En;
        if (c + 1 < NCH) {
            pn = __half22float2(*(__half2*)(g_Ph + base + 4096));
            En = g_lastE[(size_t)(bh * NCH + c + 1) * 64 + v];
        }
        S.x = fmaf(S.x, E, p.x);
        S.y = fmaf(S.y, E, p.y);
        p = pn;
        E = En;
    }
}

// ---------------- bigInter: cumsum + GEMM1 + (GEMM2 + interGEMM) fused -----
#define OFF_Q 17408
#define OFF_K 26624
#define OFF_U 35840
#define OFF_A 45056
#define OFF_S 54272
#define SMEM_BI 63488

__global__ void __launch_bounds__(256) biginter_kernel() {
    extern __shared__ char smc[];
    float* sGf = (float*)smc;
    uint32_t sb = smem_u32(smc);
    uint32_t Qb = sb + OFF_Q, Kb = sb + OFF_K, Ub = sb + OFF_U, Ab = sb + OFF_A,
             Sb = sb + OFF_S;
    __half* QhP = (__half*)(smc + OFF_Q);
    __half* KhP = (__half*)(smc + OFF_K);
    __half* UhP = (__half*)(smc + OFF_U);
    __half* AhP = (__half*)(smc + OFF_A);
    __half* ShP = (__half*)(smc + OFF_S);
    __shared__ float sTot[4][64];

    int c = blockIdx.x, bh = blockIdx.y;
    int b = bh >> 4, h = bh & 15;
    int tid = threadIdx.x;
    size_t rowbase = (size_t)(b * LSEQ + c * CT) * HIDK + h * HDIM;
    size_t sbase = ((size_t)(bh * NCH + c)) << 12;

#pragma unroll
    for (int i = 0; i < 2; i++) {
        int idx = tid + i * 256;
        int t = idx >> 3, c8 = (idx & 7) << 3;
        size_t gi = rowbase + (size_t)t * HIDK + c8;
        *(uint4*)&QhP[t * PDH + c8] = *(const uint4*)(g_qh16 + gi);
        *(uint4*)&KhP[t * PDH + c8] = *(const uint4*)(g_kh16 + gi);
        *(uint4*)&UhP[t * PDH + c8] = *(const uint4*)(g_vh16 + gi);
        *(uint4*)&ShP[t * PDH + c8] = *(const uint4*)(g_Sh + sbase + ((size_t)t << 6) + c8);
        uint4 gg4 = *(const uint4*)(g_gkh + gi);
        const __half2* gh = (const __half2*)&gg4;
        float* dst = &sGf[t * PD + c8];
        float2 a0 = __half22float2(gh[0]);
        float2 a1 = __half22float2(gh[1]);
        float2 a2 = __half22float2(gh[2]);
        float2 a3 = __half22float2(gh[3]);
        dst[0] = a0.x; dst[1] = a0.y; dst[2] = a1.x; dst[3] = a1.y;
        dst[4] = a2.x; dst[5] = a2.y; dst[6] = a3.x; dst[7] = a3.y;
    }
    __syncthreads();

    cumsum_gate(sGf, UhP, sTot, tid);

    int w = tid >> 5, l = tid & 31;
    int m0 = (w & 3) << 4, n0h = (w >> 2) << 5;
    int lr2 = l >> 2, lc2 = (l & 3) << 1;

    // GEMM1: A = Q.K^T masked -> fp16
    {
        float cc[4][4];
#pragma unroll
        for (int i = 0; i < 4; i++)
#pragma unroll
            for (int j = 0; j < 4; j++) cc[i][j] = 0.f;
#pragma unroll
        for (int k0 = 0; k0 < 64; k0 += 16) {
            uint32_t a[4], b0[4], b1[4];
            ldmx4(a[0], a[1], a[2], a[3],
                  Qb + ((m0 + (l & 15)) * PDH + k0 + ((l & 16) ? 8 : 0)) * 2);
            ldmx4(b0[0], b0[1], b0[2], b0[3],
                  Kb + ((n0h + (l & 7) + ((l & 16) ? 8 : 0)) * PDH + k0 + ((l & 8) ? 8 : 0)) * 2);
            ldmx4(b1[0], b1[1], b1[2], b1[3],
                  Kb + ((n0h + 16 + (l & 7) + ((l & 16) ? 8 : 0)) * PDH + k0 + ((l & 8) ? 8 : 0)) * 2);
            mma16816(cc[0], a, &b0[0]);
            mma16816(cc[1], a, &b0[2]);
            mma16816(cc[2], a, &b1[0]);
            mma16816(cc[3], a, &b1[2]);
        }
        int tr = m0 + lr2;
#pragma unroll
        for (int nf = 0; nf < 4; nf++) {
            int sc = n0h + nf * 8 + lc2;
            *(__half2*)&AhP[tr * PDH + sc] = __halves2half2(
                __float2half(sc <= tr ? cc[nf][0] : 0.f),
                __float2half(sc + 1 <= tr ? cc[nf][1] : 0.f));
            int tr2 = tr + 8;
            *(__half2*)&AhP[tr2 * PDH + sc] = __halves2half2(
                __float2half(sc <= tr2 ? cc[nf][2] : 0.f),
                __float2half(sc + 1 <= tr2 ? cc[nf][3] : 0.f));
        }
    }
    __syncthreads();

    // GEMM2 (A'.U) + interGEMM (Q.S^T) accumulated into one fragment set
    {
        float cc[4][4];
#pragma unroll
        for (int i = 0; i < 4; i++)
#pragma unroll
            for (int j = 0; j < 4; j++) cc[i][j] = 0.f;
#pragma unroll
        for (int s0 = 0; s0 < 64; s0 += 16) {
            uint32_t a[4], b0[4], b1[4];
            ldmx4(a[0], a[1], a[2], a[3],
                  Ab + ((m0 + (l & 15)) * PDH + s0 + ((l & 16) ? 8 : 0)) * 2);
            ldmx4t(b0[0], b0[1], b0[2], b0[3],
                   Ub + ((s0 + (l & 15)) * PDH + n0h + ((l & 16) ? 8 : 0)) * 2);
            ldmx4t(b1[0], b1[1], b1[2], b1[3],
                   Ub + ((s0 + (l & 15)) * PDH + n0h + 16 + ((l & 16) ? 8 : 0)) * 2);
            mma16816(cc[0], a, &b0[0]);
            mma16816(cc[1], a, &b0[2]);
            mma16816(cc[2], a, &b1[0]);
            mma16816(cc[3], a, &b1[2]);
        }
#pragma unroll
        for (int k0 = 0; k0 < 64; k0 += 16) {
            uint32_t a[4], b0[4], b1[4];
            ldmx4(a[0], a[1], a[2], a[3],
                  Qb + ((m0 + (l & 15)) * PDH + k0 + ((l & 16) ? 8 : 0)) * 2);
            ldmx4(b0[0], b0[1], b0[2], b0[3],
                  Sb + ((n0h + (l & 7) + ((l & 16) ? 8 : 0)) * PDH + k0 + ((l & 8) ? 8 : 0)) * 2);
            ldmx4(b1[0], b1[1], b1[2], b1[3],
                  Sb + ((n0h + 16 + (l & 7) + ((l & 16) ? 8 : 0)) * PDH + k0 + ((l & 8) ? 8 : 0)) * 2);
            mma16816(cc[0], a, &b0[0]);
            mma16816(cc[1], a, &b0[2]);
            mma16816(cc[2], a, &b1[0]);
            mma16816(cc[3], a, &b1[2]);
        }
        int tr = m0 + lr2;
#pragma unroll
        for (int nf = 0; nf < 4; nf++) {
            int v = n0h + nf * 8 + lc2;
            float2 e0 = *(float2*)&sGf[tr * PD + v];
            *(__half2*)&g_attf[rowbase + (size_t)tr * HIDK + v] =
                __floats2half2_rn(cc[nf][0] * e0.x, cc[nf][1] * e0.y);
            float2 e1 = *(float2*)&sGf[(tr + 8) * PD + v];
            *(__half2*)&g_attf[rowbase + (size_t)(tr + 8) * HIDK + v] =
                __floats2half2_rn(cc[nf][2] * e1.x, cc[nf][3] * e1.y);
        }
    }
}

// ---------------- LayerNorm + SiLU gate -> fp16 y (vectorized) --------------
__global__ void __launch_bounds__(256) ln_gate_kernel(const float* __restrict__ gamma,
                                                      const float* __restrict__ beta) {
    int row = blockIdx.x;
    int tid = threadIdx.x;
    int col0 = tid * 4;
    size_t rb = (size_t)row * HIDK;

    uint2 av = *(const uint2*)(g_attf + rb + col0);
    const __half2* ah = (const __half2*)&av;
    float2 a01 = __half22float2(ah[0]);
    float2 a23 = __half22float2(ah[1]);
    float vals[4] = {a01.x, a01.y, a23.x, a23.y};

    float s = vals[0] + vals[1] + vals[2] + vals[3];
    float s2 = fmaf(vals[0], vals[0],
                    fmaf(vals[1], vals[1], fmaf(vals[2], vals[2], vals[3] * vals[3])));
#pragma unroll
    for (int o = 16; o; o >>= 1) {
        s += __shfl_xor_sync(0xffffffffu, s, o);
        s2 += __shfl_xor_sync(0xffffffffu, s2, o);
    }
    __shared__ float rs[8], rs2[8];
    int warp = tid >> 5;
    if ((tid & 31) == 0) { rs[warp] = s; rs2[warp] = s2; }
    __syncthreads();
    s = 0.f;
    s2 = 0.f;
#pragma unroll
    for (int w = 0; w < 8; w++) { s += rs[w]; s2 += rs2[w]; }
    float mean = s * (1.f / HIDK);
    float var = s2 * (1.f / HIDK) - mean * mean;
    float rstd = rsqrtf(var + 1e-5f);

    uint2 gv2 = *(const uint2*)(g_xgh + rb + col0);
    const __half2* gh = (const __half2*)&gv2;
    float2 g01 = __half22float2(gh[0]);
    float2 g23 = __half22float2(gh[1]);
    float gvs[4] = {g01.x, g01.y, g23.x, g23.y};

    float4 gm = *(const float4*)(gamma + col0);
    float4 bt = *(const float4*)(beta + col0);
    float gmv[4] = {gm.x, gm.y, gm.z, gm.w};
    float btv[4] = {bt.x, bt.y, bt.z, bt.w};

    __half yh4[4];
#pragma unroll
    for (int i = 0; i < 4; i++) {
        float sil = gvs[i] / (1.f + __expf(-gvs[i]));
        float yv = ((vals[i] - mean) * rstd * gmv[i] + btv[i]) * sil;
        yh4[i] = __float2half(yv);
    }
    *(uint2*)(g_yh + rb + col0) = *(uint2*)yh4;
}

// ---------------- launch --------------------------------------------------
extern "C" void kernel_launch(void* const* d_in, const int* in_sizes, int n_in,
                              void* d_out, int out_size) {
    const float* x = (const float*)d_in[0];
    const float* Wq = (const float*)d_in[1];
    const float* Wk = (const float*)d_in[2];
    const float* Wv = (const float*)d_in[3];
    const float* Wg = (const float*)d_in[4];
    const float* Wgk1 = (const float*)d_in[5];
    const float* Wgk2 = (const float*)d_in[6];
    const float* bgk2 = (const float*)d_in[7];
    const float* gamma = (const float*)d_in[8];
    const float* beta = (const float*)d_in[9];
    const float* Wout = (const float*)d_in[10];
    float* out = (float*)d_out;

    cudaFuncSetAttribute(chunkP_kernel, cudaFuncAttributeMaxDynamicSharedMemorySize, SMEM_CP);
    cudaFuncSetAttribute(biginter_kernel, cudaFuncAttributeMaxDynamicSharedMemorySize, SMEM_BI);
    cudaFuncSetAttribute(mmproj_kv_kernel, cudaFuncAttributeMaxDynamicSharedMemorySize, SMEM_MM);
    cudaFuncSetAttribute(mmproj_qg_kernel, cudaFuncAttributeMaxDynamicSharedMemorySize, SMEM_MM);
    cudaFuncSetAttribute(mmout_kernel, cudaFuncAttributeMaxDynamicSharedMemorySize, SMEM_MM);
    cudaFuncSetAttribute(lr_fused_kernel, cudaFuncAttributeMaxDynamicSharedMemorySize, SMEM_LR);

    cudaStream_t s1 = g_res.s1;

    // fork: side stream handles wconv, then q/xg projections
    cudaEventRecord(g_res.eA, 0);
    cudaStreamWaitEvent(s1, g_res.eA, 0);
    wconv_kernel<<<dim3(32, 32, 5), 256, 0, s1>>>(Wq, Wk, Wv, Wg, Wout);
    cudaEventRecord(g_res.eW, s1);

    // main stream: lr_fused (x conversion + gk)
    lr_fused_kernel<<<MTOK / 16, 256, SMEM_LR>>>(x, Wgk1, Wgk2, bgk2);
    cudaEventRecord(g_res.eL, 0);

    // side stream: q + xg projections (low priority)
    cudaStreamWaitEvent(s1, g_res.eL, 0);
    mmproj_qg_kernel<<<dim3(8, 32, 2), 256, SMEM_MM, s1>>>();
    cudaEventRecord(g_res.eQ, s1);

    // main stream: k,v projections -> chunkP -> chunkscan (critical path)
    cudaStreamWaitEvent(0, g_res.eW, 0);
    mmproj_kv_kernel<<<dim3(8, 32, 2), 256, SMEM_MM>>>();
    chunkP_kernel<<<dim3(NCH, 32), 256, SMEM_CP>>>();
    chunkscan_kernel<<<dim3(4, 32), 512>>>();

    // join: need q/xg before biginter/ln_gate
    cudaStreamWaitEvent(0, g_res.eQ, 0);
    biginter_kernel<<<dim3(NCH, 32), 256, SMEM_BI>>>();
    ln_gate_kernel<<<MTOK, 256>>>(gamma, beta);

    mmout_kernel<<<dim3(8, 32, 1), 256, SMEM_MM>>>(out);
}